// round 1
// baseline (speedup 1.0000x reference)
#include <cuda_runtime.h>
#include <math.h>

#define BATCH   8
#define SEQ     2048
#define DMODEL  1024
#define DHEAD   128
#define MTOK    (BATCH*SEQ)          // 16384
#define NROUNDS 3
#define SCALE_F 0.08838834764831843f // 1/sqrt(128)

// ---------------- device scratch (no runtime allocation allowed) -------------
__device__ float g_q[MTOK*DHEAD];
__device__ float g_k[MTOK*DHEAD];
__device__ float g_v[MTOK*DHEAD];
__device__ float g_scores[(size_t)BATCH*SEQ*SEQ];   // 134 MB
__device__ float g_p[MTOK*DHEAD];
__device__ float g_zfix[MTOK*DHEAD];
__device__ float g_z[MTOK*DHEAD];
__device__ float g_h[MTOK*DHEAD];
__device__ float g_synth[MTOK*DHEAD];
__device__ float g_wd[DHEAD*DHEAD];
__device__ float g_cvec[DHEAD];
__device__ int   g_active[MTOK];
__device__ int   g_flag[NROUNDS];

// ---------------- generic SGEMM, C = alpha * A(MxK) * W(NxK)^T ---------------
// BM=BN=128, BK=8, 256 threads, 8x8 microtile. Strides allow batched (z-dim).
__global__ __launch_bounds__(256) void gemm_nt(
    const float* __restrict__ A, int lda, size_t sA,
    const float* __restrict__ W, int ldw, size_t sW,
    float* __restrict__ C, int ldc, size_t sC,
    int Kdim, float alpha)
{
    __shared__ float As[8][128];
    __shared__ float Ws[8][128];
    A += (size_t)blockIdx.z * sA;
    W += (size_t)blockIdx.z * sW;
    C += (size_t)blockIdx.z * sC;
    const int tid  = threadIdx.x;
    const int m0   = blockIdx.x * 128;
    const int n0   = blockIdx.y * 128;
    const int tx   = tid & 15;    // n direction
    const int ty   = tid >> 4;    // m direction
    const int lrow = tid >> 1;    // 0..127
    const int lkv  = (tid & 1) * 4;
    float acc[8][8] = {};
    const float* Aptr = A + (size_t)(m0 + lrow) * lda + lkv;
    const float* Wptr = W + (size_t)(n0 + lrow) * ldw + lkv;
    for (int k0 = 0; k0 < Kdim; k0 += 8) {
        float4 av = *reinterpret_cast<const float4*>(Aptr + k0);
        float4 wv = *reinterpret_cast<const float4*>(Wptr + k0);
        As[lkv+0][lrow]=av.x; As[lkv+1][lrow]=av.y; As[lkv+2][lrow]=av.z; As[lkv+3][lrow]=av.w;
        Ws[lkv+0][lrow]=wv.x; Ws[lkv+1][lrow]=wv.y; Ws[lkv+2][lrow]=wv.z; Ws[lkv+3][lrow]=wv.w;
        __syncthreads();
        #pragma unroll
        for (int k = 0; k < 8; k++) {
            float4 a0 = *reinterpret_cast<const float4*>(&As[k][ty*8]);
            float4 a1 = *reinterpret_cast<const float4*>(&As[k][ty*8+4]);
            float4 w0 = *reinterpret_cast<const float4*>(&Ws[k][tx*8]);
            float4 w1 = *reinterpret_cast<const float4*>(&Ws[k][tx*8+4]);
            float a[8] = {a0.x,a0.y,a0.z,a0.w,a1.x,a1.y,a1.z,a1.w};
            float w[8] = {w0.x,w0.y,w0.z,w0.w,w1.x,w1.y,w1.z,w1.w};
            #pragma unroll
            for (int i = 0; i < 8; i++)
                #pragma unroll
                for (int j = 0; j < 8; j++)
                    acc[i][j] = fmaf(a[i], w[j], acc[i][j]);
        }
        __syncthreads();
    }
    #pragma unroll
    for (int i = 0; i < 8; i++) {
        float* crow = C + (size_t)(m0 + ty*8 + i) * ldc + n0 + tx*8;
        #pragma unroll
        for (int j = 0; j < 8; j += 4) {
            float4 o = make_float4(alpha*acc[i][j], alpha*acc[i][j+1],
                                   alpha*acc[i][j+2], alpha*acc[i][j+3]);
            *reinterpret_cast<float4*>(crow + j) = o;
        }
    }
}

// ---------------- SGEMM NN: C = A(MxK) * B(KxN),  N = 128*grid.y ------------
__global__ __launch_bounds__(256) void gemm_nn(
    const float* __restrict__ A, int lda, size_t sA,
    const float* __restrict__ Bm, int ldb, size_t sB,
    float* __restrict__ C, int ldc, size_t sC,
    int Kdim)
{
    __shared__ float As[8][128];
    __shared__ float Bs[8][128];
    A  += (size_t)blockIdx.z * sA;
    Bm += (size_t)blockIdx.z * sB;
    C  += (size_t)blockIdx.z * sC;
    const int tid  = threadIdx.x;
    const int m0   = blockIdx.x * 128;
    const int n0   = blockIdx.y * 128;
    const int tx   = tid & 15;
    const int ty   = tid >> 4;
    const int lrow = tid >> 1;
    const int lkv  = (tid & 1) * 4;
    const int bn4  = (tid & 31) * 4;
    const int bk   = tid >> 5;
    float acc[8][8] = {};
    const float* Aptr = A + (size_t)(m0 + lrow) * lda + lkv;
    for (int k0 = 0; k0 < Kdim; k0 += 8) {
        float4 av = *reinterpret_cast<const float4*>(Aptr + k0);
        float4 bv = *reinterpret_cast<const float4*>(Bm + (size_t)(k0 + bk) * ldb + n0 + bn4);
        As[lkv+0][lrow]=av.x; As[lkv+1][lrow]=av.y; As[lkv+2][lrow]=av.z; As[lkv+3][lrow]=av.w;
        *reinterpret_cast<float4*>(&Bs[bk][bn4]) = bv;
        __syncthreads();
        #pragma unroll
        for (int k = 0; k < 8; k++) {
            float4 a0 = *reinterpret_cast<const float4*>(&As[k][ty*8]);
            float4 a1 = *reinterpret_cast<const float4*>(&As[k][ty*8+4]);
            float4 w0 = *reinterpret_cast<const float4*>(&Bs[k][tx*8]);
            float4 w1 = *reinterpret_cast<const float4*>(&Bs[k][tx*8+4]);
            float a[8] = {a0.x,a0.y,a0.z,a0.w,a1.x,a1.y,a1.z,a1.w};
            float w[8] = {w0.x,w0.y,w0.z,w0.w,w1.x,w1.y,w1.z,w1.w};
            #pragma unroll
            for (int i = 0; i < 8; i++)
                #pragma unroll
                for (int j = 0; j < 8; j++)
                    acc[i][j] = fmaf(a[i], w[j], acc[i][j]);
        }
        __syncthreads();
    }
    #pragma unroll
    for (int i = 0; i < 8; i++) {
        float* crow = C + (size_t)(m0 + ty*8 + i) * ldc + n0 + tx*8;
        #pragma unroll
        for (int j = 0; j < 8; j += 4) {
            float4 o = make_float4(acc[i][j], acc[i][j+1], acc[i][j+2], acc[i][j+3]);
            *reinterpret_cast<float4*>(crow + j) = o;
        }
    }
}

// ---------------- softmax over rows of length SEQ ----------------------------
__global__ __launch_bounds__(256) void softmax_rows(float* __restrict__ scores)
{
    float* row = scores + (size_t)blockIdx.x * SEQ;
    const int tid = threadIdx.x;
    float vals[8];
    float mx = -1e30f;
    #pragma unroll
    for (int i = 0; i < 8; i++) { vals[i] = row[tid + i*256]; mx = fmaxf(mx, vals[i]); }
    __shared__ float red[8];
    #pragma unroll
    for (int o = 16; o; o >>= 1) mx = fmaxf(mx, __shfl_xor_sync(0xffffffffu, mx, o));
    if ((tid & 31) == 0) red[tid >> 5] = mx;
    __syncthreads();
    mx = red[0];
    #pragma unroll
    for (int w = 1; w < 8; w++) mx = fmaxf(mx, red[w]);
    __syncthreads();
    float s = 0.f;
    #pragma unroll
    for (int i = 0; i < 8; i++) { vals[i] = expf(vals[i] - mx); s += vals[i]; }
    #pragma unroll
    for (int o = 16; o; o >>= 1) s += __shfl_xor_sync(0xffffffffu, s, o);
    if ((tid & 31) == 0) red[tid >> 5] = s;
    __syncthreads();
    s = red[0]+red[1]+red[2]+red[3]+red[4]+red[5]+red[6]+red[7];
    const float inv = 1.f / s;
    #pragma unroll
    for (int i = 0; i < 8; i++) row[tid + i*256] = vals[i] * inv;
}

// ---------------- small prep kernels -----------------------------------------
__global__ void prep_wd(const float* __restrict__ w1, float* __restrict__ wd)
{
    int idx = blockIdx.x * blockDim.x + threadIdx.x;   // 16384
    int j = idx >> 7, i = idx & 127;
    wd[idx] = w1[j*384 + i] - w1[j*384 + 128 + i];
}

__global__ void prep_cvec(const float* __restrict__ w1, const float* __restrict__ tb,
                          const float* __restrict__ ab, float* __restrict__ cvec)
{
    int j = threadIdx.x;   // 128
    float s = 0.f;
    for (int i = 0; i < 128; i++)
        s += tb[i]*w1[j*384 + i] + ab[i]*w1[j*384 + 128 + i];
    cvec[j] = s;
}

__global__ void init_kernel(int* __restrict__ active, int* __restrict__ flag)
{
    int idx = blockIdx.x * blockDim.x + threadIdx.x;
    if (idx < MTOK)    active[idx] = 1;
    if (idx < NROUNDS) flag[idx]   = 0;
}

__global__ void any_active_kernel(const int* __restrict__ active,
                                  int* __restrict__ flag, int r)
{
    int a = 0;
    for (int m = threadIdx.x; m < MTOK; m += blockDim.x) a |= active[m];
    a = __syncthreads_or(a);
    if (threadIdx.x == 0) flag[r] = a ? 1 : 0;
}

// h = relu(am * (zc + zfix + cvec) + b1)
__global__ void h_kernel(const float* __restrict__ zc, const float* __restrict__ zfix,
                         const float* __restrict__ cvec, const float* __restrict__ b1,
                         const int* __restrict__ active, float* __restrict__ h)
{
    int idx = blockIdx.x * blockDim.x + threadIdx.x;   // MTOK*DHEAD
    int m = idx >> 7, j = idx & 127;
    float am = active[m] ? 1.f : 0.f;
    float z  = zc[idx] + zfix[idx] + cvec[j];
    h[idx] = fmaxf(fmaf(am, z, b1[j]), 0.f);
}

// gate + update + norm + conditional apply, one block (128 thr) per token
__global__ __launch_bounds__(128) void apply_kernel(
    float* __restrict__ cur, const float* __restrict__ synth,
    const float* __restrict__ b2, const float* __restrict__ gw,
    const float* __restrict__ gb, int* __restrict__ active,
    const int* __restrict__ flag, int r)
{
    const int m = blockIdx.x;
    const int i = threadIdx.x;
    float c  = cur[(size_t)m*DHEAD + i];
    float sy = synth[(size_t)m*DHEAD + i] + b2[i];
    int   act = active[m];
    float am  = act ? 1.f : 0.f;
    float ac  = c * am;
    __shared__ float r1[4], r2[4];
    float v = ac * gw[i] + sy * gw[DHEAD + i];
    #pragma unroll
    for (int o = 16; o; o >>= 1) v += __shfl_xor_sync(0xffffffffu, v, o);
    if ((i & 31) == 0) r1[i >> 5] = v;
    __syncthreads();
    float gdot = r1[0] + r1[1] + r1[2] + r1[3] + gb[0];
    float gate = 1.f / (1.f + expf(-gdot));
    float upd  = gate * (sy - ac) * 0.1f;
    float u2 = upd * upd;
    #pragma unroll
    for (int o = 16; o; o >>= 1) u2 += __shfl_xor_sync(0xffffffffu, u2, o);
    if ((i & 31) == 0) r2[i >> 5] = u2;
    __syncthreads();
    float n2 = r2[0] + r2[1] + r2[2] + r2[3];
    if (flag[r]) {
        cur[(size_t)m*DHEAD + i] = c + upd;
        if (i == 0) active[m] = act && !(sqrtf(n2) < 0.1f);
    }
}

// ---------------- launch ------------------------------------------------------
extern "C" void kernel_launch(void* const* d_in, const int* in_sizes, int n_in,
                              void* d_out, int out_size)
{
    (void)in_sizes; (void)n_in; (void)out_size;
    const float* x  = (const float*)d_in[0];
    const float* wq = (const float*)d_in[1];
    const float* wk = (const float*)d_in[2];
    const float* wv = (const float*)d_in[3];
    const float* tw = (const float*)d_in[4];
    const float* tb = (const float*)d_in[5];
    const float* ab = (const float*)d_in[6];
    const float* w1 = (const float*)d_in[7];
    const float* b1 = (const float*)d_in[8];
    const float* w2 = (const float*)d_in[9];
    const float* b2 = (const float*)d_in[10];
    const float* gw = (const float*)d_in[11];
    const float* gb = (const float*)d_in[12];
    float* cur = (float*)d_out;

    float *q,*k,*v,*scores,*p,*zfix,*z,*h,*synth,*wd,*cvec;
    int *active,*flag;
    cudaGetSymbolAddress((void**)&q,      g_q);
    cudaGetSymbolAddress((void**)&k,      g_k);
    cudaGetSymbolAddress((void**)&v,      g_v);
    cudaGetSymbolAddress((void**)&scores, g_scores);
    cudaGetSymbolAddress((void**)&p,      g_p);
    cudaGetSymbolAddress((void**)&zfix,   g_zfix);
    cudaGetSymbolAddress((void**)&z,      g_z);
    cudaGetSymbolAddress((void**)&h,      g_h);
    cudaGetSymbolAddress((void**)&synth,  g_synth);
    cudaGetSymbolAddress((void**)&wd,     g_wd);
    cudaGetSymbolAddress((void**)&cvec,   g_cvec);
    cudaGetSymbolAddress((void**)&active, g_active);
    cudaGetSymbolAddress((void**)&flag,   g_flag);

    // q/k/v projections: [16384,1024] x [128,1024]^T
    gemm_nt<<<dim3(MTOK/128,1,1),256>>>(x, DMODEL, 0, wq, DMODEL, 0, q, DHEAD, 0, DMODEL, 1.f);
    gemm_nt<<<dim3(MTOK/128,1,1),256>>>(x, DMODEL, 0, wk, DMODEL, 0, k, DHEAD, 0, DMODEL, 1.f);
    gemm_nt<<<dim3(MTOK/128,1,1),256>>>(x, DMODEL, 0, wv, DMODEL, 0, v, DHEAD, 0, DMODEL, 1.f);

    // scores = SCALE * q @ k^T, per batch
    gemm_nt<<<dim3(SEQ/128, SEQ/128, BATCH),256>>>(
        q, DHEAD, (size_t)SEQ*DHEAD, k, DHEAD, (size_t)SEQ*DHEAD,
        scores, SEQ, (size_t)SEQ*SEQ, DHEAD, SCALE_F);

    softmax_rows<<<MTOK,256>>>(scores);

    // cur0 = attn @ v, per batch; written directly to d_out
    gemm_nn<<<dim3(SEQ/128,1,BATCH),256>>>(
        scores, SEQ, (size_t)SEQ*SEQ, v, DHEAD, (size_t)SEQ*DHEAD,
        cur, DHEAD, (size_t)SEQ*DHEAD, SEQ);

    // round-invariant precompute: p = cur0 @ tw^T; zfix = p @ (W1a - W1b)^T
    gemm_nt<<<dim3(MTOK/128,1,1),256>>>(cur, DHEAD, 0, tw, DHEAD, 0, p, DHEAD, 0, DHEAD, 1.f);
    prep_wd<<<DHEAD*DHEAD/256,256>>>(w1, wd);
    prep_cvec<<<1,128>>>(w1, tb, ab, cvec);
    gemm_nt<<<dim3(MTOK/128,1,1),256>>>(p, DHEAD, 0, wd, DHEAD, 0, zfix, DHEAD, 0, DHEAD, 1.f);

    init_kernel<<<64,256>>>(active, flag);

    for (int r = 0; r < NROUNDS; r++) {
        any_active_kernel<<<1,1024>>>(active, flag, r);
        // zc = cur @ W1c^T  (W1c = s_w1[:, 256:384])
        gemm_nt<<<dim3(MTOK/128,1,1),256>>>(cur, DHEAD, 0, w1 + 256, 3*DHEAD, 0,
                                            z, DHEAD, 0, DHEAD, 1.f);
        h_kernel<<<MTOK*DHEAD/256,256>>>(z, zfix, cvec, b1, active, h);
        // synth_raw = h @ w2^T
        gemm_nt<<<dim3(MTOK/128,1,1),256>>>(h, DHEAD, 0, w2, DHEAD, 0,
                                            synth, DHEAD, 0, DHEAD, 1.f);
        apply_kernel<<<MTOK,128>>>(cur, synth, b2, gw, gb, active, flag, r);
    }
}

// round 3
// speedup vs baseline: 3.0084x; 3.0084x over previous
#include <cuda_runtime.h>
#include <math.h>
#include <stdint.h>

#define BATCH   8
#define SEQ     2048
#define DMODEL  1024
#define DHEAD   128
#define MTOK    (BATCH*SEQ)          // 16384
#define NROUNDS 3
#define SCALE_F 0.08838834764831843f // 1/sqrt(128)

// ---------------- device scratch (no runtime allocation allowed) -------------
__device__ __align__(256) float g_xr[MTOK*DMODEL];            // rounded x
__device__ __align__(256) float g_q[MTOK*DHEAD];
__device__ __align__(256) float g_k[MTOK*DHEAD];
__device__ __align__(256) float g_v[MTOK*DHEAD];
__device__ __align__(256) float g_vt[BATCH*DHEAD*SEQ];        // v transposed per batch
__device__ __align__(256) float g_scores[(size_t)BATCH*SEQ*SEQ]; // 134 MB
__device__ __align__(256) float g_curR[MTOK*DHEAD];           // rounded copy of cur
__device__ __align__(256) float g_p[MTOK*DHEAD];
__device__ __align__(256) float g_zfix[MTOK*DHEAD];
__device__ __align__(256) float g_z[MTOK*DHEAD];
__device__ __align__(256) float g_h[MTOK*DHEAD];
__device__ __align__(256) float g_synth[MTOK*DHEAD];
__device__ __align__(256) float g_wqr[DHEAD*DMODEL];
__device__ __align__(256) float g_wkr[DHEAD*DMODEL];
__device__ __align__(256) float g_wvr[DHEAD*DMODEL];
__device__ __align__(256) float g_twr[DHEAD*DHEAD];
__device__ __align__(256) float g_w2r[DHEAD*DHEAD];
__device__ __align__(256) float g_wdr[DHEAD*DHEAD];
__device__ __align__(256) float g_w1cr[DHEAD*DHEAD];
__device__ float g_cvec[DHEAD];
__device__ int   g_active[MTOK];
__device__ int   g_flag[NROUNDS];

// ---------------- PTX helpers -------------------------------------------------
__device__ __forceinline__ uint32_t s2u(const void* p) {
    uint32_t a;
    asm("{ .reg .u64 t; cvta.to.shared.u64 t, %1; cvt.u32.u64 %0, t; }" : "=r"(a) : "l"(p));
    return a;
}
__device__ __forceinline__ float rna_tf32(float f) {
    float o;
    asm("cvt.rna.tf32.f32 %0, %1;" : "=f"(o) : "f"(f));
    return o;
}
__device__ __forceinline__ void cp_async16(uint32_t dst, const void* src) {
    asm volatile("cp.async.cg.shared.global [%0], [%1], 16;" :: "r"(dst), "l"(src) : "memory");
}
#define CP_COMMIT() asm volatile("cp.async.commit_group;" ::: "memory")
#define CP_WAIT(N)  asm volatile("cp.async.wait_group %0;" :: "n"(N) : "memory")

__device__ __forceinline__ void mma_tf32(
    float& c0, float& c1, float& c2, float& c3,
    uint32_t a0, uint32_t a1, uint32_t a2, uint32_t a3,
    uint32_t b0, uint32_t b1)
{
    asm volatile(
        "mma.sync.aligned.m16n8k8.row.col.f32.tf32.tf32.f32 "
        "{%0,%1,%2,%3}, {%4,%5,%6,%7}, {%8,%9}, {%0,%1,%2,%3};"
        : "+f"(c0), "+f"(c1), "+f"(c2), "+f"(c3)
        : "r"(a0), "r"(a1), "r"(a2), "r"(a3), "r"(b0), "r"(b1));
}

// ---------------- tensor-core tf32 NT GEMM ------------------------------------
// C = alpha * A(MxK) * B(NxK)^T ; block tile 128x128, BK=32, 256 thr, 8 warps.
// Smem row stride 36 floats -> conflict-free fragment loads.
#define SMS   36
#define STG_F (2*128*SMS)              // floats per stage (A+B)
#define SMEM_GEMM_BYTES (2*STG_F*4)    // 73728

__global__ __launch_bounds__(256) void gemm_mma(
    const float* __restrict__ A, int lda, size_t sA,
    const float* __restrict__ B, int ldb, size_t sB,
    float* __restrict__ C, int ldc, size_t sC,
    int Kdim, float alpha, int roundOut)
{
    extern __shared__ float sm[];
    const uint32_t sm_u = s2u(sm);
    A += (size_t)blockIdx.z * sA;
    B += (size_t)blockIdx.z * sB;
    C += (size_t)blockIdx.z * sC;
    const int tid  = threadIdx.x;
    const int lane = tid & 31;
    const int warp = tid >> 5;
    const int wm = (warp >> 1) * 32;     // warp M offset (4 warps)
    const int wn = (warp & 1) * 64;      // warp N offset (2 warps)
    const int m0 = blockIdx.x * 128;
    const int n0 = blockIdx.y * 128;

    // load indexing: 1024 float4 per matrix per stage, 4 iters of 256 threads
    const int lrow = tid >> 3;           // +32 per iter
    const int lc4  = (tid & 7) * 4;

    const int nK = Kdim >> 5;

    // prefetch stage 0
    {
        const float* Ag = A + (size_t)m0 * lda + lc4;
        const float* Bg = B + (size_t)n0 * ldb + lc4;
        uint32_t dA = sm_u + (uint32_t)(lrow * SMS + lc4) * 4u;
        uint32_t dB = dA + 128u * SMS * 4u;
        #pragma unroll
        for (int it = 0; it < 4; it++) {
            cp_async16(dA + it * 32u * SMS * 4u, Ag + (size_t)(lrow + it*32) * lda);
            cp_async16(dB + it * 32u * SMS * 4u, Bg + (size_t)(lrow + it*32) * ldb);
        }
        CP_COMMIT();
    }

    float acc[2][8][4];
    #pragma unroll
    for (int mi = 0; mi < 2; mi++)
        #pragma unroll
        for (int ni = 0; ni < 8; ni++)
            #pragma unroll
            for (int j = 0; j < 4; j++) acc[mi][ni][j] = 0.f;

    const int g  = lane >> 2;   // group id 0..7
    const int t4 = lane & 3;    // thread-in-group 0..3

    for (int kt = 0; kt < nK; kt++) {
        int cs = kt & 1;
        if (kt + 1 < nK) {
            int ns = cs ^ 1;
            const float* Ag = A + (size_t)m0 * lda + (kt+1)*32 + lc4;
            const float* Bg = B + (size_t)n0 * ldb + (kt+1)*32 + lc4;
            uint32_t dA = sm_u + (uint32_t)(ns * STG_F + lrow * SMS + lc4) * 4u;
            uint32_t dB = dA + 128u * SMS * 4u;
            #pragma unroll
            for (int it = 0; it < 4; it++) {
                cp_async16(dA + it * 32u * SMS * 4u, Ag + (size_t)(lrow + it*32) * lda);
                cp_async16(dB + it * 32u * SMS * 4u, Bg + (size_t)(lrow + it*32) * ldb);
            }
            CP_COMMIT();
            CP_WAIT(1);
        } else {
            CP_WAIT(0);
        }
        __syncthreads();

        const float* Asf = sm + cs * STG_F;
        const float* Bsf = Asf + 128 * SMS;

        #pragma unroll
        for (int kk = 0; kk < 4; kk++) {
            const int k8 = kk * 8;
            uint32_t a[2][4];
            #pragma unroll
            for (int mi = 0; mi < 2; mi++) {
                const float* ap = Asf + (wm + mi*16 + g) * SMS + k8 + t4;
                a[mi][0] = __float_as_uint(ap[0]);
                a[mi][1] = __float_as_uint(ap[8*SMS]);
                a[mi][2] = __float_as_uint(ap[4]);
                a[mi][3] = __float_as_uint(ap[8*SMS + 4]);
            }
            uint32_t b[8][2];
            #pragma unroll
            for (int ni = 0; ni < 8; ni++) {
                const float* bp = Bsf + (wn + ni*8 + g) * SMS + k8 + t4;
                b[ni][0] = __float_as_uint(bp[0]);
                b[ni][1] = __float_as_uint(bp[4]);
            }
            #pragma unroll
            for (int mi = 0; mi < 2; mi++)
                #pragma unroll
                for (int ni = 0; ni < 8; ni++)
                    mma_tf32(acc[mi][ni][0], acc[mi][ni][1], acc[mi][ni][2], acc[mi][ni][3],
                             a[mi][0], a[mi][1], a[mi][2], a[mi][3],
                             b[ni][0], b[ni][1]);
        }
        __syncthreads();
    }

    // epilogue
    #pragma unroll
    for (int mi = 0; mi < 2; mi++) {
        const int r0 = m0 + wm + mi*16 + g;
        #pragma unroll
        for (int ni = 0; ni < 8; ni++) {
            const int c0 = n0 + wn + ni*8 + 2*t4;
            float2 v0, v1;
            v0.x = acc[mi][ni][0] * alpha; v0.y = acc[mi][ni][1] * alpha;
            v1.x = acc[mi][ni][2] * alpha; v1.y = acc[mi][ni][3] * alpha;
            if (roundOut) {
                v0.x = rna_tf32(v0.x); v0.y = rna_tf32(v0.y);
                v1.x = rna_tf32(v1.x); v1.y = rna_tf32(v1.y);
            }
            *reinterpret_cast<float2*>(C + (size_t)r0 * ldc + c0)       = v0;
            *reinterpret_cast<float2*>(C + (size_t)(r0+8) * ldc + c0)   = v1;
        }
    }
}

// ---------------- softmax over rows of length SEQ (rounds output to tf32) ----
__global__ __launch_bounds__(256) void softmax_rows(float* __restrict__ scores)
{
    float* row = scores + (size_t)blockIdx.x * SEQ;
    const int tid = threadIdx.x;
    float vals[8];
    float mx = -1e30f;
    #pragma unroll
    for (int i = 0; i < 8; i++) { vals[i] = row[tid + i*256]; mx = fmaxf(mx, vals[i]); }
    __shared__ float red[8];
    #pragma unroll
    for (int o = 16; o; o >>= 1) mx = fmaxf(mx, __shfl_xor_sync(0xffffffffu, mx, o));
    if ((tid & 31) == 0) red[tid >> 5] = mx;
    __syncthreads();
    mx = red[0];
    #pragma unroll
    for (int w = 1; w < 8; w++) mx = fmaxf(mx, red[w]);
    __syncthreads();
    float s = 0.f;
    #pragma unroll
    for (int i = 0; i < 8; i++) { vals[i] = expf(vals[i] - mx); s += vals[i]; }
    #pragma unroll
    for (int o = 16; o; o >>= 1) s += __shfl_xor_sync(0xffffffffu, s, o);
    if ((tid & 31) == 0) red[tid >> 5] = s;
    __syncthreads();
    s = red[0]+red[1]+red[2]+red[3]+red[4]+red[5]+red[6]+red[7];
    const float inv = 1.f / s;
    #pragma unroll
    for (int i = 0; i < 8; i++) row[tid + i*256] = rna_tf32(vals[i] * inv);
}

// ---------------- small prep kernels -----------------------------------------
__global__ void round_arr(const float* __restrict__ in, float* __restrict__ out, int n4)
{
    int i = blockIdx.x * blockDim.x + threadIdx.x;
    if (i < n4) {
        float4 v = reinterpret_cast<const float4*>(in)[i];
        v.x = rna_tf32(v.x); v.y = rna_tf32(v.y); v.z = rna_tf32(v.z); v.w = rna_tf32(v.w);
        reinterpret_cast<float4*>(out)[i] = v;
    }
}

__global__ void transpose_v(const float* __restrict__ v, float* __restrict__ vt)
{
    __shared__ float t[32][33];
    int b = blockIdx.z;
    int s0 = blockIdx.x * 32, d0 = blockIdx.y * 32;
    int x = threadIdx.x, y = threadIdx.y;   // 32 x 8
    #pragma unroll
    for (int j = y; j < 32; j += 8)
        t[j][x] = v[((size_t)b*SEQ + s0 + j) * DHEAD + d0 + x];
    __syncthreads();
    #pragma unroll
    for (int j = y; j < 32; j += 8)
        vt[((size_t)b*DHEAD + d0 + j) * SEQ + s0 + x] = t[x][j];
}

__global__ void prep_wd(const float* __restrict__ w1, float* __restrict__ wd,
                        float* __restrict__ w1c)
{
    int idx = blockIdx.x * blockDim.x + threadIdx.x;   // 16384
    int j = idx >> 7, i = idx & 127;
    wd[idx]  = rna_tf32(w1[j*384 + i] - w1[j*384 + 128 + i]);
    w1c[idx] = rna_tf32(w1[j*384 + 256 + i]);
}

__global__ void prep_cvec(const float* __restrict__ w1, const float* __restrict__ tb,
                          const float* __restrict__ ab, float* __restrict__ cvec)
{
    int j = threadIdx.x;   // 128
    float s = 0.f;
    for (int i = 0; i < 128; i++)
        s += tb[i]*w1[j*384 + i] + ab[i]*w1[j*384 + 128 + i];
    cvec[j] = s;
}

__global__ void init_kernel(int* __restrict__ active, int* __restrict__ flag)
{
    int idx = blockIdx.x * blockDim.x + threadIdx.x;
    if (idx < MTOK)    active[idx] = 1;
    if (idx < NROUNDS) flag[idx]   = 0;
}

__global__ void any_active_kernel(const int* __restrict__ active,
                                  int* __restrict__ flag, int r)
{
    int a = 0;
    for (int m = threadIdx.x; m < MTOK; m += blockDim.x) a |= active[m];
    a = __syncthreads_or(a);
    if (threadIdx.x == 0) flag[r] = a ? 1 : 0;
}

// h = rna(relu(am * (zc + zfix + cvec) + b1))
__global__ void h_kernel(const float* __restrict__ zc, const float* __restrict__ zfix,
                         const float* __restrict__ cvec, const float* __restrict__ b1,
                         const int* __restrict__ active, float* __restrict__ h)
{
    int idx = blockIdx.x * blockDim.x + threadIdx.x;   // MTOK*DHEAD
    int m = idx >> 7, j = idx & 127;
    float am = active[m] ? 1.f : 0.f;
    float z  = zc[idx] + zfix[idx] + cvec[j];
    h[idx] = rna_tf32(fmaxf(fmaf(am, z, b1[j]), 0.f));
}

// gate + update + norm + conditional apply, one block (128 thr) per token
__global__ __launch_bounds__(128) void apply_kernel(
    float* __restrict__ cur, const float* __restrict__ synth,
    const float* __restrict__ b2, const float* __restrict__ gw,
    const float* __restrict__ gb, int* __restrict__ active,
    const int* __restrict__ flag, int r)
{
    const int m = blockIdx.x;
    const int i = threadIdx.x;
    float c  = cur[(size_t)m*DHEAD + i];
    float sy = synth[(size_t)m*DHEAD + i] + b2[i];
    int   act = active[m];
    float am  = act ? 1.f : 0.f;
    float ac  = c * am;
    __shared__ float r1[4], r2[4];
    float v = ac * gw[i] + sy * gw[DHEAD + i];
    #pragma unroll
    for (int o = 16; o; o >>= 1) v += __shfl_xor_sync(0xffffffffu, v, o);
    if ((i & 31) == 0) r1[i >> 5] = v;
    __syncthreads();
    float gdot = r1[0] + r1[1] + r1[2] + r1[3] + gb[0];
    float gate = 1.f / (1.f + expf(-gdot));
    float upd  = gate * (sy - ac) * 0.1f;
    float u2 = upd * upd;
    #pragma unroll
    for (int o = 16; o; o >>= 1) u2 += __shfl_xor_sync(0xffffffffu, u2, o);
    if ((i & 31) == 0) r2[i >> 5] = u2;
    __syncthreads();
    float n2 = r2[0] + r2[1] + r2[2] + r2[3];
    if (flag[r]) {
        cur[(size_t)m*DHEAD + i] = c + upd;
        if (i == 0) active[m] = act && !(sqrtf(n2) < 0.1f);
    }
}

// ---------------- launch ------------------------------------------------------
extern "C" void kernel_launch(void* const* d_in, const int* in_sizes, int n_in,
                              void* d_out, int out_size)
{
    (void)in_sizes; (void)n_in; (void)out_size;
    const float* x  = (const float*)d_in[0];
    const float* wq = (const float*)d_in[1];
    const float* wk = (const float*)d_in[2];
    const float* wv = (const float*)d_in[3];
    const float* tw = (const float*)d_in[4];
    const float* tb = (const float*)d_in[5];
    const float* ab = (const float*)d_in[6];
    const float* w1 = (const float*)d_in[7];
    const float* b1 = (const float*)d_in[8];
    const float* w2 = (const float*)d_in[9];
    const float* b2 = (const float*)d_in[10];
    const float* gw = (const float*)d_in[11];
    const float* gb = (const float*)d_in[12];
    float* cur = (float*)d_out;

    float *xr,*q,*k,*v,*vt,*scores,*curR,*p,*zfix,*z,*h,*synth;
    float *wqr,*wkr,*wvr,*twr,*w2r,*wdr,*w1cr,*cvec;
    int *active,*flag;
    cudaGetSymbolAddress((void**)&xr,     g_xr);
    cudaGetSymbolAddress((void**)&q,      g_q);
    cudaGetSymbolAddress((void**)&k,      g_k);
    cudaGetSymbolAddress((void**)&v,      g_v);
    cudaGetSymbolAddress((void**)&vt,     g_vt);
    cudaGetSymbolAddress((void**)&scores, g_scores);
    cudaGetSymbolAddress((void**)&curR,   g_curR);
    cudaGetSymbolAddress((void**)&p,      g_p);
    cudaGetSymbolAddress((void**)&zfix,   g_zfix);
    cudaGetSymbolAddress((void**)&z,      g_z);
    cudaGetSymbolAddress((void**)&h,      g_h);
    cudaGetSymbolAddress((void**)&synth,  g_synth);
    cudaGetSymbolAddress((void**)&wqr,    g_wqr);
    cudaGetSymbolAddress((void**)&wkr,    g_wkr);
    cudaGetSymbolAddress((void**)&wvr,    g_wvr);
    cudaGetSymbolAddress((void**)&twr,    g_twr);
    cudaGetSymbolAddress((void**)&w2r,    g_w2r);
    cudaGetSymbolAddress((void**)&wdr,    g_wdr);
    cudaGetSymbolAddress((void**)&w1cr,   g_w1cr);
    cudaGetSymbolAddress((void**)&cvec,   g_cvec);
    cudaGetSymbolAddress((void**)&active, g_active);
    cudaGetSymbolAddress((void**)&flag,   g_flag);

    cudaFuncSetAttribute(gemm_mma, cudaFuncAttributeMaxDynamicSharedMemorySize, SMEM_GEMM_BYTES);

    // ---- prep: round operands to tf32 (rna) -----------------------------------
    round_arr<<<(MTOK*DMODEL/4 + 255)/256, 256>>>(x,  xr,  MTOK*DMODEL/4);
    round_arr<<<(DHEAD*DMODEL/4 + 255)/256, 256>>>(wq, wqr, DHEAD*DMODEL/4);
    round_arr<<<(DHEAD*DMODEL/4 + 255)/256, 256>>>(wk, wkr, DHEAD*DMODEL/4);
    round_arr<<<(DHEAD*DMODEL/4 + 255)/256, 256>>>(wv, wvr, DHEAD*DMODEL/4);
    round_arr<<<(DHEAD*DHEAD/4  + 255)/256, 256>>>(tw, twr, DHEAD*DHEAD/4);
    round_arr<<<(DHEAD*DHEAD/4  + 255)/256, 256>>>(w2, w2r, DHEAD*DHEAD/4);
    prep_wd<<<DHEAD*DHEAD/256, 256>>>(w1, wdr, w1cr);
    prep_cvec<<<1,128>>>(w1, tb, ab, cvec);
    init_kernel<<<64,256>>>(active, flag);

    // ---- q/k/v projections (tensor core, tf32) -------------------------------
    gemm_mma<<<dim3(MTOK/128,1,1), 256, SMEM_GEMM_BYTES>>>(
        xr, DMODEL, 0, wqr, DMODEL, 0, q, DHEAD, 0, DMODEL, 1.f, 1);
    gemm_mma<<<dim3(MTOK/128,1,1), 256, SMEM_GEMM_BYTES>>>(
        xr, DMODEL, 0, wkr, DMODEL, 0, k, DHEAD, 0, DMODEL, 1.f, 1);
    gemm_mma<<<dim3(MTOK/128,1,1), 256, SMEM_GEMM_BYTES>>>(
        xr, DMODEL, 0, wvr, DMODEL, 0, v, DHEAD, 0, DMODEL, 1.f, 1);

    transpose_v<<<dim3(SEQ/32, DHEAD/32, BATCH), dim3(32,8)>>>(v, vt);

    // ---- scores = SCALE * q @ k^T, per batch ----------------------------------
    gemm_mma<<<dim3(SEQ/128, SEQ/128, BATCH), 256, SMEM_GEMM_BYTES>>>(
        q, DHEAD, (size_t)SEQ*DHEAD, k, DHEAD, (size_t)SEQ*DHEAD,
        scores, SEQ, (size_t)SEQ*SEQ, DHEAD, SCALE_F, 0);

    softmax_rows<<<MTOK,256>>>(scores);

    // ---- cur0 = attn @ v, per batch (B = vt, NT layout) ------------------------
    gemm_mma<<<dim3(SEQ/128, 1, BATCH), 256, SMEM_GEMM_BYTES>>>(
        scores, SEQ, (size_t)SEQ*SEQ, vt, SEQ, (size_t)DHEAD*SEQ,
        cur, DHEAD, (size_t)SEQ*DHEAD, SEQ, 1.f, 0);

    // ---- round-invariant precompute -------------------------------------------
    round_arr<<<(MTOK*DHEAD/4 + 255)/256, 256>>>(cur, curR, MTOK*DHEAD/4);
    gemm_mma<<<dim3(MTOK/128,1,1), 256, SMEM_GEMM_BYTES>>>(
        curR, DHEAD, 0, twr, DHEAD, 0, p, DHEAD, 0, DHEAD, 1.f, 1);
    gemm_mma<<<dim3(MTOK/128,1,1), 256, SMEM_GEMM_BYTES>>>(
        p, DHEAD, 0, wdr, DHEAD, 0, zfix, DHEAD, 0, DHEAD, 1.f, 0);

    for (int r = 0; r < NROUNDS; r++) {
        any_active_kernel<<<1,1024>>>(active, flag, r);
        round_arr<<<(MTOK*DHEAD/4 + 255)/256, 256>>>(cur, curR, MTOK*DHEAD/4);
        gemm_mma<<<dim3(MTOK/128,1,1), 256, SMEM_GEMM_BYTES>>>(
            curR, DHEAD, 0, w1cr, DHEAD, 0, z, DHEAD, 0, DHEAD, 1.f, 0);
        h_kernel<<<MTOK*DHEAD/256, 256>>>(z, zfix, cvec, b1, active, h);
        gemm_mma<<<dim3(MTOK/128,1,1), 256, SMEM_GEMM_BYTES>>>(
            h, DHEAD, 0, w2r, DHEAD, 0, synth, DHEAD, 0, DHEAD, 1.f, 0);
        apply_kernel<<<MTOK,128>>>(cur, synth, b2, gw, gb, active, flag, r);
    }
}

// round 5
// speedup vs baseline: 3.5270x; 1.1724x over previous
#include <cuda_runtime.h>
#include <math.h>
#include <stdint.h>

#define BATCH   8
#define SEQ     2048
#define DMODEL  1024
#define DHEAD   128
#define MTOK    (BATCH*SEQ)          // 16384
#define NROUNDS 3
#define SCALE_F 0.08838834764831843f // 1/sqrt(128)
#define LOG2E_F 1.4426950408889634f

// ---------------- device scratch (no runtime allocation allowed) -------------
__device__ __align__(256) float g_xr[MTOK*DMODEL];            // rounded x
__device__ __align__(256) float g_q[MTOK*DHEAD];
__device__ __align__(256) float g_k[MTOK*DHEAD];
__device__ __align__(256) float g_v[MTOK*DHEAD];
__device__ __align__(256) float g_vt[BATCH*DHEAD*SEQ];        // v transposed per batch
__device__ __align__(256) float g_curR[MTOK*DHEAD];           // rounded copy of cur
__device__ __align__(256) float g_p[MTOK*DHEAD];
__device__ __align__(256) float g_zfix[MTOK*DHEAD];
__device__ __align__(256) float g_h[MTOK*DHEAD];
__device__ __align__(256) float g_synth[MTOK*DHEAD];
__device__ __align__(256) float g_wqr[DHEAD*DMODEL];
__device__ __align__(256) float g_wkr[DHEAD*DMODEL];
__device__ __align__(256) float g_wvr[DHEAD*DMODEL];
__device__ __align__(256) float g_twr[DHEAD*DHEAD];
__device__ __align__(256) float g_w2r[DHEAD*DHEAD];
__device__ __align__(256) float g_wdr[DHEAD*DHEAD];
__device__ __align__(256) float g_w1cr[DHEAD*DHEAD];
__device__ float g_cvec[DHEAD];
__device__ int   g_active[MTOK];
__device__ int   g_flag[NROUNDS];

// ---------------- PTX helpers -------------------------------------------------
__device__ __forceinline__ uint32_t s2u(const void* p) {
    uint32_t a;
    asm("{ .reg .u64 t; cvta.to.shared.u64 t, %1; cvt.u32.u64 %0, t; }" : "=r"(a) : "l"(p));
    return a;
}
__device__ __forceinline__ float rna_tf32(float f) {
    float o;
    asm("cvt.rna.tf32.f32 %0, %1;" : "=f"(o) : "f"(f));
    return o;
}
__device__ __forceinline__ void cp_async16(uint32_t dst, const void* src) {
    asm volatile("cp.async.cg.shared.global [%0], [%1], 16;" :: "r"(dst), "l"(src) : "memory");
}
#define CP_COMMIT() asm volatile("cp.async.commit_group;" ::: "memory")
#define CP_WAIT(N)  asm volatile("cp.async.wait_group %0;" :: "n"(N) : "memory")

__device__ __forceinline__ void mma_tf32(
    float& c0, float& c1, float& c2, float& c3,
    uint32_t a0, uint32_t a1, uint32_t a2, uint32_t a3,
    uint32_t b0, uint32_t b1)
{
    asm volatile(
        "mma.sync.aligned.m16n8k8.row.col.f32.tf32.tf32.f32 "
        "{%0,%1,%2,%3}, {%4,%5,%6,%7}, {%8,%9}, {%0,%1,%2,%3};"
        : "+f"(c0), "+f"(c1), "+f"(c2), "+f"(c3)
        : "r"(a0), "r"(a1), "r"(a2), "r"(a3), "r"(b0), "r"(b1));
}

// ---------------- tensor-core tf32 NT GEMM ------------------------------------
// C = alpha * A(MxK) * B(NxK)^T ; block tile 128x128, BK=32, 256 thr, 8 warps.
// mode 0: C = alpha*acc ; mode 1: C = rna(alpha*acc)
// mode 2: C = rna(relu(active[row]*(acc + zfix + cvec) + b1))   (alpha ignored=1)
#define SMS   36
#define STG_F (2*128*SMS)              // floats per stage (A+B)
#define SMEM_GEMM_BYTES (2*STG_F*4)    // 73728

__global__ __launch_bounds__(256) void gemm_mma(
    const float* __restrict__ A, int lda, size_t sA,
    const float* __restrict__ B, int ldb, size_t sB,
    float* __restrict__ C, int ldc, size_t sC,
    int Kdim, float alpha, int mode,
    const float* __restrict__ zfix, const float* __restrict__ cvec,
    const float* __restrict__ b1v, const int* __restrict__ activep)
{
    extern __shared__ float sm[];
    const uint32_t sm_u = s2u(sm);
    A += (size_t)blockIdx.z * sA;
    B += (size_t)blockIdx.z * sB;
    C += (size_t)blockIdx.z * sC;
    const int tid  = threadIdx.x;
    const int lane = tid & 31;
    const int warp = tid >> 5;
    const int wm = (warp >> 1) * 32;
    const int wn = (warp & 1) * 64;
    const int m0 = blockIdx.x * 128;
    const int n0 = blockIdx.y * 128;

    const int lrow = tid >> 3;           // +32 per iter
    const int lc4  = (tid & 7) * 4;

    const int nK = Kdim >> 5;

    {
        const float* Ag = A + (size_t)m0 * lda + lc4;
        const float* Bg = B + (size_t)n0 * ldb + lc4;
        uint32_t dA = sm_u + (uint32_t)(lrow * SMS + lc4) * 4u;
        uint32_t dB = dA + 128u * SMS * 4u;
        #pragma unroll
        for (int it = 0; it < 4; it++) {
            cp_async16(dA + it * 32u * SMS * 4u, Ag + (size_t)(lrow + it*32) * lda);
            cp_async16(dB + it * 32u * SMS * 4u, Bg + (size_t)(lrow + it*32) * ldb);
        }
        CP_COMMIT();
    }

    float acc[2][8][4];
    #pragma unroll
    for (int mi = 0; mi < 2; mi++)
        #pragma unroll
        for (int ni = 0; ni < 8; ni++)
            #pragma unroll
            for (int j = 0; j < 4; j++) acc[mi][ni][j] = 0.f;

    const int g  = lane >> 2;
    const int t4 = lane & 3;

    for (int kt = 0; kt < nK; kt++) {
        int cs = kt & 1;
        if (kt + 1 < nK) {
            int ns = cs ^ 1;
            const float* Ag = A + (size_t)m0 * lda + (kt+1)*32 + lc4;
            const float* Bg = B + (size_t)n0 * ldb + (kt+1)*32 + lc4;
            uint32_t dA = sm_u + (uint32_t)(ns * STG_F + lrow * SMS + lc4) * 4u;
            uint32_t dB = dA + 128u * SMS * 4u;
            #pragma unroll
            for (int it = 0; it < 4; it++) {
                cp_async16(dA + it * 32u * SMS * 4u, Ag + (size_t)(lrow + it*32) * lda);
                cp_async16(dB + it * 32u * SMS * 4u, Bg + (size_t)(lrow + it*32) * ldb);
            }
            CP_COMMIT();
            CP_WAIT(1);
        } else {
            CP_WAIT(0);
        }
        __syncthreads();

        const float* Asf = sm + cs * STG_F;
        const float* Bsf = Asf + 128 * SMS;

        #pragma unroll
        for (int kk = 0; kk < 4; kk++) {
            const int k8 = kk * 8;
            uint32_t a[2][4];
            #pragma unroll
            for (int mi = 0; mi < 2; mi++) {
                const float* ap = Asf + (wm + mi*16 + g) * SMS + k8 + t4;
                a[mi][0] = __float_as_uint(ap[0]);
                a[mi][1] = __float_as_uint(ap[8*SMS]);
                a[mi][2] = __float_as_uint(ap[4]);
                a[mi][3] = __float_as_uint(ap[8*SMS + 4]);
            }
            uint32_t b[8][2];
            #pragma unroll
            for (int ni = 0; ni < 8; ni++) {
                const float* bp = Bsf + (wn + ni*8 + g) * SMS + k8 + t4;
                b[ni][0] = __float_as_uint(bp[0]);
                b[ni][1] = __float_as_uint(bp[4]);
            }
            #pragma unroll
            for (int mi = 0; mi < 2; mi++)
                #pragma unroll
                for (int ni = 0; ni < 8; ni++)
                    mma_tf32(acc[mi][ni][0], acc[mi][ni][1], acc[mi][ni][2], acc[mi][ni][3],
                             a[mi][0], a[mi][1], a[mi][2], a[mi][3],
                             b[ni][0], b[ni][1]);
        }
        __syncthreads();
    }

    // epilogue
    #pragma unroll
    for (int mi = 0; mi < 2; mi++) {
        const int rA = m0 + wm + mi*16 + g;
        const int rB = rA + 8;
        float amA = 0.f, amB = 0.f;
        if (mode == 2) {
            amA = activep[rA] ? 1.f : 0.f;
            amB = activep[rB] ? 1.f : 0.f;
        }
        #pragma unroll
        for (int ni = 0; ni < 8; ni++) {
            const int c0 = n0 + wn + ni*8 + 2*t4;
            float2 v0, v1;
            if (mode == 2) {
                float2 zA = *reinterpret_cast<const float2*>(zfix + (size_t)rA*ldc + c0);
                float2 zB = *reinterpret_cast<const float2*>(zfix + (size_t)rB*ldc + c0);
                float2 cc = *reinterpret_cast<const float2*>(cvec + c0);
                float2 bb = *reinterpret_cast<const float2*>(b1v + c0);
                v0.x = rna_tf32(fmaxf(fmaf(amA, acc[mi][ni][0] + zA.x + cc.x, bb.x), 0.f));
                v0.y = rna_tf32(fmaxf(fmaf(amA, acc[mi][ni][1] + zA.y + cc.y, bb.y), 0.f));
                v1.x = rna_tf32(fmaxf(fmaf(amB, acc[mi][ni][2] + zB.x + cc.x, bb.x), 0.f));
                v1.y = rna_tf32(fmaxf(fmaf(amB, acc[mi][ni][3] + zB.y + cc.y, bb.y), 0.f));
            } else {
                v0.x = acc[mi][ni][0] * alpha; v0.y = acc[mi][ni][1] * alpha;
                v1.x = acc[mi][ni][2] * alpha; v1.y = acc[mi][ni][3] * alpha;
                if (mode == 1) {
                    v0.x = rna_tf32(v0.x); v0.y = rna_tf32(v0.y);
                    v1.x = rna_tf32(v1.x); v1.y = rna_tf32(v1.y);
                }
            }
            *reinterpret_cast<float2*>(C + (size_t)rA * ldc + c0) = v0;
            *reinterpret_cast<float2*>(C + (size_t)rB * ldc + c0) = v1;
        }
    }
}

// ---------------- fused flash attention ---------------------------------------
// Grid: (SEQ/128, BATCH). 256 threads, 8 warps; warp handles 16 Q rows.
// Q fragments in registers; K/V tiles (64 kv) double-buffered via cp.async.
#define KVT 64
#define KS_STRIDE 132
#define VS_STRIDE 68
#define PS_STRIDE 68
#define FL_K_OFF 0
#define FL_V_OFF (2*64*KS_STRIDE)                   // 16896 floats
#define FL_P_OFF (FL_V_OFF + 2*128*VS_STRIDE)       // 34304 floats
#define FL_SMEM_FLOATS (FL_P_OFF + 8*16*PS_STRIDE)  // 43008 floats
#define FL_SMEM_BYTES (FL_SMEM_FLOATS*4)            // 172032 B

__global__ __launch_bounds__(256) void flash_attn(
    const float* __restrict__ q, const float* __restrict__ k,
    const float* __restrict__ vt, float* __restrict__ outc,
    float* __restrict__ outR)
{
    extern __shared__ float sm[];
    const uint32_t sm_u = s2u(sm);
    const int b   = blockIdx.y;
    const int qb  = blockIdx.x * 128;
    const int tid = threadIdx.x, lane = tid & 31, warp = tid >> 5;
    const int g   = lane >> 2, t4 = lane & 3;

    const float* qB = q  + ((size_t)b*SEQ + qb)*DHEAD;
    const float* kB = k  + (size_t)b*SEQ*DHEAD;
    const float* vB = vt + (size_t)b*DHEAD*SEQ;

    // cooperative load indices (full tiles: K 64x128, V 128x64)
    const int kc = tid >> 5;          // 0..7   (+8 per iter, 8 iters)
    const int kf = (tid & 31) * 4;    // 0..124
    const int vc = tid >> 4;          // 0..15  (+16 per iter, 8 iters)
    const int vf = (tid & 15) * 4;    // 0..60

    // Q fragments (q already tf32-rounded)
    uint32_t qa[16][4];
    {
        const float* q0 = qB + (size_t)(warp*16 + g)*DHEAD;
        const float* q8 = q0 + 8*DHEAD;
        #pragma unroll
        for (int ks = 0; ks < 16; ks++) {
            qa[ks][0] = __float_as_uint(q0[8*ks + t4]);
            qa[ks][1] = __float_as_uint(q8[8*ks + t4]);
            qa[ks][2] = __float_as_uint(q0[8*ks + t4 + 4]);
            qa[ks][3] = __float_as_uint(q8[8*ks + t4 + 4]);
        }
    }

    float oacc[16][4];
    #pragma unroll
    for (int ni = 0; ni < 16; ni++)
        #pragma unroll
        for (int j = 0; j < 4; j++) oacc[ni][j] = 0.f;
    float m0 = -1e30f, m1 = -1e30f, l0 = 0.f, l1 = 0.f;

    // prefetch tile 0
    {
        #pragma unroll
        for (int it = 0; it < 8; it++) {
            cp_async16(sm_u + (uint32_t)(FL_K_OFF + (kc + it*8)*KS_STRIDE + kf)*4u,
                       kB + (size_t)(kc + it*8)*DHEAD + kf);
            cp_async16(sm_u + (uint32_t)(FL_V_OFF + (vc + it*16)*VS_STRIDE + vf)*4u,
                       vB + (size_t)(vc + it*16)*SEQ + vf);
        }
        CP_COMMIT();
    }

    const int nTiles = SEQ / KVT;  // 32
    for (int t = 0; t < nTiles; t++) {
        const int cs = t & 1;
        if (t + 1 < nTiles) {
            const int ns = cs ^ 1;
            const int kv1 = (t+1) * KVT;
            #pragma unroll
            for (int it = 0; it < 8; it++) {
                cp_async16(sm_u + (uint32_t)(FL_K_OFF + ns*64*KS_STRIDE + (kc + it*8)*KS_STRIDE + kf)*4u,
                           kB + (size_t)(kv1 + kc + it*8)*DHEAD + kf);
                cp_async16(sm_u + (uint32_t)(FL_V_OFF + ns*128*VS_STRIDE + (vc + it*16)*VS_STRIDE + vf)*4u,
                           vB + (size_t)(vc + it*16)*SEQ + kv1 + vf);
            }
            CP_COMMIT();
            CP_WAIT(1);
        } else {
            CP_WAIT(0);
        }
        __syncthreads();

        const float* Ks = sm + FL_K_OFF + cs*64*KS_STRIDE;
        const float* Vs = sm + FL_V_OFF + cs*128*VS_STRIDE;
        float* Pw = sm + FL_P_OFF + warp*16*PS_STRIDE;

        // S = Q @ K^T (16 x 64 per warp)
        float sacc[8][4];
        #pragma unroll
        for (int ni = 0; ni < 8; ni++)
            #pragma unroll
            for (int j = 0; j < 4; j++) sacc[ni][j] = 0.f;
        #pragma unroll
        for (int ks = 0; ks < 16; ks++) {
            #pragma unroll
            for (int ni = 0; ni < 8; ni++) {
                const float* bp = Ks + (ni*8+g)*KS_STRIDE + ks*8 + t4;
                mma_tf32(sacc[ni][0], sacc[ni][1], sacc[ni][2], sacc[ni][3],
                         qa[ks][0], qa[ks][1], qa[ks][2], qa[ks][3],
                         __float_as_uint(bp[0]), __float_as_uint(bp[4]));
            }
        }

        // online softmax (rows g and g+8; stats across quad lanes t4)
        float mx0 = -1e30f, mx1 = -1e30f;
        #pragma unroll
        for (int ni = 0; ni < 8; ni++) {
            sacc[ni][0] *= SCALE_F; sacc[ni][1] *= SCALE_F;
            sacc[ni][2] *= SCALE_F; sacc[ni][3] *= SCALE_F;
            mx0 = fmaxf(mx0, fmaxf(sacc[ni][0], sacc[ni][1]));
            mx1 = fmaxf(mx1, fmaxf(sacc[ni][2], sacc[ni][3]));
        }
        mx0 = fmaxf(mx0, __shfl_xor_sync(0xffffffffu, mx0, 1));
        mx0 = fmaxf(mx0, __shfl_xor_sync(0xffffffffu, mx0, 2));
        mx1 = fmaxf(mx1, __shfl_xor_sync(0xffffffffu, mx1, 1));
        mx1 = fmaxf(mx1, __shfl_xor_sync(0xffffffffu, mx1, 2));
        const float nm0 = fmaxf(m0, mx0), nm1 = fmaxf(m1, mx1);
        const float sc0 = exp2f((m0 - nm0) * LOG2E_F);
        const float sc1 = exp2f((m1 - nm1) * LOG2E_F);
        m0 = nm0; m1 = nm1;
        float rs0 = 0.f, rs1 = 0.f;
        #pragma unroll
        for (int ni = 0; ni < 8; ni++) {
            float p0 = exp2f((sacc[ni][0] - nm0) * LOG2E_F);
            float p1 = exp2f((sacc[ni][1] - nm0) * LOG2E_F);
            float p2 = exp2f((sacc[ni][2] - nm1) * LOG2E_F);
            float p3 = exp2f((sacc[ni][3] - nm1) * LOG2E_F);
            rs0 += p0 + p1; rs1 += p2 + p3;
            Pw[g*PS_STRIDE + ni*8 + 2*t4]       = rna_tf32(p0);
            Pw[g*PS_STRIDE + ni*8 + 2*t4 + 1]   = rna_tf32(p1);
            Pw[(g+8)*PS_STRIDE + ni*8 + 2*t4]   = rna_tf32(p2);
            Pw[(g+8)*PS_STRIDE + ni*8 + 2*t4+1] = rna_tf32(p3);
        }
        rs0 += __shfl_xor_sync(0xffffffffu, rs0, 1);
        rs0 += __shfl_xor_sync(0xffffffffu, rs0, 2);
        rs1 += __shfl_xor_sync(0xffffffffu, rs1, 1);
        rs1 += __shfl_xor_sync(0xffffffffu, rs1, 2);
        l0 = l0 * sc0 + rs0;
        l1 = l1 * sc1 + rs1;
        #pragma unroll
        for (int ni = 0; ni < 16; ni++) {
            oacc[ni][0] *= sc0; oacc[ni][1] *= sc0;
            oacc[ni][2] *= sc1; oacc[ni][3] *= sc1;
        }
        __syncwarp();

        // O += P @ V  (A = P 16x64 from smem, B = Vt 128x64)
        #pragma unroll
        for (int ks = 0; ks < 8; ks++) {
            uint32_t pa0 = __float_as_uint(Pw[g*PS_STRIDE + ks*8 + t4]);
            uint32_t pa1 = __float_as_uint(Pw[(g+8)*PS_STRIDE + ks*8 + t4]);
            uint32_t pa2 = __float_as_uint(Pw[g*PS_STRIDE + ks*8 + t4 + 4]);
            uint32_t pa3 = __float_as_uint(Pw[(g+8)*PS_STRIDE + ks*8 + t4 + 4]);
            #pragma unroll
            for (int ni = 0; ni < 16; ni++) {
                const float* vp = Vs + (ni*8+g)*VS_STRIDE + ks*8 + t4;
                mma_tf32(oacc[ni][0], oacc[ni][1], oacc[ni][2], oacc[ni][3],
                         pa0, pa1, pa2, pa3,
                         __float_as_uint(vp[0]), __float_as_uint(vp[4]));
            }
        }
        __syncthreads();
    }

    // epilogue: normalize, write cur + rounded curR
    const float inv0 = 1.f / l0, inv1 = 1.f / l1;
    const size_t rowA = (size_t)b*SEQ + qb + warp*16 + g;
    const size_t rowB = rowA + 8;
    #pragma unroll
    for (int ni = 0; ni < 16; ni++) {
        const int c0 = ni*8 + 2*t4;
        float2 v0, v1;
        v0.x = oacc[ni][0]*inv0; v0.y = oacc[ni][1]*inv0;
        v1.x = oacc[ni][2]*inv1; v1.y = oacc[ni][3]*inv1;
        *reinterpret_cast<float2*>(outc + rowA*DHEAD + c0) = v0;
        *reinterpret_cast<float2*>(outc + rowB*DHEAD + c0) = v1;
        float2 r0, r1;
        r0.x = rna_tf32(v0.x); r0.y = rna_tf32(v0.y);
        r1.x = rna_tf32(v1.x); r1.y = rna_tf32(v1.y);
        *reinterpret_cast<float2*>(outR + rowA*DHEAD + c0) = r0;
        *reinterpret_cast<float2*>(outR + rowB*DHEAD + c0) = r1;
    }
}

// ---------------- small prep kernels -----------------------------------------
__global__ void round_arr(const float* __restrict__ in, float* __restrict__ out, int n4)
{
    int i = blockIdx.x * blockDim.x + threadIdx.x;
    if (i < n4) {
        float4 v = reinterpret_cast<const float4*>(in)[i];
        v.x = rna_tf32(v.x); v.y = rna_tf32(v.y); v.z = rna_tf32(v.z); v.w = rna_tf32(v.w);
        reinterpret_cast<float4*>(out)[i] = v;
    }
}

__global__ void transpose_v(const float* __restrict__ v, float* __restrict__ vt)
{
    __shared__ float t[32][33];
    int b = blockIdx.z;
    int s0 = blockIdx.x * 32, d0 = blockIdx.y * 32;
    int x = threadIdx.x, y = threadIdx.y;   // 32 x 8
    #pragma unroll
    for (int j = y; j < 32; j += 8)
        t[j][x] = v[((size_t)b*SEQ + s0 + j) * DHEAD + d0 + x];
    __syncthreads();
    #pragma unroll
    for (int j = y; j < 32; j += 8)
        vt[((size_t)b*DHEAD + d0 + j) * SEQ + s0 + x] = t[x][j];
}

__global__ void prep_wd(const float* __restrict__ w1, float* __restrict__ wd,
                        float* __restrict__ w1c)
{
    int idx = blockIdx.x * blockDim.x + threadIdx.x;   // 16384
    int j = idx >> 7, i = idx & 127;
    wd[idx]  = rna_tf32(w1[j*384 + i] - w1[j*384 + 128 + i]);
    w1c[idx] = rna_tf32(w1[j*384 + 256 + i]);
}

__global__ void prep_cvec(const float* __restrict__ w1, const float* __restrict__ tb,
                          const float* __restrict__ ab, float* __restrict__ cvec)
{
    int j = threadIdx.x;   // 128
    float s = 0.f;
    for (int i = 0; i < 128; i++)
        s += tb[i]*w1[j*384 + i] + ab[i]*w1[j*384 + 128 + i];
    cvec[j] = s;
}

__global__ void init_kernel(int* __restrict__ active, int* __restrict__ flag)
{
    int idx = blockIdx.x * blockDim.x + threadIdx.x;
    if (idx < MTOK)    active[idx] = 1;
    if (idx < NROUNDS) flag[idx]   = 0;
}

__global__ void any_active_kernel(const int* __restrict__ active,
                                  int* __restrict__ flag, int r)
{
    int a = 0;
    for (int m = threadIdx.x; m < MTOK; m += blockDim.x) a |= active[m];
    a = __syncthreads_or(a);
    if (threadIdx.x == 0) flag[r] = a ? 1 : 0;
}

// gate + update + norm + conditional apply; also writes rounded curR
__global__ __launch_bounds__(128) void apply_kernel(
    float* __restrict__ cur, float* __restrict__ curR,
    const float* __restrict__ synth,
    const float* __restrict__ b2, const float* __restrict__ gw,
    const float* __restrict__ gb, int* __restrict__ active,
    const int* __restrict__ flag, int r)
{
    const int m = blockIdx.x;
    const int i = threadIdx.x;
    float c  = cur[(size_t)m*DHEAD + i];
    float sy = synth[(size_t)m*DHEAD + i] + b2[i];
    int   act = active[m];
    float am  = act ? 1.f : 0.f;
    float ac  = c * am;
    __shared__ float r1[4], r2[4];
    float v = ac * gw[i] + sy * gw[DHEAD + i];
    #pragma unroll
    for (int o = 16; o; o >>= 1) v += __shfl_xor_sync(0xffffffffu, v, o);
    if ((i & 31) == 0) r1[i >> 5] = v;
    __syncthreads();
    float gdot = r1[0] + r1[1] + r1[2] + r1[3] + gb[0];
    float gate = 1.f / (1.f + expf(-gdot));
    float upd  = gate * (sy - ac) * 0.1f;
    float u2 = upd * upd;
    #pragma unroll
    for (int o = 16; o; o >>= 1) u2 += __shfl_xor_sync(0xffffffffu, u2, o);
    if ((i & 31) == 0) r2[i >> 5] = u2;
    __syncthreads();
    float n2 = r2[0] + r2[1] + r2[2] + r2[3];
    float newc = c;
    if (flag[r]) {
        newc = c + upd;
        cur[(size_t)m*DHEAD + i] = newc;
        if (i == 0) active[m] = act && !(sqrtf(n2) < 0.1f);
    }
    curR[(size_t)m*DHEAD + i] = rna_tf32(newc);
}

// ---------------- launch ------------------------------------------------------
extern "C" void kernel_launch(void* const* d_in, const int* in_sizes, int n_in,
                              void* d_out, int out_size)
{
    (void)in_sizes; (void)n_in; (void)out_size;
    const float* x  = (const float*)d_in[0];
    const float* wq = (const float*)d_in[1];
    const float* wk = (const float*)d_in[2];
    const float* wv = (const float*)d_in[3];
    const float* tw = (const float*)d_in[4];
    const float* tb = (const float*)d_in[5];
    const float* ab = (const float*)d_in[6];
    const float* w1 = (const float*)d_in[7];
    const float* b1 = (const float*)d_in[8];
    const float* w2 = (const float*)d_in[9];
    const float* b2 = (const float*)d_in[10];
    const float* gw = (const float*)d_in[11];
    const float* gb = (const float*)d_in[12];
    float* cur = (float*)d_out;

    float *xr,*q,*k,*v,*vt,*curR,*p,*zfix,*h,*synth;
    float *wqr,*wkr,*wvr,*twr,*w2r,*wdr,*w1cr,*cvec;
    int *active,*flag;
    cudaGetSymbolAddress((void**)&xr,     g_xr);
    cudaGetSymbolAddress((void**)&q,      g_q);
    cudaGetSymbolAddress((void**)&k,      g_k);
    cudaGetSymbolAddress((void**)&v,      g_v);
    cudaGetSymbolAddress((void**)&vt,     g_vt);
    cudaGetSymbolAddress((void**)&curR,   g_curR);
    cudaGetSymbolAddress((void**)&p,      g_p);
    cudaGetSymbolAddress((void**)&zfix,   g_zfix);
    cudaGetSymbolAddress((void**)&h,      g_h);
    cudaGetSymbolAddress((void**)&synth,  g_synth);
    cudaGetSymbolAddress((void**)&wqr,    g_wqr);
    cudaGetSymbolAddress((void**)&wkr,    g_wkr);
    cudaGetSymbolAddress((void**)&wvr,    g_wvr);
    cudaGetSymbolAddress((void**)&twr,    g_twr);
    cudaGetSymbolAddress((void**)&w2r,    g_w2r);
    cudaGetSymbolAddress((void**)&wdr,    g_wdr);
    cudaGetSymbolAddress((void**)&w1cr,   g_w1cr);
    cudaGetSymbolAddress((void**)&cvec,   g_cvec);
    cudaGetSymbolAddress((void**)&active, g_active);
    cudaGetSymbolAddress((void**)&flag,   g_flag);

    cudaFuncSetAttribute(gemm_mma,   cudaFuncAttributeMaxDynamicSharedMemorySize, SMEM_GEMM_BYTES);
    cudaFuncSetAttribute(flash_attn, cudaFuncAttributeMaxDynamicSharedMemorySize, FL_SMEM_BYTES);

    // ---- prep: round operands to tf32 (rna) -----------------------------------
    round_arr<<<(MTOK*DMODEL/4 + 255)/256, 256>>>(x,  xr,  MTOK*DMODEL/4);
    round_arr<<<(DHEAD*DMODEL/4 + 255)/256, 256>>>(wq, wqr, DHEAD*DMODEL/4);
    round_arr<<<(DHEAD*DMODEL/4 + 255)/256, 256>>>(wk, wkr, DHEAD*DMODEL/4);
    round_arr<<<(DHEAD*DMODEL/4 + 255)/256, 256>>>(wv, wvr, DHEAD*DMODEL/4);
    round_arr<<<(DHEAD*DHEAD/4  + 255)/256, 256>>>(tw, twr, DHEAD*DHEAD/4);
    round_arr<<<(DHEAD*DHEAD/4  + 255)/256, 256>>>(w2, w2r, DHEAD*DHEAD/4);
    prep_wd<<<DHEAD*DHEAD/256, 256>>>(w1, wdr, w1cr);
    prep_cvec<<<1,128>>>(w1, tb, ab, cvec);
    init_kernel<<<64,256>>>(active, flag);

    // ---- q/k/v projections (rounded outputs feed flash) ------------------------
    gemm_mma<<<dim3(MTOK/128,1,1), 256, SMEM_GEMM_BYTES>>>(
        xr, DMODEL, 0, wqr, DMODEL, 0, q, DHEAD, 0, DMODEL, 1.f, 1, 0,0,0,0);
    gemm_mma<<<dim3(MTOK/128,1,1), 256, SMEM_GEMM_BYTES>>>(
        xr, DMODEL, 0, wkr, DMODEL, 0, k, DHEAD, 0, DMODEL, 1.f, 1, 0,0,0,0);
    gemm_mma<<<dim3(MTOK/128,1,1), 256, SMEM_GEMM_BYTES>>>(
        xr, DMODEL, 0, wvr, DMODEL, 0, v, DHEAD, 0, DMODEL, 1.f, 1, 0,0,0,0);

    transpose_v<<<dim3(SEQ/32, DHEAD/32, BATCH), dim3(32,8)>>>(v, vt);

    // ---- fused attention: cur = softmax(qk^T*scale) @ v ------------------------
    flash_attn<<<dim3(SEQ/128, BATCH), 256, FL_SMEM_BYTES>>>(q, k, vt, cur, curR);

    // ---- round-invariant precompute: zfix = (cur0@tw^T)@(W1a-W1b)^T ------------
    gemm_mma<<<dim3(MTOK/128,1,1), 256, SMEM_GEMM_BYTES>>>(
        curR, DHEAD, 0, twr, DHEAD, 0, p, DHEAD, 0, DHEAD, 1.f, 1, 0,0,0,0);
    gemm_mma<<<dim3(MTOK/128,1,1), 256, SMEM_GEMM_BYTES>>>(
        p, DHEAD, 0, wdr, DHEAD, 0, zfix, DHEAD, 0, DHEAD, 1.f, 0, 0,0,0,0);

    for (int r = 0; r < NROUNDS; r++) {
        any_active_kernel<<<1,1024>>>(active, flag, r);
        // h = rna(relu(am*(cur@W1c^T + zfix + cvec) + b1))  — fused epilogue
        gemm_mma<<<dim3(MTOK/128,1,1), 256, SMEM_GEMM_BYTES>>>(
            curR, DHEAD, 0, w1cr, DHEAD, 0, h, DHEAD, 0, DHEAD, 1.f, 2,
            zfix, cvec, b1, active);
        gemm_mma<<<dim3(MTOK/128,1,1), 256, SMEM_GEMM_BYTES>>>(
            h, DHEAD, 0, w2r, DHEAD, 0, synth, DHEAD, 0, DHEAD, 1.f, 0, 0,0,0,0);
        apply_kernel<<<MTOK,128>>>(cur, curR, synth, b2, gw, gb, active, flag, r);
    }
}

// round 6
// speedup vs baseline: 4.0943x; 1.1608x over previous
#include <cuda_runtime.h>
#include <math.h>
#include <stdint.h>

#define BATCH   8
#define SEQ     2048
#define DMODEL  1024
#define DHEAD   128
#define MTOK    (BATCH*SEQ)          // 16384
#define NROUNDS 3
#define SCALE_F 0.08838834764831843f // 1/sqrt(128)
#define LOG2E_F 1.4426950408889634f

// ---------------- device scratch (no runtime allocation allowed) -------------
__device__ __align__(256) float g_xr[MTOK*DMODEL];            // rounded x
__device__ __align__(256) float g_qkv[3*MTOK*DHEAD];          // q,k,v contiguous
__device__ __align__(256) float g_vt[BATCH*DHEAD*SEQ];        // v transposed per batch
__device__ __align__(256) float g_curR[MTOK*DHEAD];           // rounded copy of cur
__device__ __align__(256) float g_zfix[MTOK*DHEAD];
__device__ __align__(256) float g_wqkvr[3*DHEAD*DMODEL];
__device__ __align__(256) float g_twr[DHEAD*DHEAD];
__device__ __align__(256) float g_w2r[DHEAD*DHEAD];
__device__ __align__(256) float g_wdr[DHEAD*DHEAD];
__device__ __align__(256) float g_w1cr[DHEAD*DHEAD];
__device__ float g_cvec[DHEAD];
__device__ int   g_active[MTOK];
__device__ int   g_flag[NROUNDS];

// ---------------- PTX helpers -------------------------------------------------
__device__ __forceinline__ uint32_t s2u(const void* p) {
    uint32_t a;
    asm("{ .reg .u64 t; cvta.to.shared.u64 t, %1; cvt.u32.u64 %0, t; }" : "=r"(a) : "l"(p));
    return a;
}
__device__ __forceinline__ float rna_tf32(float f) {
    float o;
    asm("cvt.rna.tf32.f32 %0, %1;" : "=f"(o) : "f"(f));
    return o;
}
__device__ __forceinline__ void cp_async16(uint32_t dst, const void* src) {
    asm volatile("cp.async.cg.shared.global [%0], [%1], 16;" :: "r"(dst), "l"(src) : "memory");
}
#define CP_COMMIT() asm volatile("cp.async.commit_group;" ::: "memory")
#define CP_WAIT(N)  asm volatile("cp.async.wait_group %0;" :: "n"(N) : "memory")

__device__ __forceinline__ void mma_tf32(
    float& c0, float& c1, float& c2, float& c3,
    uint32_t a0, uint32_t a1, uint32_t a2, uint32_t a3,
    uint32_t b0, uint32_t b1)
{
    asm volatile(
        "mma.sync.aligned.m16n8k8.row.col.f32.tf32.tf32.f32 "
        "{%0,%1,%2,%3}, {%4,%5,%6,%7}, {%8,%9}, {%0,%1,%2,%3};"
        : "+f"(c0), "+f"(c1), "+f"(c2), "+f"(c3)
        : "r"(a0), "r"(a1), "r"(a2), "r"(a3), "r"(b0), "r"(b1));
}

// ---------------- tensor-core tf32 NT GEMM (pipelined, large-K) ---------------
// C = alpha * A(MxK) * W(NxK)^T ; block tile 128x128, BK=32, 256 thr, 8 warps.
// mode 0: C = alpha*acc ; mode 1: C = rna(alpha*acc)
#define SMS   36
#define STG_F (2*128*SMS)
#define SMEM_GEMM_BYTES (2*STG_F*4)    // 73728

__global__ __launch_bounds__(256) void gemm_mma(
    const float* __restrict__ A, int lda, size_t sA,
    const float* __restrict__ B, int ldb, size_t sB,
    float* __restrict__ C, int ldc, size_t sC,
    int Kdim, float alpha, int mode)
{
    extern __shared__ float sm[];
    const uint32_t sm_u = s2u(sm);
    A += (size_t)blockIdx.z * sA;
    B += (size_t)blockIdx.z * sB;
    C += (size_t)blockIdx.z * sC;
    const int tid  = threadIdx.x;
    const int lane = tid & 31;
    const int warp = tid >> 5;
    const int wm = (warp >> 1) * 32;
    const int wn = (warp & 1) * 64;
    const int m0 = blockIdx.x * 128;
    const int n0 = blockIdx.y * 128;

    const int lrow = tid >> 3;
    const int lc4  = (tid & 7) * 4;

    const int nK = Kdim >> 5;

    {
        const float* Ag = A + (size_t)m0 * lda + lc4;
        const float* Bg = B + (size_t)n0 * ldb + lc4;
        uint32_t dA = sm_u + (uint32_t)(lrow * SMS + lc4) * 4u;
        uint32_t dB = dA + 128u * SMS * 4u;
        #pragma unroll
        for (int it = 0; it < 4; it++) {
            cp_async16(dA + it * 32u * SMS * 4u, Ag + (size_t)(lrow + it*32) * lda);
            cp_async16(dB + it * 32u * SMS * 4u, Bg + (size_t)(lrow + it*32) * ldb);
        }
        CP_COMMIT();
    }

    float acc[2][8][4];
    #pragma unroll
    for (int mi = 0; mi < 2; mi++)
        #pragma unroll
        for (int ni = 0; ni < 8; ni++)
            #pragma unroll
            for (int j = 0; j < 4; j++) acc[mi][ni][j] = 0.f;

    const int g  = lane >> 2;
    const int t4 = lane & 3;

    for (int kt = 0; kt < nK; kt++) {
        int cs = kt & 1;
        if (kt + 1 < nK) {
            int ns = cs ^ 1;
            const float* Ag = A + (size_t)m0 * lda + (kt+1)*32 + lc4;
            const float* Bg = B + (size_t)n0 * ldb + (kt+1)*32 + lc4;
            uint32_t dA = sm_u + (uint32_t)(ns * STG_F + lrow * SMS + lc4) * 4u;
            uint32_t dB = dA + 128u * SMS * 4u;
            #pragma unroll
            for (int it = 0; it < 4; it++) {
                cp_async16(dA + it * 32u * SMS * 4u, Ag + (size_t)(lrow + it*32) * lda);
                cp_async16(dB + it * 32u * SMS * 4u, Bg + (size_t)(lrow + it*32) * ldb);
            }
            CP_COMMIT();
            CP_WAIT(1);
        } else {
            CP_WAIT(0);
        }
        __syncthreads();

        const float* Asf = sm + cs * STG_F;
        const float* Bsf = Asf + 128 * SMS;

        #pragma unroll
        for (int kk = 0; kk < 4; kk++) {
            const int k8 = kk * 8;
            uint32_t a[2][4];
            #pragma unroll
            for (int mi = 0; mi < 2; mi++) {
                const float* ap = Asf + (wm + mi*16 + g) * SMS + k8 + t4;
                a[mi][0] = __float_as_uint(ap[0]);
                a[mi][1] = __float_as_uint(ap[8*SMS]);
                a[mi][2] = __float_as_uint(ap[4]);
                a[mi][3] = __float_as_uint(ap[8*SMS + 4]);
            }
            uint32_t b[8][2];
            #pragma unroll
            for (int ni = 0; ni < 8; ni++) {
                const float* bp = Bsf + (wn + ni*8 + g) * SMS + k8 + t4;
                b[ni][0] = __float_as_uint(bp[0]);
                b[ni][1] = __float_as_uint(bp[4]);
            }
            #pragma unroll
            for (int mi = 0; mi < 2; mi++)
                #pragma unroll
                for (int ni = 0; ni < 8; ni++)
                    mma_tf32(acc[mi][ni][0], acc[mi][ni][1], acc[mi][ni][2], acc[mi][ni][3],
                             a[mi][0], a[mi][1], a[mi][2], a[mi][3],
                             b[ni][0], b[ni][1]);
        }
        __syncthreads();
    }

    #pragma unroll
    for (int mi = 0; mi < 2; mi++) {
        const int rA = m0 + wm + mi*16 + g;
        const int rB = rA + 8;
        #pragma unroll
        for (int ni = 0; ni < 8; ni++) {
            const int c0 = n0 + wn + ni*8 + 2*t4;
            float2 v0, v1;
            v0.x = acc[mi][ni][0] * alpha; v0.y = acc[mi][ni][1] * alpha;
            v1.x = acc[mi][ni][2] * alpha; v1.y = acc[mi][ni][3] * alpha;
            if (mode == 1) {
                v0.x = rna_tf32(v0.x); v0.y = rna_tf32(v0.y);
                v1.x = rna_tf32(v1.x); v1.y = rna_tf32(v1.y);
            }
            *reinterpret_cast<float2*>(C + (size_t)rA * ldc + c0) = v0;
            *reinterpret_cast<float2*>(C + (size_t)rB * ldc + c0) = v1;
        }
    }
}

// ---------------- fused double-GEMM kernels (K = 128, smem-resident) ----------
#define RSMS 132
#define F_T0 0                   // A then (reused) H/P
#define F_T1 (128*RSMS)          // W1
#define F_T2 (2*128*RSMS)        // W2
#define F_RED (3*128*RSMS)       // 128*4 reduction floats
#define FUSED_SMEM_BYTES ((3*128*RSMS + 128*4)*4)   // 204800

__device__ __forceinline__ void load_tile128(uint32_t sdst, const float* __restrict__ src,
                                             int lrow, int lc4)
{
    #pragma unroll
    for (int kt = 0; kt < 4; kt++)
        #pragma unroll
        for (int it = 0; it < 4; it++)
            cp_async16(sdst + (uint32_t)((lrow + it*32)*RSMS + kt*32 + lc4)*4u,
                       src + (size_t)(lrow + it*32)*128 + kt*32 + lc4);
}

__device__ __forceinline__ void mma_128x128(const float* __restrict__ As,
                                            const float* __restrict__ Bs,
                                            float acc[2][8][4],
                                            int wm, int wn, int g, int t4)
{
    #pragma unroll
    for (int k8 = 0; k8 < 16; k8++) {
        const int ko = k8*8 + t4;
        uint32_t a[2][4];
        #pragma unroll
        for (int mi = 0; mi < 2; mi++) {
            const float* ap = As + (wm + mi*16 + g)*RSMS + ko;
            a[mi][0] = __float_as_uint(ap[0]);
            a[mi][1] = __float_as_uint(ap[8*RSMS]);
            a[mi][2] = __float_as_uint(ap[4]);
            a[mi][3] = __float_as_uint(ap[8*RSMS + 4]);
        }
        #pragma unroll
        for (int ni = 0; ni < 8; ni++) {
            const float* bp = Bs + (wn + ni*8 + g)*RSMS + ko;
            uint32_t b0 = __float_as_uint(bp[0]);
            uint32_t b1r = __float_as_uint(bp[4]);
            #pragma unroll
            for (int mi = 0; mi < 2; mi++)
                mma_tf32(acc[mi][ni][0], acc[mi][ni][1], acc[mi][ni][2], acc[mi][ni][3],
                         a[mi][0], a[mi][1], a[mi][2], a[mi][3], b0, b1r);
        }
    }
}

// zfix = (curR @ tw^T rounded) @ wd^T
__global__ __launch_bounds__(256) void zfix_fused(
    const float* __restrict__ curR, const float* __restrict__ tw,
    const float* __restrict__ wd, float* __restrict__ zfix)
{
    extern __shared__ float sm[];
    const uint32_t sm_u = s2u(sm);
    const int tid = threadIdx.x, lane = tid & 31, warp = tid >> 5;
    const int wm = (warp >> 1) * 32, wn = (warp & 1) * 64;
    const int g = lane >> 2, t4 = lane & 3;
    const int m0 = blockIdx.x * 128;
    const int lrow = tid >> 3, lc4 = (tid & 7) * 4;

    load_tile128(sm_u + F_T0*4, curR + (size_t)m0*128, lrow, lc4);
    load_tile128(sm_u + F_T1*4, tw, lrow, lc4);
    load_tile128(sm_u + F_T2*4, wd, lrow, lc4);
    CP_COMMIT(); CP_WAIT(0);
    __syncthreads();

    float acc[2][8][4];
    #pragma unroll
    for (int mi = 0; mi < 2; mi++)
        #pragma unroll
        for (int ni = 0; ni < 8; ni++)
            #pragma unroll
            for (int j = 0; j < 4; j++) acc[mi][ni][j] = 0.f;

    mma_128x128(sm + F_T0, sm + F_T1, acc, wm, wn, g, t4);
    __syncthreads();

    // p = rna(acc) -> T0 (overwrite A)
    float* Ps = sm + F_T0;
    #pragma unroll
    for (int mi = 0; mi < 2; mi++) {
        const int rA = wm + mi*16 + g, rB = rA + 8;
        #pragma unroll
        for (int ni = 0; ni < 8; ni++) {
            const int c0 = wn + ni*8 + 2*t4;
            float2 p0, p1;
            p0.x = rna_tf32(acc[mi][ni][0]); p0.y = rna_tf32(acc[mi][ni][1]);
            p1.x = rna_tf32(acc[mi][ni][2]); p1.y = rna_tf32(acc[mi][ni][3]);
            *reinterpret_cast<float2*>(&Ps[rA*RSMS + c0]) = p0;
            *reinterpret_cast<float2*>(&Ps[rB*RSMS + c0]) = p1;
        }
    }
    __syncthreads();

    #pragma unroll
    for (int mi = 0; mi < 2; mi++)
        #pragma unroll
        for (int ni = 0; ni < 8; ni++)
            #pragma unroll
            for (int j = 0; j < 4; j++) acc[mi][ni][j] = 0.f;

    mma_128x128(sm + F_T0, sm + F_T2, acc, wm, wn, g, t4);

    #pragma unroll
    for (int mi = 0; mi < 2; mi++) {
        const int rA = m0 + wm + mi*16 + g, rB = rA + 8;
        #pragma unroll
        for (int ni = 0; ni < 8; ni++) {
            const int c0 = wn + ni*8 + 2*t4;
            float2 v0, v1;
            v0.x = acc[mi][ni][0]; v0.y = acc[mi][ni][1];
            v1.x = acc[mi][ni][2]; v1.y = acc[mi][ni][3];
            *reinterpret_cast<float2*>(zfix + (size_t)rA*128 + c0) = v0;
            *reinterpret_cast<float2*>(zfix + (size_t)rB*128 + c0) = v1;
        }
    }
}

// One full dialectical round:
//   h = rna(relu(am*(curR@W1c^T + zfix + cvec) + b1))   (in smem)
//   synth = h @ w2^T + b2
//   gate/update/norm/apply + next-round flag
__global__ __launch_bounds__(256) void round_fused(
    float* __restrict__ cur, float* __restrict__ curR,
    const float* __restrict__ zfix,
    const float* __restrict__ w1c, const float* __restrict__ w2,
    const float* __restrict__ cvec, const float* __restrict__ b1,
    const float* __restrict__ b2, const float* __restrict__ gw,
    const float* __restrict__ gb, int* __restrict__ active,
    int* __restrict__ flag, int r)
{
    extern __shared__ float sm[];
    const uint32_t sm_u = s2u(sm);
    __shared__ int s_any;
    const int tid = threadIdx.x, lane = tid & 31, warp = tid >> 5;
    const int wm = (warp >> 1) * 32, wn = (warp & 1) * 64;
    const int g = lane >> 2, t4 = lane & 3;
    const int m0 = blockIdx.x * 128;
    const int lrow = tid >> 3, lc4 = (tid & 7) * 4;
    if (tid == 0) s_any = 0;

    load_tile128(sm_u + F_T0*4, curR + (size_t)m0*128, lrow, lc4);
    load_tile128(sm_u + F_T1*4, w1c, lrow, lc4);
    load_tile128(sm_u + F_T2*4, w2, lrow, lc4);
    CP_COMMIT(); CP_WAIT(0);
    __syncthreads();

    float acc[2][8][4];
    #pragma unroll
    for (int mi = 0; mi < 2; mi++)
        #pragma unroll
        for (int ni = 0; ni < 8; ni++)
            #pragma unroll
            for (int j = 0; j < 4; j++) acc[mi][ni][j] = 0.f;

    mma_128x128(sm + F_T0, sm + F_T1, acc, wm, wn, g, t4);
    __syncthreads();

    // epilogue 1: h -> T0
    float amr[4];
    {
        float* Hs = sm + F_T0;
        #pragma unroll
        for (int mi = 0; mi < 2; mi++) {
            const int rA = wm + mi*16 + g, rB = rA + 8;
            const float amA = active[m0 + rA] ? 1.f : 0.f;
            const float amB = active[m0 + rB] ? 1.f : 0.f;
            amr[mi*2] = amA; amr[mi*2+1] = amB;
            #pragma unroll
            for (int ni = 0; ni < 8; ni++) {
                const int c0 = wn + ni*8 + 2*t4;
                float2 zA = *reinterpret_cast<const float2*>(zfix + (size_t)(m0+rA)*128 + c0);
                float2 zB = *reinterpret_cast<const float2*>(zfix + (size_t)(m0+rB)*128 + c0);
                float2 cc = *reinterpret_cast<const float2*>(cvec + c0);
                float2 bb = *reinterpret_cast<const float2*>(b1 + c0);
                float2 h0, h1;
                h0.x = rna_tf32(fmaxf(fmaf(amA, acc[mi][ni][0] + zA.x + cc.x, bb.x), 0.f));
                h0.y = rna_tf32(fmaxf(fmaf(amA, acc[mi][ni][1] + zA.y + cc.y, bb.y), 0.f));
                h1.x = rna_tf32(fmaxf(fmaf(amB, acc[mi][ni][2] + zB.x + cc.x, bb.x), 0.f));
                h1.y = rna_tf32(fmaxf(fmaf(amB, acc[mi][ni][3] + zB.y + cc.y, bb.y), 0.f));
                *reinterpret_cast<float2*>(&Hs[rA*RSMS + c0]) = h0;
                *reinterpret_cast<float2*>(&Hs[rB*RSMS + c0]) = h1;
            }
        }
    }
    __syncthreads();

    #pragma unroll
    for (int mi = 0; mi < 2; mi++)
        #pragma unroll
        for (int ni = 0; ni < 8; ni++)
            #pragma unroll
            for (int j = 0; j < 4; j++) acc[mi][ni][j] = 0.f;

    mma_128x128(sm + F_T0, sm + F_T2, acc, wm, wn, g, t4);

    // epilogue 2: reductions for gate and norm
    const int flg = flag[r];
    float d1[4] = {0,0,0,0}, nn[4] = {0,0,0,0};
    #pragma unroll
    for (int mi = 0; mi < 2; mi++) {
        const int rA = wm + mi*16 + g, rB = rA + 8;
        const float amA = amr[mi*2], amB = amr[mi*2+1];
        #pragma unroll
        for (int ni = 0; ni < 8; ni++) {
            const int c0 = wn + ni*8 + 2*t4;
            float2 cA = *reinterpret_cast<const float2*>(cur + (size_t)(m0+rA)*128 + c0);
            float2 cB = *reinterpret_cast<const float2*>(cur + (size_t)(m0+rB)*128 + c0);
            float2 bb = *reinterpret_cast<const float2*>(b2 + c0);
            float2 g1 = *reinterpret_cast<const float2*>(gw + c0);
            float2 g2 = *reinterpret_cast<const float2*>(gw + 128 + c0);
            float syA0 = acc[mi][ni][0] + bb.x, syA1 = acc[mi][ni][1] + bb.y;
            float syB0 = acc[mi][ni][2] + bb.x, syB1 = acc[mi][ni][3] + bb.y;
            float acA0 = cA.x * amA, acA1 = cA.y * amA;
            float acB0 = cB.x * amB, acB1 = cB.y * amB;
            d1[mi*2]   += acA0*g1.x + syA0*g2.x + acA1*g1.y + syA1*g2.y;
            d1[mi*2+1] += acB0*g1.x + syB0*g2.x + acB1*g1.y + syB1*g2.y;
            float dA0 = syA0-acA0, dA1 = syA1-acA1;
            float dB0 = syB0-acB0, dB1 = syB1-acB1;
            nn[mi*2]   += dA0*dA0 + dA1*dA1;
            nn[mi*2+1] += dB0*dB0 + dB1*dB1;
        }
    }
    #pragma unroll
    for (int j = 0; j < 4; j++) {
        d1[j] += __shfl_xor_sync(0xffffffffu, d1[j], 1);
        d1[j] += __shfl_xor_sync(0xffffffffu, d1[j], 2);
        nn[j] += __shfl_xor_sync(0xffffffffu, nn[j], 1);
        nn[j] += __shfl_xor_sync(0xffffffffu, nn[j], 2);
    }
    float* red = sm + F_RED;
    if (t4 == 0) {
        const int hf = (warp & 1) * 2;
        #pragma unroll
        for (int mi = 0; mi < 2; mi++) {
            const int rA = wm + mi*16 + g, rB = rA + 8;
            red[rA*4 + hf]     = d1[mi*2];
            red[rA*4 + hf + 1] = nn[mi*2];
            red[rB*4 + hf]     = d1[mi*2+1];
            red[rB*4 + hf + 1] = nn[mi*2+1];
        }
    }
    __syncthreads();

    const float gbv = gb[0];
    #pragma unroll
    for (int mi = 0; mi < 2; mi++) {
        const int rA = wm + mi*16 + g, rB = rA + 8;
        const float amA = amr[mi*2], amB = amr[mi*2+1];
        float gdA = red[rA*4+0] + red[rA*4+2] + gbv;
        float gdB = red[rB*4+0] + red[rB*4+2] + gbv;
        float n2A = red[rA*4+1] + red[rA*4+3];
        float n2B = red[rB*4+1] + red[rB*4+3];
        float gateA = 1.f / (1.f + expf(-gdA));
        float gateB = 1.f / (1.f + expf(-gdB));
        int stableA = (gateA * 0.1f * sqrtf(n2A)) < 0.1f;
        int stableB = (gateB * 0.1f * sqrtf(n2B)) < 0.1f;
        #pragma unroll
        for (int ni = 0; ni < 8; ni++) {
            const int c0 = wn + ni*8 + 2*t4;
            float2 cA = *reinterpret_cast<const float2*>(cur + (size_t)(m0+rA)*128 + c0);
            float2 cB = *reinterpret_cast<const float2*>(cur + (size_t)(m0+rB)*128 + c0);
            float2 bb = *reinterpret_cast<const float2*>(b2 + c0);
            float syA0 = acc[mi][ni][0] + bb.x, syA1 = acc[mi][ni][1] + bb.y;
            float syB0 = acc[mi][ni][2] + bb.x, syB1 = acc[mi][ni][3] + bb.y;
            float2 o0, o1;
            o0.x = cA.x; o0.y = cA.y; o1.x = cB.x; o1.y = cB.y;
            if (flg) {
                o0.x += gateA * (syA0 - cA.x*amA) * 0.1f;
                o0.y += gateA * (syA1 - cA.y*amA) * 0.1f;
                o1.x += gateB * (syB0 - cB.x*amB) * 0.1f;
                o1.y += gateB * (syB1 - cB.y*amB) * 0.1f;
            }
            *reinterpret_cast<float2*>(cur + (size_t)(m0+rA)*128 + c0) = o0;
            *reinterpret_cast<float2*>(cur + (size_t)(m0+rB)*128 + c0) = o1;
            float2 r0, r1;
            r0.x = rna_tf32(o0.x); r0.y = rna_tf32(o0.y);
            r1.x = rna_tf32(o1.x); r1.y = rna_tf32(o1.y);
            *reinterpret_cast<float2*>(curR + (size_t)(m0+rA)*128 + c0) = r0;
            *reinterpret_cast<float2*>(curR + (size_t)(m0+rB)*128 + c0) = r1;
        }
        if ((warp & 1) == 0 && t4 == 0) {
            int actA = amA > 0.f, actB = amB > 0.f;
            int naA = actA && !stableA;
            int naB = actB && !stableB;
            if (flg) { active[m0+rA] = naA; active[m0+rB] = naB; }
            int effA = flg ? naA : actA;
            int effB = flg ? naB : actB;
            if (effA | effB) s_any = 1;
        }
    }
    __syncthreads();
    if (tid == 0 && (r + 1) < NROUNDS && s_any) atomicOr(&flag[r+1], 1);
}

// ---------------- fused flash attention (unchanged from R5) -------------------
#define KVT 64
#define KS_STRIDE 132
#define VS_STRIDE 68
#define PS_STRIDE 68
#define FL_K_OFF 0
#define FL_V_OFF (2*64*KS_STRIDE)
#define FL_P_OFF (FL_V_OFF + 2*128*VS_STRIDE)
#define FL_SMEM_FLOATS (FL_P_OFF + 8*16*PS_STRIDE)
#define FL_SMEM_BYTES (FL_SMEM_FLOATS*4)

__global__ __launch_bounds__(256) void flash_attn(
    const float* __restrict__ q, const float* __restrict__ k,
    const float* __restrict__ vt, float* __restrict__ outc,
    float* __restrict__ outR)
{
    extern __shared__ float sm[];
    const uint32_t sm_u = s2u(sm);
    const int b   = blockIdx.y;
    const int qb  = blockIdx.x * 128;
    const int tid = threadIdx.x, lane = tid & 31, warp = tid >> 5;
    const int g   = lane >> 2, t4 = lane & 3;

    const float* qB = q  + ((size_t)b*SEQ + qb)*DHEAD;
    const float* kB = k  + (size_t)b*SEQ*DHEAD;
    const float* vB = vt + (size_t)b*DHEAD*SEQ;

    const int kc = tid >> 5;
    const int kf = (tid & 31) * 4;
    const int vc = tid >> 4;
    const int vf = (tid & 15) * 4;

    uint32_t qa[16][4];
    {
        const float* q0 = qB + (size_t)(warp*16 + g)*DHEAD;
        const float* q8 = q0 + 8*DHEAD;
        #pragma unroll
        for (int ks = 0; ks < 16; ks++) {
            qa[ks][0] = __float_as_uint(q0[8*ks + t4]);
            qa[ks][1] = __float_as_uint(q8[8*ks + t4]);
            qa[ks][2] = __float_as_uint(q0[8*ks + t4 + 4]);
            qa[ks][3] = __float_as_uint(q8[8*ks + t4 + 4]);
        }
    }

    float oacc[16][4];
    #pragma unroll
    for (int ni = 0; ni < 16; ni++)
        #pragma unroll
        for (int j = 0; j < 4; j++) oacc[ni][j] = 0.f;
    float m0 = -1e30f, m1 = -1e30f, l0 = 0.f, l1 = 0.f;

    {
        #pragma unroll
        for (int it = 0; it < 8; it++) {
            cp_async16(sm_u + (uint32_t)(FL_K_OFF + (kc + it*8)*KS_STRIDE + kf)*4u,
                       kB + (size_t)(kc + it*8)*DHEAD + kf);
            cp_async16(sm_u + (uint32_t)(FL_V_OFF + (vc + it*16)*VS_STRIDE + vf)*4u,
                       vB + (size_t)(vc + it*16)*SEQ + vf);
        }
        CP_COMMIT();
    }

    const int nTiles = SEQ / KVT;
    for (int t = 0; t < nTiles; t++) {
        const int cs = t & 1;
        if (t + 1 < nTiles) {
            const int ns = cs ^ 1;
            const int kv1 = (t+1) * KVT;
            #pragma unroll
            for (int it = 0; it < 8; it++) {
                cp_async16(sm_u + (uint32_t)(FL_K_OFF + ns*64*KS_STRIDE + (kc + it*8)*KS_STRIDE + kf)*4u,
                           kB + (size_t)(kv1 + kc + it*8)*DHEAD + kf);
                cp_async16(sm_u + (uint32_t)(FL_V_OFF + ns*128*VS_STRIDE + (vc + it*16)*VS_STRIDE + vf)*4u,
                           vB + (size_t)(vc + it*16)*SEQ + kv1 + vf);
            }
            CP_COMMIT();
            CP_WAIT(1);
        } else {
            CP_WAIT(0);
        }
        __syncthreads();

        const float* Ks = sm + FL_K_OFF + cs*64*KS_STRIDE;
        const float* Vs = sm + FL_V_OFF + cs*128*VS_STRIDE;
        float* Pw = sm + FL_P_OFF + warp*16*PS_STRIDE;

        float sacc[8][4];
        #pragma unroll
        for (int ni = 0; ni < 8; ni++)
            #pragma unroll
            for (int j = 0; j < 4; j++) sacc[ni][j] = 0.f;
        #pragma unroll
        for (int ks = 0; ks < 16; ks++) {
            #pragma unroll
            for (int ni = 0; ni < 8; ni++) {
                const float* bp = Ks + (ni*8+g)*KS_STRIDE + ks*8 + t4;
                mma_tf32(sacc[ni][0], sacc[ni][1], sacc[ni][2], sacc[ni][3],
                         qa[ks][0], qa[ks][1], qa[ks][2], qa[ks][3],
                         __float_as_uint(bp[0]), __float_as_uint(bp[4]));
            }
        }

        float mx0 = -1e30f, mx1 = -1e30f;
        #pragma unroll
        for (int ni = 0; ni < 8; ni++) {
            sacc[ni][0] *= SCALE_F; sacc[ni][1] *= SCALE_F;
            sacc[ni][2] *= SCALE_F; sacc[ni][3] *= SCALE_F;
            mx0 = fmaxf(mx0, fmaxf(sacc[ni][0], sacc[ni][1]));
            mx1 = fmaxf(mx1, fmaxf(sacc[ni][2], sacc[ni][3]));
        }
        mx0 = fmaxf(mx0, __shfl_xor_sync(0xffffffffu, mx0, 1));
        mx0 = fmaxf(mx0, __shfl_xor_sync(0xffffffffu, mx0, 2));
        mx1 = fmaxf(mx1, __shfl_xor_sync(0xffffffffu, mx1, 1));
        mx1 = fmaxf(mx1, __shfl_xor_sync(0xffffffffu, mx1, 2));
        const float nm0 = fmaxf(m0, mx0), nm1 = fmaxf(m1, mx1);
        const float sc0 = exp2f((m0 - nm0) * LOG2E_F);
        const float sc1 = exp2f((m1 - nm1) * LOG2E_F);
        m0 = nm0; m1 = nm1;
        float rs0 = 0.f, rs1 = 0.f;
        #pragma unroll
        for (int ni = 0; ni < 8; ni++) {
            float p0 = exp2f((sacc[ni][0] - nm0) * LOG2E_F);
            float p1 = exp2f((sacc[ni][1] - nm0) * LOG2E_F);
            float p2 = exp2f((sacc[ni][2] - nm1) * LOG2E_F);
            float p3 = exp2f((sacc[ni][3] - nm1) * LOG2E_F);
            rs0 += p0 + p1; rs1 += p2 + p3;
            Pw[g*PS_STRIDE + ni*8 + 2*t4]       = rna_tf32(p0);
            Pw[g*PS_STRIDE + ni*8 + 2*t4 + 1]   = rna_tf32(p1);
            Pw[(g+8)*PS_STRIDE + ni*8 + 2*t4]   = rna_tf32(p2);
            Pw[(g+8)*PS_STRIDE + ni*8 + 2*t4+1] = rna_tf32(p3);
        }
        rs0 += __shfl_xor_sync(0xffffffffu, rs0, 1);
        rs0 += __shfl_xor_sync(0xffffffffu, rs0, 2);
        rs1 += __shfl_xor_sync(0xffffffffu, rs1, 1);
        rs1 += __shfl_xor_sync(0xffffffffu, rs1, 2);
        l0 = l0 * sc0 + rs0;
        l1 = l1 * sc1 + rs1;
        #pragma unroll
        for (int ni = 0; ni < 16; ni++) {
            oacc[ni][0] *= sc0; oacc[ni][1] *= sc0;
            oacc[ni][2] *= sc1; oacc[ni][3] *= sc1;
        }
        __syncwarp();

        #pragma unroll
        for (int ks = 0; ks < 8; ks++) {
            uint32_t pa0 = __float_as_uint(Pw[g*PS_STRIDE + ks*8 + t4]);
            uint32_t pa1 = __float_as_uint(Pw[(g+8)*PS_STRIDE + ks*8 + t4]);
            uint32_t pa2 = __float_as_uint(Pw[g*PS_STRIDE + ks*8 + t4 + 4]);
            uint32_t pa3 = __float_as_uint(Pw[(g+8)*PS_STRIDE + ks*8 + t4 + 4]);
            #pragma unroll
            for (int ni = 0; ni < 16; ni++) {
                const float* vp = Vs + (ni*8+g)*VS_STRIDE + ks*8 + t4;
                mma_tf32(oacc[ni][0], oacc[ni][1], oacc[ni][2], oacc[ni][3],
                         pa0, pa1, pa2, pa3,
                         __float_as_uint(vp[0]), __float_as_uint(vp[4]));
            }
        }
        __syncthreads();
    }

    const float inv0 = 1.f / l0, inv1 = 1.f / l1;
    const size_t rowA = (size_t)b*SEQ + qb + warp*16 + g;
    const size_t rowB = rowA + 8;
    #pragma unroll
    for (int ni = 0; ni < 16; ni++) {
        const int c0 = ni*8 + 2*t4;
        float2 v0, v1;
        v0.x = oacc[ni][0]*inv0; v0.y = oacc[ni][1]*inv0;
        v1.x = oacc[ni][2]*inv1; v1.y = oacc[ni][3]*inv1;
        *reinterpret_cast<float2*>(outc + rowA*DHEAD + c0) = v0;
        *reinterpret_cast<float2*>(outc + rowB*DHEAD + c0) = v1;
        float2 r0, r1;
        r0.x = rna_tf32(v0.x); r0.y = rna_tf32(v0.y);
        r1.x = rna_tf32(v1.x); r1.y = rna_tf32(v1.y);
        *reinterpret_cast<float2*>(outR + rowA*DHEAD + c0) = r0;
        *reinterpret_cast<float2*>(outR + rowB*DHEAD + c0) = r1;
    }
}

// ---------------- small prep kernels -----------------------------------------
__global__ void round_arr(const float* __restrict__ in, float* __restrict__ out, int n4)
{
    int i = blockIdx.x * blockDim.x + threadIdx.x;
    if (i < n4) {
        float4 v = reinterpret_cast<const float4*>(in)[i];
        v.x = rna_tf32(v.x); v.y = rna_tf32(v.y); v.z = rna_tf32(v.z); v.w = rna_tf32(v.w);
        reinterpret_cast<float4*>(out)[i] = v;
    }
}

__global__ void transpose_v(const float* __restrict__ v, float* __restrict__ vt)
{
    __shared__ float t[32][33];
    int b = blockIdx.z;
    int s0 = blockIdx.x * 32, d0 = blockIdx.y * 32;
    int x = threadIdx.x, y = threadIdx.y;
    #pragma unroll
    for (int j = y; j < 32; j += 8)
        t[j][x] = v[((size_t)b*SEQ + s0 + j) * DHEAD + d0 + x];
    __syncthreads();
    #pragma unroll
    for (int j = y; j < 32; j += 8)
        vt[((size_t)b*DHEAD + d0 + j) * SEQ + s0 + x] = t[x][j];
}

__global__ void prep_wd(const float* __restrict__ w1, float* __restrict__ wd,
                        float* __restrict__ w1c)
{
    int idx = blockIdx.x * blockDim.x + threadIdx.x;
    int j = idx >> 7, i = idx & 127;
    wd[idx]  = rna_tf32(w1[j*384 + i] - w1[j*384 + 128 + i]);
    w1c[idx] = rna_tf32(w1[j*384 + 256 + i]);
}

__global__ void prep_cvec(const float* __restrict__ w1, const float* __restrict__ tb,
                          const float* __restrict__ ab, float* __restrict__ cvec)
{
    int j = threadIdx.x;
    float s = 0.f;
    for (int i = 0; i < 128; i++)
        s += tb[i]*w1[j*384 + i] + ab[i]*w1[j*384 + 128 + i];
    cvec[j] = s;
}

__global__ void init_kernel(int* __restrict__ active, int* __restrict__ flag)
{
    int idx = blockIdx.x * blockDim.x + threadIdx.x;
    if (idx < MTOK) active[idx] = 1;
    if (idx < NROUNDS) flag[idx] = (idx == 0) ? 1 : 0;
}

// ---------------- launch ------------------------------------------------------
extern "C" void kernel_launch(void* const* d_in, const int* in_sizes, int n_in,
                              void* d_out, int out_size)
{
    (void)in_sizes; (void)n_in; (void)out_size;
    const float* x  = (const float*)d_in[0];
    const float* wq = (const float*)d_in[1];
    const float* wk = (const float*)d_in[2];
    const float* wv = (const float*)d_in[3];
    const float* tw = (const float*)d_in[4];
    const float* tb = (const float*)d_in[5];
    const float* ab = (const float*)d_in[6];
    const float* w1 = (const float*)d_in[7];
    const float* b1 = (const float*)d_in[8];
    const float* w2 = (const float*)d_in[9];
    const float* b2 = (const float*)d_in[10];
    const float* gw = (const float*)d_in[11];
    const float* gb = (const float*)d_in[12];
    float* cur = (float*)d_out;

    float *xr,*qkv,*vt,*curR,*zfix,*wqkvr,*twr,*w2r,*wdr,*w1cr,*cvec;
    int *active,*flag;
    cudaGetSymbolAddress((void**)&xr,     g_xr);
    cudaGetSymbolAddress((void**)&qkv,    g_qkv);
    cudaGetSymbolAddress((void**)&vt,     g_vt);
    cudaGetSymbolAddress((void**)&curR,   g_curR);
    cudaGetSymbolAddress((void**)&zfix,   g_zfix);
    cudaGetSymbolAddress((void**)&wqkvr,  g_wqkvr);
    cudaGetSymbolAddress((void**)&twr,    g_twr);
    cudaGetSymbolAddress((void**)&w2r,    g_w2r);
    cudaGetSymbolAddress((void**)&wdr,    g_wdr);
    cudaGetSymbolAddress((void**)&w1cr,   g_w1cr);
    cudaGetSymbolAddress((void**)&cvec,   g_cvec);
    cudaGetSymbolAddress((void**)&active, g_active);
    cudaGetSymbolAddress((void**)&flag,   g_flag);

    cudaFuncSetAttribute(gemm_mma,    cudaFuncAttributeMaxDynamicSharedMemorySize, SMEM_GEMM_BYTES);
    cudaFuncSetAttribute(flash_attn,  cudaFuncAttributeMaxDynamicSharedMemorySize, FL_SMEM_BYTES);
    cudaFuncSetAttribute(zfix_fused,  cudaFuncAttributeMaxDynamicSharedMemorySize, FUSED_SMEM_BYTES);
    cudaFuncSetAttribute(round_fused, cudaFuncAttributeMaxDynamicSharedMemorySize, FUSED_SMEM_BYTES);

    const int WN = DHEAD*DMODEL;   // 131072

    // ---- prep -------------------------------------------------------------
    round_arr<<<(MTOK*DMODEL/4 + 255)/256, 256>>>(x,  xr, MTOK*DMODEL/4);
    round_arr<<<(WN/4 + 255)/256, 256>>>(wq, wqkvr,        WN/4);
    round_arr<<<(WN/4 + 255)/256, 256>>>(wk, wqkvr + WN,   WN/4);
    round_arr<<<(WN/4 + 255)/256, 256>>>(wv, wqkvr + 2*WN, WN/4);
    round_arr<<<(DHEAD*DHEAD/4 + 255)/256, 256>>>(tw, twr, DHEAD*DHEAD/4);
    round_arr<<<(DHEAD*DHEAD/4 + 255)/256, 256>>>(w2, w2r, DHEAD*DHEAD/4);
    prep_wd<<<DHEAD*DHEAD/256, 256>>>(w1, wdr, w1cr);
    prep_cvec<<<1,128>>>(w1, tb, ab, cvec);
    init_kernel<<<64,256>>>(active, flag);

    // ---- q/k/v in one launch (grid.z selects weight + output slice) --------
    gemm_mma<<<dim3(MTOK/128,1,3), 256, SMEM_GEMM_BYTES>>>(
        xr, DMODEL, 0, wqkvr, DMODEL, (size_t)WN,
        qkv, DHEAD, (size_t)MTOK*DHEAD, DMODEL, 1.f, 1);

    transpose_v<<<dim3(SEQ/32, DHEAD/32, BATCH), dim3(32,8)>>>(qkv + 2*(size_t)MTOK*DHEAD, vt);

    // ---- fused attention ----------------------------------------------------
    flash_attn<<<dim3(SEQ/128, BATCH), 256, FL_SMEM_BYTES>>>(
        qkv, qkv + (size_t)MTOK*DHEAD, vt, cur, curR);

    // ---- fused zfix precompute ----------------------------------------------
    zfix_fused<<<MTOK/128, 256, FUSED_SMEM_BYTES>>>(curR, twr, wdr, zfix);

    // ---- fully fused dialectical rounds --------------------------------------
    for (int r = 0; r < NROUNDS; r++)
        round_fused<<<MTOK/128, 256, FUSED_SMEM_BYTES>>>(
            cur, curR, zfix, w1cr, w2r, cvec, b1, b2, gw, gb, active, flag, r);
}

// round 7
// speedup vs baseline: 4.6022x; 1.1241x over previous
#include <cuda_runtime.h>
#include <math.h>
#include <stdint.h>

#define BATCH   8
#define SEQ     2048
#define DMODEL  1024
#define DHEAD   128
#define MTOK    (BATCH*SEQ)          // 16384
#define NROUNDS 3
#define SCALE_F 0.08838834764831843f // 1/sqrt(128)
#define LOG2E_F 1.4426950408889634f
#define SLG_F   (SCALE_F*LOG2E_F)

// ---------------- device scratch (no runtime allocation allowed) -------------
__device__ __align__(256) float g_qkv[3*MTOK*DHEAD];          // q,k,v contiguous
__device__ __align__(256) float g_curR[MTOK*DHEAD];           // rounded copy of cur
__device__ __align__(256) float g_zfix[MTOK*DHEAD];
__device__ __align__(256) float g_wqkvr[3*DHEAD*DMODEL];
__device__ __align__(256) float g_twr[DHEAD*DHEAD];
__device__ __align__(256) float g_w2r[DHEAD*DHEAD];
__device__ __align__(256) float g_wdr[DHEAD*DHEAD];
__device__ __align__(256) float g_w1cr[DHEAD*DHEAD];
__device__ float g_cvec[DHEAD];
__device__ int   g_active[MTOK];
__device__ int   g_flag[NROUNDS];

// ---------------- PTX helpers -------------------------------------------------
__device__ __forceinline__ uint32_t s2u(const void* p) {
    uint32_t a;
    asm("{ .reg .u64 t; cvta.to.shared.u64 t, %1; cvt.u32.u64 %0, t; }" : "=r"(a) : "l"(p));
    return a;
}
__device__ __forceinline__ float rna_tf32(float f) {
    float o;
    asm("cvt.rna.tf32.f32 %0, %1;" : "=f"(o) : "f"(f));
    return o;
}
__device__ __forceinline__ void cp_async16(uint32_t dst, const void* src) {
    asm volatile("cp.async.cg.shared.global [%0], [%1], 16;" :: "r"(dst), "l"(src) : "memory");
}
#define CP_COMMIT() asm volatile("cp.async.commit_group;" ::: "memory")
#define CP_WAIT(N)  asm volatile("cp.async.wait_group %0;" :: "n"(N) : "memory")

__device__ __forceinline__ void mma_tf32(
    float& c0, float& c1, float& c2, float& c3,
    uint32_t a0, uint32_t a1, uint32_t a2, uint32_t a3,
    uint32_t b0, uint32_t b1)
{
    asm volatile(
        "mma.sync.aligned.m16n8k8.row.col.f32.tf32.tf32.f32 "
        "{%0,%1,%2,%3}, {%4,%5,%6,%7}, {%8,%9}, {%0,%1,%2,%3};"
        : "+f"(c0), "+f"(c1), "+f"(c2), "+f"(c3)
        : "r"(a0), "r"(a1), "r"(a2), "r"(a3), "r"(b0), "r"(b1));
}

// ---------------- QKV GEMM: out[z] = rna( x @ W[z]^T ) ------------------------
// A (x) is unrounded: loaded via LDG->rna->STS with register staging.
// B (weights) pre-rounded: cp.async double-buffered.
#define SMS   36
#define STG_F (2*128*SMS)
#define SMEM_GEMM_BYTES (2*STG_F*4)    // 73728

__global__ __launch_bounds__(256) void qkv_gemm(
    const float* __restrict__ X, const float* __restrict__ W,
    float* __restrict__ out)
{
    extern __shared__ float sm[];
    const uint32_t sm_u = s2u(sm);
    const int z = blockIdx.z;
    const float* B = W + (size_t)z*DHEAD*DMODEL;
    float* C = out + (size_t)z*MTOK*DHEAD;
    const int tid = threadIdx.x, lane = tid & 31, warp = tid >> 5;
    const int wm = (warp >> 1) * 32, wn = (warp & 1) * 64;
    const int m0 = blockIdx.x * 128;
    const int lrow = tid >> 3, lc4 = (tid & 7) * 4;
    const int g = lane >> 2, t4 = lane & 3;
    const int nK = DMODEL >> 5;   // 32

    float4 areg[4];
    // prologue: LDG A0 -> regs ; cp.async B0 ; store rounded A0
    {
        const float* Ag = X + (size_t)m0*DMODEL + lc4;
        #pragma unroll
        for (int it = 0; it < 4; it++)
            areg[it] = *reinterpret_cast<const float4*>(Ag + (size_t)(lrow+it*32)*DMODEL);
        const float* Bg = B + lc4;
        uint32_t dB = sm_u + (uint32_t)(128*SMS + lrow*SMS + lc4)*4u;
        #pragma unroll
        for (int it = 0; it < 4; it++)
            cp_async16(dB + it*32u*SMS*4u, Bg + (size_t)(lrow+it*32)*DMODEL);
        CP_COMMIT();
        #pragma unroll
        for (int it = 0; it < 4; it++) {
            float4 v = areg[it];
            v.x = rna_tf32(v.x); v.y = rna_tf32(v.y);
            v.z = rna_tf32(v.z); v.w = rna_tf32(v.w);
            *reinterpret_cast<float4*>(&sm[(lrow+it*32)*SMS + lc4]) = v;
        }
    }

    float acc[2][8][4];
    #pragma unroll
    for (int mi = 0; mi < 2; mi++)
        #pragma unroll
        for (int ni = 0; ni < 8; ni++)
            #pragma unroll
            for (int j = 0; j < 4; j++) acc[mi][ni][j] = 0.f;

    for (int kt = 0; kt < nK; kt++) {
        const int cs = kt & 1;
        if (kt + 1 < nK) {
            const int ko = (kt+1)*32;
            const float* Ag = X + (size_t)m0*DMODEL + ko + lc4;
            #pragma unroll
            for (int it = 0; it < 4; it++)
                areg[it] = *reinterpret_cast<const float4*>(Ag + (size_t)(lrow+it*32)*DMODEL);
            const int ns = cs ^ 1;
            const float* Bg = B + ko + lc4;
            uint32_t dB = sm_u + (uint32_t)(ns*STG_F + 128*SMS + lrow*SMS + lc4)*4u;
            #pragma unroll
            for (int it = 0; it < 4; it++)
                cp_async16(dB + it*32u*SMS*4u, Bg + (size_t)(lrow+it*32)*DMODEL);
            CP_COMMIT();
            CP_WAIT(1);
        } else {
            CP_WAIT(0);
        }
        __syncthreads();

        const float* Asf = sm + cs*STG_F;
        const float* Bsf = Asf + 128*SMS;
        #pragma unroll
        for (int kk = 0; kk < 4; kk++) {
            const int k8 = kk*8;
            uint32_t a[2][4];
            #pragma unroll
            for (int mi = 0; mi < 2; mi++) {
                const float* ap = Asf + (wm + mi*16 + g)*SMS + k8 + t4;
                a[mi][0] = __float_as_uint(ap[0]);
                a[mi][1] = __float_as_uint(ap[8*SMS]);
                a[mi][2] = __float_as_uint(ap[4]);
                a[mi][3] = __float_as_uint(ap[8*SMS + 4]);
            }
            #pragma unroll
            for (int ni = 0; ni < 8; ni++) {
                const float* bp = Bsf + (wn + ni*8 + g)*SMS + k8 + t4;
                uint32_t b0 = __float_as_uint(bp[0]);
                uint32_t b1 = __float_as_uint(bp[4]);
                #pragma unroll
                for (int mi = 0; mi < 2; mi++)
                    mma_tf32(acc[mi][ni][0], acc[mi][ni][1], acc[mi][ni][2], acc[mi][ni][3],
                             a[mi][0], a[mi][1], a[mi][2], a[mi][3], b0, b1);
            }
        }
        if (kt + 1 < nK) {
            const int ns = cs ^ 1;
            float* Ad = sm + ns*STG_F;
            #pragma unroll
            for (int it = 0; it < 4; it++) {
                float4 v = areg[it];
                v.x = rna_tf32(v.x); v.y = rna_tf32(v.y);
                v.z = rna_tf32(v.z); v.w = rna_tf32(v.w);
                *reinterpret_cast<float4*>(&Ad[(lrow+it*32)*SMS + lc4]) = v;
            }
        }
        __syncthreads();
    }

    #pragma unroll
    for (int mi = 0; mi < 2; mi++) {
        const int rA = m0 + wm + mi*16 + g, rB = rA + 8;
        #pragma unroll
        for (int ni = 0; ni < 8; ni++) {
            const int c0 = wn + ni*8 + 2*t4;
            float2 v0, v1;
            v0.x = rna_tf32(acc[mi][ni][0]); v0.y = rna_tf32(acc[mi][ni][1]);
            v1.x = rna_tf32(acc[mi][ni][2]); v1.y = rna_tf32(acc[mi][ni][3]);
            *reinterpret_cast<float2*>(C + (size_t)rA*DHEAD + c0) = v0;
            *reinterpret_cast<float2*>(C + (size_t)rB*DHEAD + c0) = v1;
        }
    }
}

// ---------------- fused double-GEMM kernels (K = 128, smem-resident) ----------
#define RSMS 132
#define F_T0 0
#define F_T1 (128*RSMS)
#define F_T2 (2*128*RSMS)
#define F_RED (3*128*RSMS)
#define FUSED_SMEM_BYTES ((3*128*RSMS + 128*4)*4)   // 204800

__device__ __forceinline__ void load_tile128(uint32_t sdst, const float* __restrict__ src,
                                             int lrow, int lc4)
{
    #pragma unroll
    for (int kt = 0; kt < 4; kt++)
        #pragma unroll
        for (int it = 0; it < 4; it++)
            cp_async16(sdst + (uint32_t)((lrow + it*32)*RSMS + kt*32 + lc4)*4u,
                       src + (size_t)(lrow + it*32)*128 + kt*32 + lc4);
}

__device__ __forceinline__ void mma_128x128(const float* __restrict__ As,
                                            const float* __restrict__ Bs,
                                            float acc[2][8][4],
                                            int wm, int wn, int g, int t4)
{
    #pragma unroll
    for (int k8 = 0; k8 < 16; k8++) {
        const int ko = k8*8 + t4;
        uint32_t a[2][4];
        #pragma unroll
        for (int mi = 0; mi < 2; mi++) {
            const float* ap = As + (wm + mi*16 + g)*RSMS + ko;
            a[mi][0] = __float_as_uint(ap[0]);
            a[mi][1] = __float_as_uint(ap[8*RSMS]);
            a[mi][2] = __float_as_uint(ap[4]);
            a[mi][3] = __float_as_uint(ap[8*RSMS + 4]);
        }
        #pragma unroll
        for (int ni = 0; ni < 8; ni++) {
            const float* bp = Bs + (wn + ni*8 + g)*RSMS + ko;
            uint32_t b0 = __float_as_uint(bp[0]);
            uint32_t b1r = __float_as_uint(bp[4]);
            #pragma unroll
            for (int mi = 0; mi < 2; mi++)
                mma_tf32(acc[mi][ni][0], acc[mi][ni][1], acc[mi][ni][2], acc[mi][ni][3],
                         a[mi][0], a[mi][1], a[mi][2], a[mi][3], b0, b1r);
        }
    }
}

// zfix = (curR @ tw^T rounded) @ wd^T
__global__ __launch_bounds__(256) void zfix_fused(
    const float* __restrict__ curR, const float* __restrict__ tw,
    const float* __restrict__ wd, float* __restrict__ zfix)
{
    extern __shared__ float sm[];
    const uint32_t sm_u = s2u(sm);
    const int tid = threadIdx.x, lane = tid & 31, warp = tid >> 5;
    const int wm = (warp >> 1) * 32, wn = (warp & 1) * 64;
    const int g = lane >> 2, t4 = lane & 3;
    const int m0 = blockIdx.x * 128;
    const int lrow = tid >> 3, lc4 = (tid & 7) * 4;

    load_tile128(sm_u + F_T0*4, curR + (size_t)m0*128, lrow, lc4);
    load_tile128(sm_u + F_T1*4, tw, lrow, lc4);
    load_tile128(sm_u + F_T2*4, wd, lrow, lc4);
    CP_COMMIT(); CP_WAIT(0);
    __syncthreads();

    float acc[2][8][4];
    #pragma unroll
    for (int mi = 0; mi < 2; mi++)
        #pragma unroll
        for (int ni = 0; ni < 8; ni++)
            #pragma unroll
            for (int j = 0; j < 4; j++) acc[mi][ni][j] = 0.f;

    mma_128x128(sm + F_T0, sm + F_T1, acc, wm, wn, g, t4);
    __syncthreads();

    float* Ps = sm + F_T0;
    #pragma unroll
    for (int mi = 0; mi < 2; mi++) {
        const int rA = wm + mi*16 + g, rB = rA + 8;
        #pragma unroll
        for (int ni = 0; ni < 8; ni++) {
            const int c0 = wn + ni*8 + 2*t4;
            float2 p0, p1;
            p0.x = rna_tf32(acc[mi][ni][0]); p0.y = rna_tf32(acc[mi][ni][1]);
            p1.x = rna_tf32(acc[mi][ni][2]); p1.y = rna_tf32(acc[mi][ni][3]);
            *reinterpret_cast<float2*>(&Ps[rA*RSMS + c0]) = p0;
            *reinterpret_cast<float2*>(&Ps[rB*RSMS + c0]) = p1;
        }
    }
    __syncthreads();

    #pragma unroll
    for (int mi = 0; mi < 2; mi++)
        #pragma unroll
        for (int ni = 0; ni < 8; ni++)
            #pragma unroll
            for (int j = 0; j < 4; j++) acc[mi][ni][j] = 0.f;

    mma_128x128(sm + F_T0, sm + F_T2, acc, wm, wn, g, t4);

    #pragma unroll
    for (int mi = 0; mi < 2; mi++) {
        const int rA = m0 + wm + mi*16 + g, rB = rA + 8;
        #pragma unroll
        for (int ni = 0; ni < 8; ni++) {
            const int c0 = wn + ni*8 + 2*t4;
            float2 v0, v1;
            v0.x = acc[mi][ni][0]; v0.y = acc[mi][ni][1];
            v1.x = acc[mi][ni][2]; v1.y = acc[mi][ni][3];
            *reinterpret_cast<float2*>(zfix + (size_t)rA*128 + c0) = v0;
            *reinterpret_cast<float2*>(zfix + (size_t)rB*128 + c0) = v1;
        }
    }
}

// One full dialectical round (validated in R6)
__global__ __launch_bounds__(256) void round_fused(
    float* __restrict__ cur, float* __restrict__ curR,
    const float* __restrict__ zfix,
    const float* __restrict__ w1c, const float* __restrict__ w2,
    const float* __restrict__ cvec, const float* __restrict__ b1,
    const float* __restrict__ b2, const float* __restrict__ gw,
    const float* __restrict__ gb, int* __restrict__ active,
    int* __restrict__ flag, int r)
{
    extern __shared__ float sm[];
    const uint32_t sm_u = s2u(sm);
    __shared__ int s_any;
    const int tid = threadIdx.x, lane = tid & 31, warp = tid >> 5;
    const int wm = (warp >> 1) * 32, wn = (warp & 1) * 64;
    const int g = lane >> 2, t4 = lane & 3;
    const int m0 = blockIdx.x * 128;
    const int lrow = tid >> 3, lc4 = (tid & 7) * 4;
    if (tid == 0) s_any = 0;

    load_tile128(sm_u + F_T0*4, curR + (size_t)m0*128, lrow, lc4);
    load_tile128(sm_u + F_T1*4, w1c, lrow, lc4);
    load_tile128(sm_u + F_T2*4, w2, lrow, lc4);
    CP_COMMIT(); CP_WAIT(0);
    __syncthreads();

    float acc[2][8][4];
    #pragma unroll
    for (int mi = 0; mi < 2; mi++)
        #pragma unroll
        for (int ni = 0; ni < 8; ni++)
            #pragma unroll
            for (int j = 0; j < 4; j++) acc[mi][ni][j] = 0.f;

    mma_128x128(sm + F_T0, sm + F_T1, acc, wm, wn, g, t4);
    __syncthreads();

    float amr[4];
    {
        float* Hs = sm + F_T0;
        #pragma unroll
        for (int mi = 0; mi < 2; mi++) {
            const int rA = wm + mi*16 + g, rB = rA + 8;
            const float amA = active[m0 + rA] ? 1.f : 0.f;
            const float amB = active[m0 + rB] ? 1.f : 0.f;
            amr[mi*2] = amA; amr[mi*2+1] = amB;
            #pragma unroll
            for (int ni = 0; ni < 8; ni++) {
                const int c0 = wn + ni*8 + 2*t4;
                float2 zA = *reinterpret_cast<const float2*>(zfix + (size_t)(m0+rA)*128 + c0);
                float2 zB = *reinterpret_cast<const float2*>(zfix + (size_t)(m0+rB)*128 + c0);
                float2 cc = *reinterpret_cast<const float2*>(cvec + c0);
                float2 bb = *reinterpret_cast<const float2*>(b1 + c0);
                float2 h0, h1;
                h0.x = rna_tf32(fmaxf(fmaf(amA, acc[mi][ni][0] + zA.x + cc.x, bb.x), 0.f));
                h0.y = rna_tf32(fmaxf(fmaf(amA, acc[mi][ni][1] + zA.y + cc.y, bb.y), 0.f));
                h1.x = rna_tf32(fmaxf(fmaf(amB, acc[mi][ni][2] + zB.x + cc.x, bb.x), 0.f));
                h1.y = rna_tf32(fmaxf(fmaf(amB, acc[mi][ni][3] + zB.y + cc.y, bb.y), 0.f));
                *reinterpret_cast<float2*>(&Hs[rA*RSMS + c0]) = h0;
                *reinterpret_cast<float2*>(&Hs[rB*RSMS + c0]) = h1;
            }
        }
    }
    __syncthreads();

    #pragma unroll
    for (int mi = 0; mi < 2; mi++)
        #pragma unroll
        for (int ni = 0; ni < 8; ni++)
            #pragma unroll
            for (int j = 0; j < 4; j++) acc[mi][ni][j] = 0.f;

    mma_128x128(sm + F_T0, sm + F_T2, acc, wm, wn, g, t4);

    const int flg = flag[r];
    float d1[4] = {0,0,0,0}, nn[4] = {0,0,0,0};
    #pragma unroll
    for (int mi = 0; mi < 2; mi++) {
        const int rA = wm + mi*16 + g, rB = rA + 8;
        const float amA = amr[mi*2], amB = amr[mi*2+1];
        #pragma unroll
        for (int ni = 0; ni < 8; ni++) {
            const int c0 = wn + ni*8 + 2*t4;
            float2 cA = *reinterpret_cast<const float2*>(cur + (size_t)(m0+rA)*128 + c0);
            float2 cB = *reinterpret_cast<const float2*>(cur + (size_t)(m0+rB)*128 + c0);
            float2 bb = *reinterpret_cast<const float2*>(b2 + c0);
            float2 g1 = *reinterpret_cast<const float2*>(gw + c0);
            float2 g2 = *reinterpret_cast<const float2*>(gw + 128 + c0);
            float syA0 = acc[mi][ni][0] + bb.x, syA1 = acc[mi][ni][1] + bb.y;
            float syB0 = acc[mi][ni][2] + bb.x, syB1 = acc[mi][ni][3] + bb.y;
            float acA0 = cA.x * amA, acA1 = cA.y * amA;
            float acB0 = cB.x * amB, acB1 = cB.y * amB;
            d1[mi*2]   += acA0*g1.x + syA0*g2.x + acA1*g1.y + syA1*g2.y;
            d1[mi*2+1] += acB0*g1.x + syB0*g2.x + acB1*g1.y + syB1*g2.y;
            float dA0 = syA0-acA0, dA1 = syA1-acA1;
            float dB0 = syB0-acB0, dB1 = syB1-acB1;
            nn[mi*2]   += dA0*dA0 + dA1*dA1;
            nn[mi*2+1] += dB0*dB0 + dB1*dB1;
        }
    }
    #pragma unroll
    for (int j = 0; j < 4; j++) {
        d1[j] += __shfl_xor_sync(0xffffffffu, d1[j], 1);
        d1[j] += __shfl_xor_sync(0xffffffffu, d1[j], 2);
        nn[j] += __shfl_xor_sync(0xffffffffu, nn[j], 1);
        nn[j] += __shfl_xor_sync(0xffffffffu, nn[j], 2);
    }
    float* red = sm + F_RED;
    if (t4 == 0) {
        const int hf = (warp & 1) * 2;
        #pragma unroll
        for (int mi = 0; mi < 2; mi++) {
            const int rA = wm + mi*16 + g, rB = rA + 8;
            red[rA*4 + hf]     = d1[mi*2];
            red[rA*4 + hf + 1] = nn[mi*2];
            red[rB*4 + hf]     = d1[mi*2+1];
            red[rB*4 + hf + 1] = nn[mi*2+1];
        }
    }
    __syncthreads();

    const float gbv = gb[0];
    #pragma unroll
    for (int mi = 0; mi < 2; mi++) {
        const int rA = wm + mi*16 + g, rB = rA + 8;
        const float amA = amr[mi*2], amB = amr[mi*2+1];
        float gdA = red[rA*4+0] + red[rA*4+2] + gbv;
        float gdB = red[rB*4+0] + red[rB*4+2] + gbv;
        float n2A = red[rA*4+1] + red[rA*4+3];
        float n2B = red[rB*4+1] + red[rB*4+3];
        float gateA = 1.f / (1.f + expf(-gdA));
        float gateB = 1.f / (1.f + expf(-gdB));
        int stableA = (gateA * 0.1f * sqrtf(n2A)) < 0.1f;
        int stableB = (gateB * 0.1f * sqrtf(n2B)) < 0.1f;
        #pragma unroll
        for (int ni = 0; ni < 8; ni++) {
            const int c0 = wn + ni*8 + 2*t4;
            float2 cA = *reinterpret_cast<const float2*>(cur + (size_t)(m0+rA)*128 + c0);
            float2 cB = *reinterpret_cast<const float2*>(cur + (size_t)(m0+rB)*128 + c0);
            float2 bb = *reinterpret_cast<const float2*>(b2 + c0);
            float syA0 = acc[mi][ni][0] + bb.x, syA1 = acc[mi][ni][1] + bb.y;
            float syB0 = acc[mi][ni][2] + bb.x, syB1 = acc[mi][ni][3] + bb.y;
            float2 o0, o1;
            o0.x = cA.x; o0.y = cA.y; o1.x = cB.x; o1.y = cB.y;
            if (flg) {
                o0.x += gateA * (syA0 - cA.x*amA) * 0.1f;
                o0.y += gateA * (syA1 - cA.y*amA) * 0.1f;
                o1.x += gateB * (syB0 - cB.x*amB) * 0.1f;
                o1.y += gateB * (syB1 - cB.y*amB) * 0.1f;
            }
            *reinterpret_cast<float2*>(cur + (size_t)(m0+rA)*128 + c0) = o0;
            *reinterpret_cast<float2*>(cur + (size_t)(m0+rB)*128 + c0) = o1;
            float2 r0, r1;
            r0.x = rna_tf32(o0.x); r0.y = rna_tf32(o0.y);
            r1.x = rna_tf32(o1.x); r1.y = rna_tf32(o1.y);
            *reinterpret_cast<float2*>(curR + (size_t)(m0+rA)*128 + c0) = r0;
            *reinterpret_cast<float2*>(curR + (size_t)(m0+rB)*128 + c0) = r1;
        }
        if ((warp & 1) == 0 && t4 == 0) {
            int actA = amA > 0.f, actB = amB > 0.f;
            int naA = actA && !stableA;
            int naB = actB && !stableB;
            if (flg) { active[m0+rA] = naA; active[m0+rB] = naB; }
            int effA = flg ? naA : actA;
            int effB = flg ? naB : actB;
            if (effA | effB) s_any = 1;
        }
    }
    __syncthreads();
    if (tid == 0 && (r + 1) < NROUNDS && s_any) atomicOr(&flag[r+1], 1);
}

// ---------------- fused flash attention (no-max softmax, natural V) -----------
#define KVT 64
#define KS_STRIDE 132
#define VSN 136
#define PS_STRIDE 68
#define FL_K_OFF 0
#define FL_V_OFF (2*64*KS_STRIDE)                   // 16896 floats
#define FL_P_OFF (FL_V_OFF + 2*64*VSN)              // 34304 floats
#define FL_SMEM_FLOATS (FL_P_OFF + 8*16*PS_STRIDE)  // 43008 floats
#define FL_SMEM_BYTES (FL_SMEM_FLOATS*4)            // 172032 B

__global__ __launch_bounds__(256) void flash_attn(
    const float* __restrict__ q, const float* __restrict__ k,
    const float* __restrict__ v, float* __restrict__ outc,
    float* __restrict__ outR)
{
    extern __shared__ float sm[];
    const uint32_t sm_u = s2u(sm);
    const int b   = blockIdx.y;
    const int qb  = blockIdx.x * 128;
    const int tid = threadIdx.x, lane = tid & 31, warp = tid >> 5;
    const int g   = lane >> 2, t4 = lane & 3;

    const float* qB = q + ((size_t)b*SEQ + qb)*DHEAD;
    const float* kB = k + (size_t)b*SEQ*DHEAD;
    const float* vB = v + (size_t)b*SEQ*DHEAD;

    const int kc = tid >> 5;          // 0..7 (+8/iter, 8 iters)
    const int kf = (tid & 31) * 4;

    uint32_t qa[16][4];
    {
        const float* q0 = qB + (size_t)(warp*16 + g)*DHEAD;
        const float* q8 = q0 + 8*DHEAD;
        #pragma unroll
        for (int ks = 0; ks < 16; ks++) {
            qa[ks][0] = __float_as_uint(q0[8*ks + t4]);
            qa[ks][1] = __float_as_uint(q8[8*ks + t4]);
            qa[ks][2] = __float_as_uint(q0[8*ks + t4 + 4]);
            qa[ks][3] = __float_as_uint(q8[8*ks + t4 + 4]);
        }
    }

    float oacc[16][4];
    #pragma unroll
    for (int ni = 0; ni < 16; ni++)
        #pragma unroll
        for (int j = 0; j < 4; j++) oacc[ni][j] = 0.f;
    float l0 = 0.f, l1 = 0.f;

    // prefetch tile 0 (K and V identical natural layout, 64x128)
    {
        #pragma unroll
        for (int it = 0; it < 8; it++) {
            cp_async16(sm_u + (uint32_t)(FL_K_OFF + (kc + it*8)*KS_STRIDE + kf)*4u,
                       kB + (size_t)(kc + it*8)*DHEAD + kf);
            cp_async16(sm_u + (uint32_t)(FL_V_OFF + (kc + it*8)*VSN + kf)*4u,
                       vB + (size_t)(kc + it*8)*DHEAD + kf);
        }
        CP_COMMIT();
    }

    const int nTiles = SEQ / KVT;  // 32
    for (int t = 0; t < nTiles; t++) {
        const int cs = t & 1;
        if (t + 1 < nTiles) {
            const int ns = cs ^ 1;
            const int kv1 = (t+1) * KVT;
            #pragma unroll
            for (int it = 0; it < 8; it++) {
                cp_async16(sm_u + (uint32_t)(FL_K_OFF + ns*64*KS_STRIDE + (kc + it*8)*KS_STRIDE + kf)*4u,
                           kB + (size_t)(kv1 + kc + it*8)*DHEAD + kf);
                cp_async16(sm_u + (uint32_t)(FL_V_OFF + ns*64*VSN + (kc + it*8)*VSN + kf)*4u,
                           vB + (size_t)(kv1 + kc + it*8)*DHEAD + kf);
            }
            CP_COMMIT();
            CP_WAIT(1);
        } else {
            CP_WAIT(0);
        }
        __syncthreads();

        const float* Ks = sm + FL_K_OFF + cs*64*KS_STRIDE;
        const float* Vs = sm + FL_V_OFF + cs*64*VSN;
        float* Pw = sm + FL_P_OFF + warp*16*PS_STRIDE;

        // S = Q @ K^T (16 x 64 per warp)
        float sacc[8][4];
        #pragma unroll
        for (int ni = 0; ni < 8; ni++)
            #pragma unroll
            for (int j = 0; j < 4; j++) sacc[ni][j] = 0.f;
        #pragma unroll
        for (int ks = 0; ks < 16; ks++) {
            #pragma unroll
            for (int ni = 0; ni < 8; ni++) {
                const float* bp = Ks + (ni*8+g)*KS_STRIDE + ks*8 + t4;
                mma_tf32(sacc[ni][0], sacc[ni][1], sacc[ni][2], sacc[ni][3],
                         qa[ks][0], qa[ks][1], qa[ks][2], qa[ks][3],
                         __float_as_uint(bp[0]), __float_as_uint(bp[4]));
            }
        }

        // fixed-base softmax accumulation (scores bounded; no max tracking)
        float rs0 = 0.f, rs1 = 0.f;
        #pragma unroll
        for (int ni = 0; ni < 8; ni++) {
            float p0 = exp2f(sacc[ni][0] * SLG_F);
            float p1 = exp2f(sacc[ni][1] * SLG_F);
            float p2 = exp2f(sacc[ni][2] * SLG_F);
            float p3 = exp2f(sacc[ni][3] * SLG_F);
            rs0 += p0 + p1; rs1 += p2 + p3;
            Pw[g*PS_STRIDE + ni*8 + 2*t4]       = rna_tf32(p0);
            Pw[g*PS_STRIDE + ni*8 + 2*t4 + 1]   = rna_tf32(p1);
            Pw[(g+8)*PS_STRIDE + ni*8 + 2*t4]   = rna_tf32(p2);
            Pw[(g+8)*PS_STRIDE + ni*8 + 2*t4+1] = rna_tf32(p3);
        }
        rs0 += __shfl_xor_sync(0xffffffffu, rs0, 1);
        rs0 += __shfl_xor_sync(0xffffffffu, rs0, 2);
        rs1 += __shfl_xor_sync(0xffffffffu, rs1, 1);
        rs1 += __shfl_xor_sync(0xffffffffu, rs1, 2);
        l0 += rs0;
        l1 += rs1;
        __syncwarp();

        // O += P @ V  (A = P 16x64 from smem; B from natural-layout V tile)
        #pragma unroll
        for (int ks = 0; ks < 8; ks++) {
            uint32_t pa0 = __float_as_uint(Pw[g*PS_STRIDE + ks*8 + t4]);
            uint32_t pa1 = __float_as_uint(Pw[(g+8)*PS_STRIDE + ks*8 + t4]);
            uint32_t pa2 = __float_as_uint(Pw[g*PS_STRIDE + ks*8 + t4 + 4]);
            uint32_t pa3 = __float_as_uint(Pw[(g+8)*PS_STRIDE + ks*8 + t4 + 4]);
            const float* v0p = Vs + (ks*8 + t4)*VSN;
            const float* v1p = Vs + (ks*8 + t4 + 4)*VSN;
            #pragma unroll
            for (int ni = 0; ni < 16; ni++) {
                mma_tf32(oacc[ni][0], oacc[ni][1], oacc[ni][2], oacc[ni][3],
                         pa0, pa1, pa2, pa3,
                         __float_as_uint(v0p[ni*8+g]), __float_as_uint(v1p[ni*8+g]));
            }
        }
        __syncthreads();
    }

    const float inv0 = 1.f / l0, inv1 = 1.f / l1;
    const size_t rowA = (size_t)b*SEQ + qb + warp*16 + g;
    const size_t rowB = rowA + 8;
    #pragma unroll
    for (int ni = 0; ni < 16; ni++) {
        const int c0 = ni*8 + 2*t4;
        float2 v0, v1;
        v0.x = oacc[ni][0]*inv0; v0.y = oacc[ni][1]*inv0;
        v1.x = oacc[ni][2]*inv1; v1.y = oacc[ni][3]*inv1;
        *reinterpret_cast<float2*>(outc + rowA*DHEAD + c0) = v0;
        *reinterpret_cast<float2*>(outc + rowB*DHEAD + c0) = v1;
        float2 r0, r1;
        r0.x = rna_tf32(v0.x); r0.y = rna_tf32(v0.y);
        r1.x = rna_tf32(v1.x); r1.y = rna_tf32(v1.y);
        *reinterpret_cast<float2*>(outR + rowA*DHEAD + c0) = r0;
        *reinterpret_cast<float2*>(outR + rowB*DHEAD + c0) = r1;
    }
}

// ---------------- single prep kernel -------------------------------------------
__global__ void prep_all(
    const float* __restrict__ wq, const float* __restrict__ wk,
    const float* __restrict__ wv, const float* __restrict__ tw,
    const float* __restrict__ w2, const float* __restrict__ w1,
    const float* __restrict__ tb, const float* __restrict__ ab,
    float* __restrict__ wqkvr, float* __restrict__ twr,
    float* __restrict__ w2r, float* __restrict__ wdr,
    float* __restrict__ w1cr, float* __restrict__ cvec,
    int* __restrict__ active, int* __restrict__ flag)
{
    int idx = blockIdx.x * blockDim.x + threadIdx.x;
    const int WN4 = DHEAD*DMODEL/4;     // 32768
    const int T4  = DHEAD*DHEAD/4;      // 4096
    if (idx < 3*WN4) {
        const float* src = (idx < WN4) ? wq : (idx < 2*WN4 ? wk : wv);
        int off = (idx < WN4) ? idx : (idx < 2*WN4 ? idx - WN4 : idx - 2*WN4);
        float4 vv = reinterpret_cast<const float4*>(src)[off];
        vv.x = rna_tf32(vv.x); vv.y = rna_tf32(vv.y);
        vv.z = rna_tf32(vv.z); vv.w = rna_tf32(vv.w);
        reinterpret_cast<float4*>(wqkvr)[idx] = vv;
        return;
    }
    idx -= 3*WN4;
    if (idx < T4) {
        float4 vv = reinterpret_cast<const float4*>(tw)[idx];
        vv.x = rna_tf32(vv.x); vv.y = rna_tf32(vv.y);
        vv.z = rna_tf32(vv.z); vv.w = rna_tf32(vv.w);
        reinterpret_cast<float4*>(twr)[idx] = vv;
        return;
    }
    idx -= T4;
    if (idx < T4) {
        float4 vv = reinterpret_cast<const float4*>(w2)[idx];
        vv.x = rna_tf32(vv.x); vv.y = rna_tf32(vv.y);
        vv.z = rna_tf32(vv.z); vv.w = rna_tf32(vv.w);
        reinterpret_cast<float4*>(w2r)[idx] = vv;
        return;
    }
    idx -= T4;
    if (idx < DHEAD*DHEAD) {
        int j = idx >> 7, i = idx & 127;
        wdr[idx]  = rna_tf32(w1[j*384 + i] - w1[j*384 + 128 + i]);
        w1cr[idx] = rna_tf32(w1[j*384 + 256 + i]);
        return;
    }
    idx -= DHEAD*DHEAD;
    if (idx < MTOK) { active[idx] = 1; return; }
    idx -= MTOK;
    if (idx < NROUNDS) { flag[idx] = (idx == 0) ? 1 : 0; return; }
    idx -= NROUNDS;
    if (idx < DHEAD) {
        float s = 0.f;
        for (int i = 0; i < 128; i++)
            s += tb[i]*w1[idx*384 + i] + ab[i]*w1[idx*384 + 128 + i];
        cvec[idx] = s;
    }
}
#define PREP_ITEMS (3*(DHEAD*DMODEL/4) + 2*(DHEAD*DHEAD/4) + DHEAD*DHEAD + MTOK + NROUNDS + DHEAD)

// ---------------- launch ------------------------------------------------------
extern "C" void kernel_launch(void* const* d_in, const int* in_sizes, int n_in,
                              void* d_out, int out_size)
{
    (void)in_sizes; (void)n_in; (void)out_size;
    const float* x  = (const float*)d_in[0];
    const float* wq = (const float*)d_in[1];
    const float* wk = (const float*)d_in[2];
    const float* wv = (const float*)d_in[3];
    const float* tw = (const float*)d_in[4];
    const float* tb = (const float*)d_in[5];
    const float* ab = (const float*)d_in[6];
    const float* w1 = (const float*)d_in[7];
    const float* b1 = (const float*)d_in[8];
    const float* w2 = (const float*)d_in[9];
    const float* b2 = (const float*)d_in[10];
    const float* gw = (const float*)d_in[11];
    const float* gb = (const float*)d_in[12];
    float* cur = (float*)d_out;

    float *qkv,*curR,*zfix,*wqkvr,*twr,*w2r,*wdr,*w1cr,*cvec;
    int *active,*flag;
    cudaGetSymbolAddress((void**)&qkv,    g_qkv);
    cudaGetSymbolAddress((void**)&curR,   g_curR);
    cudaGetSymbolAddress((void**)&zfix,   g_zfix);
    cudaGetSymbolAddress((void**)&wqkvr,  g_wqkvr);
    cudaGetSymbolAddress((void**)&twr,    g_twr);
    cudaGetSymbolAddress((void**)&w2r,    g_w2r);
    cudaGetSymbolAddress((void**)&wdr,    g_wdr);
    cudaGetSymbolAddress((void**)&w1cr,   g_w1cr);
    cudaGetSymbolAddress((void**)&cvec,   g_cvec);
    cudaGetSymbolAddress((void**)&active, g_active);
    cudaGetSymbolAddress((void**)&flag,   g_flag);

    cudaFuncSetAttribute(qkv_gemm,    cudaFuncAttributeMaxDynamicSharedMemorySize, SMEM_GEMM_BYTES);
    cudaFuncSetAttribute(flash_attn,  cudaFuncAttributeMaxDynamicSharedMemorySize, FL_SMEM_BYTES);
    cudaFuncSetAttribute(zfix_fused,  cudaFuncAttributeMaxDynamicSharedMemorySize, FUSED_SMEM_BYTES);
    cudaFuncSetAttribute(round_fused, cudaFuncAttributeMaxDynamicSharedMemorySize, FUSED_SMEM_BYTES);

    // ---- one prep launch -----------------------------------------------------
    prep_all<<<(PREP_ITEMS + 255)/256, 256>>>(
        wq, wk, wv, tw, w2, w1, tb, ab,
        wqkvr, twr, w2r, wdr, w1cr, cvec, active, flag);

    // ---- q/k/v (x rounded in-kernel) ------------------------------------------
    qkv_gemm<<<dim3(MTOK/128,1,3), 256, SMEM_GEMM_BYTES>>>(x, wqkvr, qkv);

    // ---- fused attention (natural V layout) ------------------------------------
    flash_attn<<<dim3(SEQ/128, BATCH), 256, FL_SMEM_BYTES>>>(
        qkv, qkv + (size_t)MTOK*DHEAD, qkv + 2*(size_t)MTOK*DHEAD, cur, curR);

    // ---- fused zfix precompute --------------------------------------------------
    zfix_fused<<<MTOK/128, 256, FUSED_SMEM_BYTES>>>(curR, twr, wdr, zfix);

    // ---- fully fused dialectical rounds ------------------------------------------
    for (int r = 0; r < NROUNDS; r++)
        round_fused<<<MTOK/128, 256, FUSED_SMEM_BYTES>>>(
            cur, curR, zfix, w1cr, w2r, cvec, b1, b2, gw, gb, active, flag, r);
}

// round 8
// speedup vs baseline: 7.0450x; 1.5308x over previous
#include <cuda_runtime.h>
#include <cuda_fp16.h>
#include <math.h>
#include <stdint.h>

#define BATCH   8
#define SEQ     2048
#define DMODEL  1024
#define DHEAD   128
#define MTOK    (BATCH*SEQ)          // 16384
#define NROUNDS 3
#define SCALE_F 0.08838834764831843f // 1/sqrt(128)
#define LOG2E_F 1.4426950408889634f

// ---------------- device scratch (no runtime allocation allowed) -------------
__device__ __align__(256) __half g_qkv[3*MTOK*DHEAD];         // q,k,v fp16
__device__ __align__(256) __half g_curR[MTOK*DHEAD];          // fp16 copy of cur
__device__ __align__(256) float  g_zfix[MTOK*DHEAD];
__device__ __align__(256) __half g_wqkvr[3*DHEAD*DMODEL];
__device__ __align__(256) __half g_twr[DHEAD*DHEAD];
__device__ __align__(256) __half g_w2r[DHEAD*DHEAD];
__device__ __align__(256) __half g_wdr[DHEAD*DHEAD];
__device__ __align__(256) __half g_w1cr[DHEAD*DHEAD];
__device__ float g_cvec[DHEAD];
__device__ int   g_active[MTOK];
__device__ int   g_flag[NROUNDS];

// ---------------- PTX helpers -------------------------------------------------
__device__ __forceinline__ uint32_t s2u(const void* p) {
    uint32_t a;
    asm("{ .reg .u64 t; cvta.to.shared.u64 t, %1; cvt.u32.u64 %0, t; }" : "=r"(a) : "l"(p));
    return a;
}
__device__ __forceinline__ void cp_async16(uint32_t dst, const void* src) {
    asm volatile("cp.async.cg.shared.global [%0], [%1], 16;" :: "r"(dst), "l"(src) : "memory");
}
#define CP_COMMIT() asm volatile("cp.async.commit_group;" ::: "memory")
#define CP_WAIT(N)  asm volatile("cp.async.wait_group %0;" :: "n"(N) : "memory")
#define U32(p) (*reinterpret_cast<const uint32_t*>(p))

__device__ __forceinline__ uint32_t pk(float lo, float hi) {
    __half2 h = __floats2half2_rn(lo, hi);
    return *reinterpret_cast<uint32_t*>(&h);
}

__device__ __forceinline__ void mma_f16(
    float& c0, float& c1, float& c2, float& c3,
    uint32_t a0, uint32_t a1, uint32_t a2, uint32_t a3,
    uint32_t b0, uint32_t b1)
{
    asm volatile(
        "mma.sync.aligned.m16n8k16.row.col.f32.f16.f16.f32 "
        "{%0,%1,%2,%3}, {%4,%5,%6,%7}, {%8,%9}, {%0,%1,%2,%3};"
        : "+f"(c0), "+f"(c1), "+f"(c2), "+f"(c3)
        : "r"(a0), "r"(a1), "r"(a2), "r"(a3), "r"(b0), "r"(b1));
}

__device__ __forceinline__ void ldsm4t(uint32_t& d0, uint32_t& d1, uint32_t& d2,
                                       uint32_t& d3, uint32_t addr)
{
    asm volatile("ldmatrix.sync.aligned.m8n8.x4.trans.shared.b16 {%0,%1,%2,%3}, [%4];"
        : "=r"(d0), "=r"(d1), "=r"(d2), "=r"(d3) : "r"(addr));
}

// ---------------- QKV GEMM (fp16 mma, fp32 x converted in-kernel) -------------
#define QSA 40
#define QTILE_H (128*QSA)
#define QSTG_H (2*QTILE_H)
#define QKV_SMEM_BYTES (2*QSTG_H*2)   // 40960

__global__ __launch_bounds__(256) void qkv_gemm(
    const float* __restrict__ X, const __half* __restrict__ W,
    __half* __restrict__ out)
{
    extern __shared__ char smraw[];
    __half* smh = (__half*)smraw;
    const uint32_t sm_u = s2u(smh);
    const int z = blockIdx.z;
    const __half* B = W + (size_t)z*DHEAD*DMODEL;
    __half* C = out + (size_t)z*MTOK*DHEAD;
    const int tid = threadIdx.x, lane = tid & 31, warp = tid >> 5;
    const int wm = (warp >> 1) * 32, wn = (warp & 1) * 64;
    const int m0 = blockIdx.x * 128;
    const int lrow = tid >> 3, lc4 = (tid & 7) * 4;
    const int brow = tid >> 2, bc8 = (tid & 3) * 8;
    const int g = lane >> 2, t4 = lane & 3;
    const int nK = DMODEL >> 5;   // 32

    float4 areg[4];
    {
        const float* Ag = X + (size_t)m0*DMODEL + lc4;
        #pragma unroll
        for (int it = 0; it < 4; it++)
            areg[it] = *reinterpret_cast<const float4*>(Ag + (size_t)(lrow+it*32)*DMODEL);
        #pragma unroll
        for (int itb = 0; itb < 2; itb++)
            cp_async16(sm_u + (uint32_t)(QTILE_H + (brow+itb*64)*QSA + bc8)*2u,
                       B + (size_t)(brow+itb*64)*DMODEL + bc8);
        CP_COMMIT();
        #pragma unroll
        for (int it = 0; it < 4; it++) {
            float4 v = areg[it];
            uint2 h2 = make_uint2(pk(v.x, v.y), pk(v.z, v.w));
            *reinterpret_cast<uint2*>(&smh[(lrow+it*32)*QSA + lc4]) = h2;
        }
    }

    float acc[2][8][4];
    #pragma unroll
    for (int mi = 0; mi < 2; mi++)
        #pragma unroll
        for (int ni = 0; ni < 8; ni++)
            #pragma unroll
            for (int j = 0; j < 4; j++) acc[mi][ni][j] = 0.f;

    for (int kt = 0; kt < nK; kt++) {
        const int cs = kt & 1;
        if (kt + 1 < nK) {
            const int ko = (kt+1)*32;
            const float* Ag = X + (size_t)m0*DMODEL + ko + lc4;
            #pragma unroll
            for (int it = 0; it < 4; it++)
                areg[it] = *reinterpret_cast<const float4*>(Ag + (size_t)(lrow+it*32)*DMODEL);
            const int ns = cs ^ 1;
            #pragma unroll
            for (int itb = 0; itb < 2; itb++)
                cp_async16(sm_u + (uint32_t)(ns*QSTG_H + QTILE_H + (brow+itb*64)*QSA + bc8)*2u,
                           B + (size_t)(brow+itb*64)*DMODEL + ko + bc8);
            CP_COMMIT();
            CP_WAIT(1);
        } else {
            CP_WAIT(0);
        }
        __syncthreads();

        const __half* Ash = smh + cs*QSTG_H;
        const __half* Bsh = Ash + QTILE_H;
        #pragma unroll
        for (int kk = 0; kk < 2; kk++) {
            const int k0 = kk*16 + 2*t4;
            uint32_t a[2][4];
            #pragma unroll
            for (int mi = 0; mi < 2; mi++) {
                const __half* ap = Ash + (wm + mi*16 + g)*QSA + k0;
                a[mi][0] = U32(ap);
                a[mi][1] = U32(ap + 8*QSA);
                a[mi][2] = U32(ap + 8);
                a[mi][3] = U32(ap + 8*QSA + 8);
            }
            #pragma unroll
            for (int ni = 0; ni < 8; ni++) {
                const __half* bp = Bsh + (wn + ni*8 + g)*QSA + k0;
                uint32_t b0 = U32(bp), b1 = U32(bp + 8);
                #pragma unroll
                for (int mi = 0; mi < 2; mi++)
                    mma_f16(acc[mi][ni][0], acc[mi][ni][1], acc[mi][ni][2], acc[mi][ni][3],
                            a[mi][0], a[mi][1], a[mi][2], a[mi][3], b0, b1);
            }
        }
        if (kt + 1 < nK) {
            const int ns = cs ^ 1;
            __half* Ad = smh + ns*QSTG_H;
            #pragma unroll
            for (int it = 0; it < 4; it++) {
                float4 v = areg[it];
                uint2 h2 = make_uint2(pk(v.x, v.y), pk(v.z, v.w));
                *reinterpret_cast<uint2*>(&Ad[(lrow+it*32)*QSA + lc4]) = h2;
            }
        }
        __syncthreads();
    }

    #pragma unroll
    for (int mi = 0; mi < 2; mi++) {
        const int rA = m0 + wm + mi*16 + g, rB = rA + 8;
        #pragma unroll
        for (int ni = 0; ni < 8; ni++) {
            const int c0 = wn + ni*8 + 2*t4;
            *reinterpret_cast<__half2*>(C + (size_t)rA*DHEAD + c0) =
                __floats2half2_rn(acc[mi][ni][0], acc[mi][ni][1]);
            *reinterpret_cast<__half2*>(C + (size_t)rB*DHEAD + c0) =
                __floats2half2_rn(acc[mi][ni][2], acc[mi][ni][3]);
        }
    }
}

// ---------------- fused flash attention (fp16 mma, register P) ----------------
#define SKV 136
#define FH_K 0
#define FH_V (2*64*SKV)
#define FL_SMEM_BYTES ((FH_V + 2*64*SKV)*2)   // 69632

__global__ __launch_bounds__(256) void flash_attn(
    const __half* __restrict__ q, const __half* __restrict__ k,
    const __half* __restrict__ v, float* __restrict__ outc,
    __half* __restrict__ outR)
{
    extern __shared__ char smraw[];
    __half* smh = (__half*)smraw;
    const uint32_t sm_u = s2u(smh);
    const int b   = blockIdx.y;
    const int qb  = blockIdx.x * 128;
    const int tid = threadIdx.x, lane = tid & 31, warp = tid >> 5;
    const int g   = lane >> 2, t4 = lane & 3;

    const __half* qB = q + ((size_t)b*SEQ + qb)*DHEAD;
    const __half* kB = k + (size_t)b*SEQ*DHEAD;
    const __half* vB = v + (size_t)b*SEQ*DHEAD;

    const int kc = tid >> 4;          // 0..15 (+16/iter, 4 iters)
    const int kf = (tid & 15) * 8;    // halves

    uint32_t qa[8][4];
    {
        const __half* q0 = qB + (size_t)(warp*16 + g)*DHEAD;
        const __half* q8 = q0 + 8*DHEAD;
        #pragma unroll
        for (int ks = 0; ks < 8; ks++) {
            const int o = ks*16 + 2*t4;
            qa[ks][0] = U32(q0 + o);
            qa[ks][1] = U32(q8 + o);
            qa[ks][2] = U32(q0 + o + 8);
            qa[ks][3] = U32(q8 + o + 8);
        }
    }

    float oacc[16][4];
    #pragma unroll
    for (int ni = 0; ni < 16; ni++)
        #pragma unroll
        for (int j = 0; j < 4; j++) oacc[ni][j] = 0.f;
    float m0 = -1e30f, m1 = -1e30f, l0 = 0.f, l1 = 0.f;

    {
        #pragma unroll
        for (int it = 0; it < 4; it++) {
            cp_async16(sm_u + (uint32_t)(FH_K + (kc + it*16)*SKV + kf)*2u,
                       kB + (size_t)(kc + it*16)*DHEAD + kf);
            cp_async16(sm_u + (uint32_t)(FH_V + (kc + it*16)*SKV + kf)*2u,
                       vB + (size_t)(kc + it*16)*DHEAD + kf);
        }
        CP_COMMIT();
    }

    const int nTiles = SEQ / 64;  // 32
    for (int t = 0; t < nTiles; t++) {
        const int cs = t & 1;
        if (t + 1 < nTiles) {
            const int ns = cs ^ 1;
            const int kv1 = (t+1) * 64;
            #pragma unroll
            for (int it = 0; it < 4; it++) {
                cp_async16(sm_u + (uint32_t)(FH_K + ns*64*SKV + (kc + it*16)*SKV + kf)*2u,
                           kB + (size_t)(kv1 + kc + it*16)*DHEAD + kf);
                cp_async16(sm_u + (uint32_t)(FH_V + ns*64*SKV + (kc + it*16)*SKV + kf)*2u,
                           vB + (size_t)(kv1 + kc + it*16)*DHEAD + kf);
            }
            CP_COMMIT();
            CP_WAIT(1);
        } else {
            CP_WAIT(0);
        }
        __syncthreads();

        const __half* Ks = smh + FH_K + cs*64*SKV;
        const uint32_t vb0 = sm_u + (uint32_t)(FH_V + cs*64*SKV + lane*SKV)*2u;

        // S = Q @ K^T (16 x 64 per warp)
        float sacc[8][4];
        #pragma unroll
        for (int ni = 0; ni < 8; ni++)
            #pragma unroll
            for (int j = 0; j < 4; j++) sacc[ni][j] = 0.f;
        #pragma unroll
        for (int ks = 0; ks < 8; ks++) {
            #pragma unroll
            for (int ni = 0; ni < 8; ni++) {
                const __half* bp = Ks + (ni*8+g)*SKV + ks*16 + 2*t4;
                mma_f16(sacc[ni][0], sacc[ni][1], sacc[ni][2], sacc[ni][3],
                        qa[ks][0], qa[ks][1], qa[ks][2], qa[ks][3],
                        U32(bp), U32(bp + 8));
            }
        }

        // online softmax (rows g and g+8; stats across quad lanes)
        float mx0 = -1e30f, mx1 = -1e30f;
        #pragma unroll
        for (int ni = 0; ni < 8; ni++) {
            sacc[ni][0] *= SCALE_F; sacc[ni][1] *= SCALE_F;
            sacc[ni][2] *= SCALE_F; sacc[ni][3] *= SCALE_F;
            mx0 = fmaxf(mx0, fmaxf(sacc[ni][0], sacc[ni][1]));
            mx1 = fmaxf(mx1, fmaxf(sacc[ni][2], sacc[ni][3]));
        }
        mx0 = fmaxf(mx0, __shfl_xor_sync(0xffffffffu, mx0, 1));
        mx0 = fmaxf(mx0, __shfl_xor_sync(0xffffffffu, mx0, 2));
        mx1 = fmaxf(mx1, __shfl_xor_sync(0xffffffffu, mx1, 1));
        mx1 = fmaxf(mx1, __shfl_xor_sync(0xffffffffu, mx1, 2));
        const float nm0 = fmaxf(m0, mx0), nm1 = fmaxf(m1, mx1);
        const float sc0 = exp2f((m0 - nm0) * LOG2E_F);
        const float sc1 = exp2f((m1 - nm1) * LOG2E_F);
        m0 = nm0; m1 = nm1;

        float rs0 = 0.f, rs1 = 0.f;
        uint32_t pa[4][4];
        #pragma unroll
        for (int j = 0; j < 4; j++) {
            const int n0i = 2*j, n1i = 2*j + 1;
            float p00 = exp2f((sacc[n0i][0] - nm0) * LOG2E_F);
            float p01 = exp2f((sacc[n0i][1] - nm0) * LOG2E_F);
            float p02 = exp2f((sacc[n0i][2] - nm1) * LOG2E_F);
            float p03 = exp2f((sacc[n0i][3] - nm1) * LOG2E_F);
            float p10 = exp2f((sacc[n1i][0] - nm0) * LOG2E_F);
            float p11 = exp2f((sacc[n1i][1] - nm0) * LOG2E_F);
            float p12 = exp2f((sacc[n1i][2] - nm1) * LOG2E_F);
            float p13 = exp2f((sacc[n1i][3] - nm1) * LOG2E_F);
            rs0 += p00 + p01 + p10 + p11;
            rs1 += p02 + p03 + p12 + p13;
            pa[j][0] = pk(p00, p01);   // A row g,   kv 16j+2t4
            pa[j][1] = pk(p02, p03);   // A row g+8, kv 16j+2t4
            pa[j][2] = pk(p10, p11);   // A row g,   kv 16j+8+2t4
            pa[j][3] = pk(p12, p13);   // A row g+8, kv 16j+8+2t4
        }
        rs0 += __shfl_xor_sync(0xffffffffu, rs0, 1);
        rs0 += __shfl_xor_sync(0xffffffffu, rs0, 2);
        rs1 += __shfl_xor_sync(0xffffffffu, rs1, 1);
        rs1 += __shfl_xor_sync(0xffffffffu, rs1, 2);
        l0 = l0 * sc0 + rs0;
        l1 = l1 * sc1 + rs1;
        #pragma unroll
        for (int ni = 0; ni < 16; ni++) {
            oacc[ni][0] *= sc0; oacc[ni][1] *= sc0;
            oacc[ni][2] *= sc1; oacc[ni][3] *= sc1;
        }

        // O += P @ V : A = register P frags, B = ldmatrix.trans from natural V
        #pragma unroll
        for (int jp = 0; jp < 2; jp++) {
            const uint32_t ab = vb0 + (uint32_t)(jp*32*SKV)*2u;
            #pragma unroll
            for (int ni = 0; ni < 16; ni++) {
                uint32_t b0, b1, b2, b3;
                ldsm4t(b0, b1, b2, b3, ab + ni*16);
                mma_f16(oacc[ni][0], oacc[ni][1], oacc[ni][2], oacc[ni][3],
                        pa[2*jp][0], pa[2*jp][1], pa[2*jp][2], pa[2*jp][3], b0, b1);
                mma_f16(oacc[ni][0], oacc[ni][1], oacc[ni][2], oacc[ni][3],
                        pa[2*jp+1][0], pa[2*jp+1][1], pa[2*jp+1][2], pa[2*jp+1][3], b2, b3);
            }
        }
        __syncthreads();
    }

    const float inv0 = 1.f / l0, inv1 = 1.f / l1;
    const size_t rowA = (size_t)b*SEQ + qb + warp*16 + g;
    const size_t rowB = rowA + 8;
    #pragma unroll
    for (int ni = 0; ni < 16; ni++) {
        const int c0 = ni*8 + 2*t4;
        float2 v0, v1;
        v0.x = oacc[ni][0]*inv0; v0.y = oacc[ni][1]*inv0;
        v1.x = oacc[ni][2]*inv1; v1.y = oacc[ni][3]*inv1;
        *reinterpret_cast<float2*>(outc + rowA*DHEAD + c0) = v0;
        *reinterpret_cast<float2*>(outc + rowB*DHEAD + c0) = v1;
        *reinterpret_cast<__half2*>(outR + rowA*DHEAD + c0) = __floats2half2_rn(v0.x, v0.y);
        *reinterpret_cast<__half2*>(outR + rowB*DHEAD + c0) = __floats2half2_rn(v1.x, v1.y);
    }
}

// ---------------- fused double-GEMM kernels (fp16, K = 128) -------------------
#define HSMS 136
#define H_T1 (128*HSMS)
#define H_T2 (2*128*HSMS)
#define H_RED_B (3*128*HSMS*2)
#define FUSED_SMEM_BYTES (H_RED_B + 128*4*4)   // 106496

__device__ __forceinline__ void load_tile128h(uint32_t sdst, const __half* __restrict__ src,
                                              int tid)
{
    const int row = tid >> 4, c8 = (tid & 15) * 8;
    #pragma unroll
    for (int it = 0; it < 8; it++)
        cp_async16(sdst + (uint32_t)((row + it*16)*HSMS + c8)*2u,
                   src + (size_t)(row + it*16)*128 + c8);
}

__device__ __forceinline__ void mma_128x128h(const __half* __restrict__ As,
                                             const __half* __restrict__ Bs,
                                             float acc[2][8][4],
                                             int wm, int wn, int g, int t4)
{
    #pragma unroll
    for (int ks = 0; ks < 8; ks++) {
        const int k0 = ks*16 + 2*t4;
        uint32_t a[2][4];
        #pragma unroll
        for (int mi = 0; mi < 2; mi++) {
            const __half* ap = As + (wm + mi*16 + g)*HSMS + k0;
            a[mi][0] = U32(ap);
            a[mi][1] = U32(ap + 8*HSMS);
            a[mi][2] = U32(ap + 8);
            a[mi][3] = U32(ap + 8*HSMS + 8);
        }
        #pragma unroll
        for (int ni = 0; ni < 8; ni++) {
            const __half* bp = Bs + (wn + ni*8 + g)*HSMS + k0;
            uint32_t b0 = U32(bp), b1 = U32(bp + 8);
            #pragma unroll
            for (int mi = 0; mi < 2; mi++)
                mma_f16(acc[mi][ni][0], acc[mi][ni][1], acc[mi][ni][2], acc[mi][ni][3],
                        a[mi][0], a[mi][1], a[mi][2], a[mi][3], b0, b1);
        }
    }
}

// zfix = (curR @ tw^T rounded) @ wd^T
__global__ __launch_bounds__(256) void zfix_fused(
    const __half* __restrict__ curR, const __half* __restrict__ tw,
    const __half* __restrict__ wd, float* __restrict__ zfix)
{
    extern __shared__ char smraw[];
    __half* smh = (__half*)smraw;
    const uint32_t sm_u = s2u(smh);
    const int tid = threadIdx.x, lane = tid & 31, warp = tid >> 5;
    const int wm = (warp >> 1) * 32, wn = (warp & 1) * 64;
    const int g = lane >> 2, t4 = lane & 3;
    const int m0 = blockIdx.x * 128;

    load_tile128h(sm_u, curR + (size_t)m0*128, tid);
    load_tile128h(sm_u + H_T1*2, tw, tid);
    load_tile128h(sm_u + H_T2*2, wd, tid);
    CP_COMMIT(); CP_WAIT(0);
    __syncthreads();

    float acc[2][8][4];
    #pragma unroll
    for (int mi = 0; mi < 2; mi++)
        #pragma unroll
        for (int ni = 0; ni < 8; ni++)
            #pragma unroll
            for (int j = 0; j < 4; j++) acc[mi][ni][j] = 0.f;

    mma_128x128h(smh, smh + H_T1, acc, wm, wn, g, t4);
    __syncthreads();

    #pragma unroll
    for (int mi = 0; mi < 2; mi++) {
        const int rA = wm + mi*16 + g, rB = rA + 8;
        #pragma unroll
        for (int ni = 0; ni < 8; ni++) {
            const int c0 = wn + ni*8 + 2*t4;
            *reinterpret_cast<__half2*>(&smh[rA*HSMS + c0]) =
                __floats2half2_rn(acc[mi][ni][0], acc[mi][ni][1]);
            *reinterpret_cast<__half2*>(&smh[rB*HSMS + c0]) =
                __floats2half2_rn(acc[mi][ni][2], acc[mi][ni][3]);
        }
    }
    __syncthreads();

    #pragma unroll
    for (int mi = 0; mi < 2; mi++)
        #pragma unroll
        for (int ni = 0; ni < 8; ni++)
            #pragma unroll
            for (int j = 0; j < 4; j++) acc[mi][ni][j] = 0.f;

    mma_128x128h(smh, smh + H_T2, acc, wm, wn, g, t4);

    #pragma unroll
    for (int mi = 0; mi < 2; mi++) {
        const int rA = m0 + wm + mi*16 + g, rB = rA + 8;
        #pragma unroll
        for (int ni = 0; ni < 8; ni++) {
            const int c0 = wn + ni*8 + 2*t4;
            float2 v0, v1;
            v0.x = acc[mi][ni][0]; v0.y = acc[mi][ni][1];
            v1.x = acc[mi][ni][2]; v1.y = acc[mi][ni][3];
            *reinterpret_cast<float2*>(zfix + (size_t)rA*128 + c0) = v0;
            *reinterpret_cast<float2*>(zfix + (size_t)rB*128 + c0) = v1;
        }
    }
}

// One full dialectical round
__global__ __launch_bounds__(256) void round_fused(
    float* __restrict__ cur, __half* __restrict__ curR,
    const float* __restrict__ zfix,
    const __half* __restrict__ w1c, const __half* __restrict__ w2,
    const float* __restrict__ cvec, const float* __restrict__ b1,
    const float* __restrict__ b2, const float* __restrict__ gw,
    const float* __restrict__ gb, int* __restrict__ active,
    int* __restrict__ flag, int r)
{
    extern __shared__ char smraw[];
    __half* smh = (__half*)smraw;
    const uint32_t sm_u = s2u(smh);
    __shared__ int s_any;
    const int tid = threadIdx.x, lane = tid & 31, warp = tid >> 5;
    const int wm = (warp >> 1) * 32, wn = (warp & 1) * 64;
    const int g = lane >> 2, t4 = lane & 3;
    const int m0 = blockIdx.x * 128;
    if (tid == 0) s_any = 0;

    load_tile128h(sm_u, curR + (size_t)m0*128, tid);
    load_tile128h(sm_u + H_T1*2, w1c, tid);
    load_tile128h(sm_u + H_T2*2, w2, tid);
    CP_COMMIT(); CP_WAIT(0);
    __syncthreads();

    float acc[2][8][4];
    #pragma unroll
    for (int mi = 0; mi < 2; mi++)
        #pragma unroll
        for (int ni = 0; ni < 8; ni++)
            #pragma unroll
            for (int j = 0; j < 4; j++) acc[mi][ni][j] = 0.f;

    mma_128x128h(smh, smh + H_T1, acc, wm, wn, g, t4);
    __syncthreads();

    float amr[4];
    #pragma unroll
    for (int mi = 0; mi < 2; mi++) {
        const int rA = wm + mi*16 + g, rB = rA + 8;
        const float amA = active[m0 + rA] ? 1.f : 0.f;
        const float amB = active[m0 + rB] ? 1.f : 0.f;
        amr[mi*2] = amA; amr[mi*2+1] = amB;
        #pragma unroll
        for (int ni = 0; ni < 8; ni++) {
            const int c0 = wn + ni*8 + 2*t4;
            float2 zA = *reinterpret_cast<const float2*>(zfix + (size_t)(m0+rA)*128 + c0);
            float2 zB = *reinterpret_cast<const float2*>(zfix + (size_t)(m0+rB)*128 + c0);
            float2 cc = *reinterpret_cast<const float2*>(cvec + c0);
            float2 bb = *reinterpret_cast<const float2*>(b1 + c0);
            float h00 = fmaxf(fmaf(amA, acc[mi][ni][0] + zA.x + cc.x, bb.x), 0.f);
            float h01 = fmaxf(fmaf(amA, acc[mi][ni][1] + zA.y + cc.y, bb.y), 0.f);
            float h10 = fmaxf(fmaf(amB, acc[mi][ni][2] + zB.x + cc.x, bb.x), 0.f);
            float h11 = fmaxf(fmaf(amB, acc[mi][ni][3] + zB.y + cc.y, bb.y), 0.f);
            *reinterpret_cast<__half2*>(&smh[rA*HSMS + c0]) = __floats2half2_rn(h00, h01);
            *reinterpret_cast<__half2*>(&smh[rB*HSMS + c0]) = __floats2half2_rn(h10, h11);
        }
    }
    __syncthreads();

    #pragma unroll
    for (int mi = 0; mi < 2; mi++)
        #pragma unroll
        for (int ni = 0; ni < 8; ni++)
            #pragma unroll
            for (int j = 0; j < 4; j++) acc[mi][ni][j] = 0.f;

    mma_128x128h(smh, smh + H_T2, acc, wm, wn, g, t4);

    const int flg = flag[r];
    float d1[4] = {0,0,0,0}, nn[4] = {0,0,0,0};
    #pragma unroll
    for (int mi = 0; mi < 2; mi++) {
        const int rA = wm + mi*16 + g, rB = rA + 8;
        const float amA = amr[mi*2], amB = amr[mi*2+1];
        #pragma unroll
        for (int ni = 0; ni < 8; ni++) {
            const int c0 = wn + ni*8 + 2*t4;
            float2 cA = *reinterpret_cast<const float2*>(cur + (size_t)(m0+rA)*128 + c0);
            float2 cB = *reinterpret_cast<const float2*>(cur + (size_t)(m0+rB)*128 + c0);
            float2 bb = *reinterpret_cast<const float2*>(b2 + c0);
            float2 g1 = *reinterpret_cast<const float2*>(gw + c0);
            float2 g2 = *reinterpret_cast<const float2*>(gw + 128 + c0);
            float syA0 = acc[mi][ni][0] + bb.x, syA1 = acc[mi][ni][1] + bb.y;
            float syB0 = acc[mi][ni][2] + bb.x, syB1 = acc[mi][ni][3] + bb.y;
            float acA0 = cA.x * amA, acA1 = cA.y * amA;
            float acB0 = cB.x * amB, acB1 = cB.y * amB;
            d1[mi*2]   += acA0*g1.x + syA0*g2.x + acA1*g1.y + syA1*g2.y;
            d1[mi*2+1] += acB0*g1.x + syB0*g2.x + acB1*g1.y + syB1*g2.y;
            float dA0 = syA0-acA0, dA1 = syA1-acA1;
            float dB0 = syB0-acB0, dB1 = syB1-acB1;
            nn[mi*2]   += dA0*dA0 + dA1*dA1;
            nn[mi*2+1] += dB0*dB0 + dB1*dB1;
        }
    }
    #pragma unroll
    for (int j = 0; j < 4; j++) {
        d1[j] += __shfl_xor_sync(0xffffffffu, d1[j], 1);
        d1[j] += __shfl_xor_sync(0xffffffffu, d1[j], 2);
        nn[j] += __shfl_xor_sync(0xffffffffu, nn[j], 1);
        nn[j] += __shfl_xor_sync(0xffffffffu, nn[j], 2);
    }
    float* red = reinterpret_cast<float*>(smraw + H_RED_B);
    if (t4 == 0) {
        const int hf = (warp & 1) * 2;
        #pragma unroll
        for (int mi = 0; mi < 2; mi++) {
            const int rA = wm + mi*16 + g, rB = rA + 8;
            red[rA*4 + hf]     = d1[mi*2];
            red[rA*4 + hf + 1] = nn[mi*2];
            red[rB*4 + hf]     = d1[mi*2+1];
            red[rB*4 + hf + 1] = nn[mi*2+1];
        }
    }
    __syncthreads();

    const float gbv = gb[0];
    #pragma unroll
    for (int mi = 0; mi < 2; mi++) {
        const int rA = wm + mi*16 + g, rB = rA + 8;
        const float amA = amr[mi*2], amB = amr[mi*2+1];
        float gdA = red[rA*4+0] + red[rA*4+2] + gbv;
        float gdB = red[rB*4+0] + red[rB*4+2] + gbv;
        float n2A = red[rA*4+1] + red[rA*4+3];
        float n2B = red[rB*4+1] + red[rB*4+3];
        float gateA = 1.f / (1.f + expf(-gdA));
        float gateB = 1.f / (1.f + expf(-gdB));
        int stableA = (gateA * 0.1f * sqrtf(n2A)) < 0.1f;
        int stableB = (gateB * 0.1f * sqrtf(n2B)) < 0.1f;
        #pragma unroll
        for (int ni = 0; ni < 8; ni++) {
            const int c0 = wn + ni*8 + 2*t4;
            float2 cA = *reinterpret_cast<const float2*>(cur + (size_t)(m0+rA)*128 + c0);
            float2 cB = *reinterpret_cast<const float2*>(cur + (size_t)(m0+rB)*128 + c0);
            float2 bb = *reinterpret_cast<const float2*>(b2 + c0);
            float syA0 = acc[mi][ni][0] + bb.x, syA1 = acc[mi][ni][1] + bb.y;
            float syB0 = acc[mi][ni][2] + bb.x, syB1 = acc[mi][ni][3] + bb.y;
            float2 o0, o1;
            o0.x = cA.x; o0.y = cA.y; o1.x = cB.x; o1.y = cB.y;
            if (flg) {
                o0.x += gateA * (syA0 - cA.x*amA) * 0.1f;
                o0.y += gateA * (syA1 - cA.y*amA) * 0.1f;
                o1.x += gateB * (syB0 - cB.x*amB) * 0.1f;
                o1.y += gateB * (syB1 - cB.y*amB) * 0.1f;
            }
            *reinterpret_cast<float2*>(cur + (size_t)(m0+rA)*128 + c0) = o0;
            *reinterpret_cast<float2*>(cur + (size_t)(m0+rB)*128 + c0) = o1;
            *reinterpret_cast<__half2*>(curR + (size_t)(m0+rA)*128 + c0) =
                __floats2half2_rn(o0.x, o0.y);
            *reinterpret_cast<__half2*>(curR + (size_t)(m0+rB)*128 + c0) =
                __floats2half2_rn(o1.x, o1.y);
        }
        if ((warp & 1) == 0 && t4 == 0) {
            int actA = amA > 0.f, actB = amB > 0.f;
            int naA = actA && !stableA;
            int naB = actB && !stableB;
            if (flg) { active[m0+rA] = naA; active[m0+rB] = naB; }
            int effA = flg ? naA : actA;
            int effB = flg ? naB : actB;
            if (effA | effB) s_any = 1;
        }
    }
    __syncthreads();
    if (tid == 0 && (r + 1) < NROUNDS && s_any) atomicOr(&flag[r+1], 1);
}

// ---------------- single prep kernel (fp16 weight copies) ---------------------
__global__ void prep_all(
    const float* __restrict__ wq, const float* __restrict__ wk,
    const float* __restrict__ wv, const float* __restrict__ tw,
    const float* __restrict__ w2, const float* __restrict__ w1,
    const float* __restrict__ tb, const float* __restrict__ ab,
    __half* __restrict__ wqkvr, __half* __restrict__ twr,
    __half* __restrict__ w2r, __half* __restrict__ wdr,
    __half* __restrict__ w1cr, float* __restrict__ cvec,
    int* __restrict__ active, int* __restrict__ flag)
{
    int idx = blockIdx.x * blockDim.x + threadIdx.x;
    const int WN4 = DHEAD*DMODEL/4;
    const int T4  = DHEAD*DHEAD/4;
    if (idx < 3*WN4) {
        const float* src = (idx < WN4) ? wq : (idx < 2*WN4 ? wk : wv);
        int off = (idx < WN4) ? idx : (idx < 2*WN4 ? idx - WN4 : idx - 2*WN4);
        float4 vv = reinterpret_cast<const float4*>(src)[off];
        reinterpret_cast<__half2*>(wqkvr)[2*idx]   = __floats2half2_rn(vv.x, vv.y);
        reinterpret_cast<__half2*>(wqkvr)[2*idx+1] = __floats2half2_rn(vv.z, vv.w);
        return;
    }
    idx -= 3*WN4;
    if (idx < T4) {
        float4 vv = reinterpret_cast<const float4*>(tw)[idx];
        reinterpret_cast<__half2*>(twr)[2*idx]   = __floats2half2_rn(vv.x, vv.y);
        reinterpret_cast<__half2*>(twr)[2*idx+1] = __floats2half2_rn(vv.z, vv.w);
        return;
    }
    idx -= T4;
    if (idx < T4) {
        float4 vv = reinterpret_cast<const float4*>(w2)[idx];
        reinterpret_cast<__half2*>(w2r)[2*idx]   = __floats2half2_rn(vv.x, vv.y);
        reinterpret_cast<__half2*>(w2r)[2*idx+1] = __floats2half2_rn(vv.z, vv.w);
        return;
    }
    idx -= T4;
    if (idx < DHEAD*DHEAD) {
        int j = idx >> 7, i = idx & 127;
        wdr[idx]  = __float2half_rn(w1[j*384 + i] - w1[j*384 + 128 + i]);
        w1cr[idx] = __float2half_rn(w1[j*384 + 256 + i]);
        return;
    }
    idx -= DHEAD*DHEAD;
    if (idx < MTOK) { active[idx] = 1; return; }
    idx -= MTOK;
    if (idx < NROUNDS) { flag[idx] = (idx == 0) ? 1 : 0; return; }
    idx -= NROUNDS;
    if (idx < DHEAD) {
        float s = 0.f;
        for (int i = 0; i < 128; i++)
            s += tb[i]*w1[idx*384 + i] + ab[i]*w1[idx*384 + 128 + i];
        cvec[idx] = s;
    }
}
#define PREP_ITEMS (3*(DHEAD*DMODEL/4) + 2*(DHEAD*DHEAD/4) + DHEAD*DHEAD + MTOK + NROUNDS + DHEAD)

// ---------------- launch ------------------------------------------------------
extern "C" void kernel_launch(void* const* d_in, const int* in_sizes, int n_in,
                              void* d_out, int out_size)
{
    (void)in_sizes; (void)n_in; (void)out_size;
    const float* x  = (const float*)d_in[0];
    const float* wq = (const float*)d_in[1];
    const float* wk = (const float*)d_in[2];
    const float* wv = (const float*)d_in[3];
    const float* tw = (const float*)d_in[4];
    const float* tb = (const float*)d_in[5];
    const float* ab = (const float*)d_in[6];
    const float* w1 = (const float*)d_in[7];
    const float* b1 = (const float*)d_in[8];
    const float* w2 = (const float*)d_in[9];
    const float* b2 = (const float*)d_in[10];
    const float* gw = (const float*)d_in[11];
    const float* gb = (const float*)d_in[12];
    float* cur = (float*)d_out;

    __half *qkv,*curR,*wqkvr,*twr,*w2r,*wdr,*w1cr;
    float *zfix,*cvec;
    int *active,*flag;
    cudaGetSymbolAddress((void**)&qkv,    g_qkv);
    cudaGetSymbolAddress((void**)&curR,   g_curR);
    cudaGetSymbolAddress((void**)&zfix,   g_zfix);
    cudaGetSymbolAddress((void**)&wqkvr,  g_wqkvr);
    cudaGetSymbolAddress((void**)&twr,    g_twr);
    cudaGetSymbolAddress((void**)&w2r,    g_w2r);
    cudaGetSymbolAddress((void**)&wdr,    g_wdr);
    cudaGetSymbolAddress((void**)&w1cr,   g_w1cr);
    cudaGetSymbolAddress((void**)&cvec,   g_cvec);
    cudaGetSymbolAddress((void**)&active, g_active);
    cudaGetSymbolAddress((void**)&flag,   g_flag);

    cudaFuncSetAttribute(qkv_gemm,    cudaFuncAttributeMaxDynamicSharedMemorySize, QKV_SMEM_BYTES);
    cudaFuncSetAttribute(flash_attn,  cudaFuncAttributeMaxDynamicSharedMemorySize, FL_SMEM_BYTES);
    cudaFuncSetAttribute(zfix_fused,  cudaFuncAttributeMaxDynamicSharedMemorySize, FUSED_SMEM_BYTES);
    cudaFuncSetAttribute(round_fused, cudaFuncAttributeMaxDynamicSharedMemorySize, FUSED_SMEM_BYTES);

    prep_all<<<(PREP_ITEMS + 255)/256, 256>>>(
        wq, wk, wv, tw, w2, w1, tb, ab,
        wqkvr, twr, w2r, wdr, w1cr, cvec, active, flag);

    qkv_gemm<<<dim3(MTOK/128,1,3), 256, QKV_SMEM_BYTES>>>(x, wqkvr, qkv);

    flash_attn<<<dim3(SEQ/128, BATCH), 256, FL_SMEM_BYTES>>>(
        qkv, qkv + (size_t)MTOK*DHEAD, qkv + 2*(size_t)MTOK*DHEAD, cur, curR);

    zfix_fused<<<MTOK/128, 256, FUSED_SMEM_BYTES>>>(curR, twr, wdr, zfix);

    for (int r = 0; r < NROUNDS; r++)
        round_fused<<<MTOK/128, 256, FUSED_SMEM_BYTES>>>(
            cur, curR, zfix, w1cr, w2r, cvec, b1, b2, gw, gb, active, flag, r);
}

// round 9
// speedup vs baseline: 7.5752x; 1.0753x over previous
#include <cuda_runtime.h>
#include <cuda_fp16.h>
#include <math.h>
#include <stdint.h>

#define BATCH   8
#define SEQ     2048
#define DMODEL  1024
#define DHEAD   128
#define MTOK    (BATCH*SEQ)          // 16384
#define NROUNDS 3
#define SCALE_F 0.08838834764831843f // 1/sqrt(128)
#define LOG2E_F 1.4426950408889634f

// ---------------- device scratch (no runtime allocation allowed) -------------
__device__ __align__(256) __half g_qkv[3*MTOK*DHEAD];         // q,k,v fp16
__device__ __align__(256) __half g_curR[MTOK*DHEAD];          // fp16 copy of cur
__device__ __align__(256) __half g_wqkvr[3*DHEAD*DMODEL];
__device__ __align__(256) __half g_twr[DHEAD*DHEAD];
__device__ __align__(256) __half g_w2r[DHEAD*DHEAD];
__device__ __align__(256) __half g_wdr[DHEAD*DHEAD];
__device__ __align__(256) __half g_w1cr[DHEAD*DHEAD];
__device__ float g_cvec[DHEAD];
__device__ int   g_cnt[NROUNDS];
__device__ int   g_any[NROUNDS];

// ---------------- PTX helpers -------------------------------------------------
__device__ __forceinline__ uint32_t s2u(const void* p) {
    uint32_t a;
    asm("{ .reg .u64 t; cvta.to.shared.u64 t, %1; cvt.u32.u64 %0, t; }" : "=r"(a) : "l"(p));
    return a;
}
__device__ __forceinline__ void cp_async16(uint32_t dst, const void* src) {
    asm volatile("cp.async.cg.shared.global [%0], [%1], 16;" :: "r"(dst), "l"(src) : "memory");
}
#define CP_COMMIT() asm volatile("cp.async.commit_group;" ::: "memory")
#define CP_WAIT(N)  asm volatile("cp.async.wait_group %0;" :: "n"(N) : "memory")
#define U32(p) (*reinterpret_cast<const uint32_t*>(p))

__device__ __forceinline__ uint32_t pk(float lo, float hi) {
    __half2 h = __floats2half2_rn(lo, hi);
    return *reinterpret_cast<uint32_t*>(&h);
}
__device__ __forceinline__ float ex2f(float x) {
    float y;
    asm("ex2.approx.ftz.f32 %0, %1;" : "=f"(y) : "f"(x));
    return y;
}

__device__ __forceinline__ void mma_f16(
    float& c0, float& c1, float& c2, float& c3,
    uint32_t a0, uint32_t a1, uint32_t a2, uint32_t a3,
    uint32_t b0, uint32_t b1)
{
    asm volatile(
        "mma.sync.aligned.m16n8k16.row.col.f32.f16.f16.f32 "
        "{%0,%1,%2,%3}, {%4,%5,%6,%7}, {%8,%9}, {%0,%1,%2,%3};"
        : "+f"(c0), "+f"(c1), "+f"(c2), "+f"(c3)
        : "r"(a0), "r"(a1), "r"(a2), "r"(a3), "r"(b0), "r"(b1));
}

__device__ __forceinline__ void ldsm4(uint32_t& d0, uint32_t& d1, uint32_t& d2,
                                      uint32_t& d3, uint32_t addr)
{
    asm volatile("ldmatrix.sync.aligned.m8n8.x4.shared.b16 {%0,%1,%2,%3}, [%4];"
        : "=r"(d0), "=r"(d1), "=r"(d2), "=r"(d3) : "r"(addr));
}
__device__ __forceinline__ void ldsm4t(uint32_t& d0, uint32_t& d1, uint32_t& d2,
                                       uint32_t& d3, uint32_t addr)
{
    asm volatile("ldmatrix.sync.aligned.m8n8.x4.trans.shared.b16 {%0,%1,%2,%3}, [%4];"
        : "=r"(d0), "=r"(d1), "=r"(d2), "=r"(d3) : "r"(addr));
}

// ---------------- QKV GEMM (fp16 mma, fp32 x converted in-kernel) -------------
#define QSA 40
#define QTILE_H (128*QSA)
#define QSTG_H (2*QTILE_H)
#define QKV_SMEM_BYTES (2*QSTG_H*2)   // 40960

__global__ __launch_bounds__(256) void qkv_gemm(
    const float* __restrict__ X, const __half* __restrict__ W,
    __half* __restrict__ out)
{
    extern __shared__ char smraw[];
    __half* smh = (__half*)smraw;
    const uint32_t sm_u = s2u(smh);
    const int z = blockIdx.x;                 // z fastest -> L2 reuse of x rows
    const __half* B = W + (size_t)z*DHEAD*DMODEL;
    __half* C = out + (size_t)z*MTOK*DHEAD;
    const int tid = threadIdx.x, lane = tid & 31, warp = tid >> 5;
    const int wm = (warp >> 1) * 32, wn = (warp & 1) * 64;
    const int m0 = blockIdx.y * 128;
    const int lrow = tid >> 3, lc4 = (tid & 7) * 4;
    const int brow = tid >> 2, bc8 = (tid & 3) * 8;
    const int g = lane >> 2, t4 = lane & 3;
    const int nK = DMODEL >> 5;   // 32

    float4 areg[4];
    {
        const float* Ag = X + (size_t)m0*DMODEL + lc4;
        #pragma unroll
        for (int it = 0; it < 4; it++)
            areg[it] = *reinterpret_cast<const float4*>(Ag + (size_t)(lrow+it*32)*DMODEL);
        #pragma unroll
        for (int itb = 0; itb < 2; itb++)
            cp_async16(sm_u + (uint32_t)(QTILE_H + (brow+itb*64)*QSA + bc8)*2u,
                       B + (size_t)(brow+itb*64)*DMODEL + bc8);
        CP_COMMIT();
        #pragma unroll
        for (int it = 0; it < 4; it++) {
            float4 v = areg[it];
            uint2 h2 = make_uint2(pk(v.x, v.y), pk(v.z, v.w));
            *reinterpret_cast<uint2*>(&smh[(lrow+it*32)*QSA + lc4]) = h2;
        }
    }

    float acc[2][8][4];
    #pragma unroll
    for (int mi = 0; mi < 2; mi++)
        #pragma unroll
        for (int ni = 0; ni < 8; ni++)
            #pragma unroll
            for (int j = 0; j < 4; j++) acc[mi][ni][j] = 0.f;

    for (int kt = 0; kt < nK; kt++) {
        const int cs = kt & 1;
        if (kt + 1 < nK) {
            const int ko = (kt+1)*32;
            const float* Ag = X + (size_t)m0*DMODEL + ko + lc4;
            #pragma unroll
            for (int it = 0; it < 4; it++)
                areg[it] = *reinterpret_cast<const float4*>(Ag + (size_t)(lrow+it*32)*DMODEL);
            const int ns = cs ^ 1;
            #pragma unroll
            for (int itb = 0; itb < 2; itb++)
                cp_async16(sm_u + (uint32_t)(ns*QSTG_H + QTILE_H + (brow+itb*64)*QSA + bc8)*2u,
                           B + (size_t)(brow+itb*64)*DMODEL + ko + bc8);
            CP_COMMIT();
            CP_WAIT(1);
        } else {
            CP_WAIT(0);
        }
        __syncthreads();

        const __half* Ash = smh + cs*QSTG_H;
        const __half* Bsh = Ash + QTILE_H;
        #pragma unroll
        for (int kk = 0; kk < 2; kk++) {
            const int k0 = kk*16 + 2*t4;
            uint32_t a[2][4];
            #pragma unroll
            for (int mi = 0; mi < 2; mi++) {
                const __half* ap = Ash + (wm + mi*16 + g)*QSA + k0;
                a[mi][0] = U32(ap);
                a[mi][1] = U32(ap + 8*QSA);
                a[mi][2] = U32(ap + 8);
                a[mi][3] = U32(ap + 8*QSA + 8);
            }
            #pragma unroll
            for (int ni = 0; ni < 8; ni++) {
                const __half* bp = Bsh + (wn + ni*8 + g)*QSA + k0;
                uint32_t b0 = U32(bp), b1 = U32(bp + 8);
                #pragma unroll
                for (int mi = 0; mi < 2; mi++)
                    mma_f16(acc[mi][ni][0], acc[mi][ni][1], acc[mi][ni][2], acc[mi][ni][3],
                            a[mi][0], a[mi][1], a[mi][2], a[mi][3], b0, b1);
            }
        }
        if (kt + 1 < nK) {
            const int ns = cs ^ 1;
            __half* Ad = smh + ns*QSTG_H;
            #pragma unroll
            for (int it = 0; it < 4; it++) {
                float4 v = areg[it];
                uint2 h2 = make_uint2(pk(v.x, v.y), pk(v.z, v.w));
                *reinterpret_cast<uint2*>(&Ad[(lrow+it*32)*QSA + lc4]) = h2;
            }
        }
        __syncthreads();
    }

    #pragma unroll
    for (int mi = 0; mi < 2; mi++) {
        const int rA = m0 + wm + mi*16 + g, rB = rA + 8;
        #pragma unroll
        for (int ni = 0; ni < 8; ni++) {
            const int c0 = wn + ni*8 + 2*t4;
            *reinterpret_cast<__half2*>(C + (size_t)rA*DHEAD + c0) =
                __floats2half2_rn(acc[mi][ni][0], acc[mi][ni][1]);
            *reinterpret_cast<__half2*>(C + (size_t)rB*DHEAD + c0) =
                __floats2half2_rn(acc[mi][ni][2], acc[mi][ni][3]);
        }
    }
}

// ---------------- fused flash attention (fp16 mma, register P) ----------------
#define SKV 136
#define FH_K 0
#define FH_V (2*64*SKV)
#define FL_SMEM_BYTES ((FH_V + 2*64*SKV)*2)   // 69632

__global__ __launch_bounds__(256) void flash_attn(
    const __half* __restrict__ q, const __half* __restrict__ k,
    const __half* __restrict__ v, float* __restrict__ outc,
    __half* __restrict__ outR)
{
    extern __shared__ char smraw[];
    __half* smh = (__half*)smraw;
    const uint32_t sm_u = s2u(smh);
    const int b   = blockIdx.y;
    const int qb  = blockIdx.x * 128;
    const int tid = threadIdx.x, lane = tid & 31, warp = tid >> 5;
    const int g   = lane >> 2, t4 = lane & 3;

    const __half* qB = q + ((size_t)b*SEQ + qb)*DHEAD;
    const __half* kB = k + (size_t)b*SEQ*DHEAD;
    const __half* vB = v + (size_t)b*SEQ*DHEAD;

    const int kc = tid >> 4;          // 0..15 (+16/iter, 4 iters)
    const int kf = (tid & 15) * 8;    // halves

    // per-lane ldmatrix base offsets for K B-frags
    const int krow = (lane >> 4)*8 + (lane & 7);
    const int kcol = ((lane >> 3) & 1) * 8;

    uint32_t qa[8][4];
    {
        const __half* q0 = qB + (size_t)(warp*16 + g)*DHEAD;
        const __half* q8 = q0 + 8*DHEAD;
        #pragma unroll
        for (int ks = 0; ks < 8; ks++) {
            const int o = ks*16 + 2*t4;
            qa[ks][0] = U32(q0 + o);
            qa[ks][1] = U32(q8 + o);
            qa[ks][2] = U32(q0 + o + 8);
            qa[ks][3] = U32(q8 + o + 8);
        }
    }

    float oacc[16][4];
    #pragma unroll
    for (int ni = 0; ni < 16; ni++)
        #pragma unroll
        for (int j = 0; j < 4; j++) oacc[ni][j] = 0.f;
    float m0 = -1e30f, m1 = -1e30f, l0 = 0.f, l1 = 0.f;

    {
        #pragma unroll
        for (int it = 0; it < 4; it++) {
            cp_async16(sm_u + (uint32_t)(FH_K + (kc + it*16)*SKV + kf)*2u,
                       kB + (size_t)(kc + it*16)*DHEAD + kf);
            cp_async16(sm_u + (uint32_t)(FH_V + (kc + it*16)*SKV + kf)*2u,
                       vB + (size_t)(kc + it*16)*DHEAD + kf);
        }
        CP_COMMIT();
    }

    const int nTiles = SEQ / 64;  // 32
    for (int t = 0; t < nTiles; t++) {
        const int cs = t & 1;
        if (t + 1 < nTiles) {
            const int ns = cs ^ 1;
            const int kv1 = (t+1) * 64;
            #pragma unroll
            for (int it = 0; it < 4; it++) {
                cp_async16(sm_u + (uint32_t)(FH_K + ns*64*SKV + (kc + it*16)*SKV + kf)*2u,
                           kB + (size_t)(kv1 + kc + it*16)*DHEAD + kf);
                cp_async16(sm_u + (uint32_t)(FH_V + ns*64*SKV + (kc + it*16)*SKV + kf)*2u,
                           vB + (size_t)(kv1 + kc + it*16)*DHEAD + kf);
            }
            CP_COMMIT();
            CP_WAIT(1);
        } else {
            CP_WAIT(0);
        }
        __syncthreads();

        const uint32_t kb0 = sm_u + (uint32_t)(FH_K + cs*64*SKV + krow*SKV + kcol)*2u;
        const uint32_t vb0 = sm_u + (uint32_t)(FH_V + cs*64*SKV + lane*SKV)*2u;

        // S = Q @ K^T (16 x 64 per warp), K frags via ldmatrix.x4
        float sacc[8][4];
        #pragma unroll
        for (int ni = 0; ni < 8; ni++)
            #pragma unroll
            for (int j = 0; j < 4; j++) sacc[ni][j] = 0.f;
        #pragma unroll
        for (int ks = 0; ks < 8; ks++) {
            #pragma unroll
            for (int nj = 0; nj < 4; nj++) {
                uint32_t b0, b1, b2, b3;
                ldsm4(b0, b1, b2, b3, kb0 + (uint32_t)(nj*16*SKV + ks*16)*2u);
                mma_f16(sacc[2*nj][0], sacc[2*nj][1], sacc[2*nj][2], sacc[2*nj][3],
                        qa[ks][0], qa[ks][1], qa[ks][2], qa[ks][3], b0, b1);
                mma_f16(sacc[2*nj+1][0], sacc[2*nj+1][1], sacc[2*nj+1][2], sacc[2*nj+1][3],
                        qa[ks][0], qa[ks][1], qa[ks][2], qa[ks][3], b2, b3);
            }
        }

        // online softmax (rows g and g+8; stats across quad lanes)
        float mx0 = -1e30f, mx1 = -1e30f;
        #pragma unroll
        for (int ni = 0; ni < 8; ni++) {
            sacc[ni][0] *= SCALE_F; sacc[ni][1] *= SCALE_F;
            sacc[ni][2] *= SCALE_F; sacc[ni][3] *= SCALE_F;
            mx0 = fmaxf(mx0, fmaxf(sacc[ni][0], sacc[ni][1]));
            mx1 = fmaxf(mx1, fmaxf(sacc[ni][2], sacc[ni][3]));
        }
        mx0 = fmaxf(mx0, __shfl_xor_sync(0xffffffffu, mx0, 1));
        mx0 = fmaxf(mx0, __shfl_xor_sync(0xffffffffu, mx0, 2));
        mx1 = fmaxf(mx1, __shfl_xor_sync(0xffffffffu, mx1, 1));
        mx1 = fmaxf(mx1, __shfl_xor_sync(0xffffffffu, mx1, 2));
        const float nm0 = fmaxf(m0, mx0), nm1 = fmaxf(m1, mx1);
        const float sc0 = ex2f((m0 - nm0) * LOG2E_F);
        const float sc1 = ex2f((m1 - nm1) * LOG2E_F);
        m0 = nm0; m1 = nm1;

        float rs0 = 0.f, rs1 = 0.f;
        uint32_t pa[4][4];
        #pragma unroll
        for (int j = 0; j < 4; j++) {
            const int n0i = 2*j, n1i = 2*j + 1;
            float p00 = ex2f((sacc[n0i][0] - nm0) * LOG2E_F);
            float p01 = ex2f((sacc[n0i][1] - nm0) * LOG2E_F);
            float p02 = ex2f((sacc[n0i][2] - nm1) * LOG2E_F);
            float p03 = ex2f((sacc[n0i][3] - nm1) * LOG2E_F);
            float p10 = ex2f((sacc[n1i][0] - nm0) * LOG2E_F);
            float p11 = ex2f((sacc[n1i][1] - nm0) * LOG2E_F);
            float p12 = ex2f((sacc[n1i][2] - nm1) * LOG2E_F);
            float p13 = ex2f((sacc[n1i][3] - nm1) * LOG2E_F);
            rs0 += p00 + p01 + p10 + p11;
            rs1 += p02 + p03 + p12 + p13;
            pa[j][0] = pk(p00, p01);
            pa[j][1] = pk(p02, p03);
            pa[j][2] = pk(p10, p11);
            pa[j][3] = pk(p12, p13);
        }
        rs0 += __shfl_xor_sync(0xffffffffu, rs0, 1);
        rs0 += __shfl_xor_sync(0xffffffffu, rs0, 2);
        rs1 += __shfl_xor_sync(0xffffffffu, rs1, 1);
        rs1 += __shfl_xor_sync(0xffffffffu, rs1, 2);
        l0 = l0 * sc0 + rs0;
        l1 = l1 * sc1 + rs1;
        #pragma unroll
        for (int ni = 0; ni < 16; ni++) {
            oacc[ni][0] *= sc0; oacc[ni][1] *= sc0;
            oacc[ni][2] *= sc1; oacc[ni][3] *= sc1;
        }

        // O += P @ V : A = register P frags, B = ldmatrix.trans from natural V
        #pragma unroll
        for (int jp = 0; jp < 2; jp++) {
            const uint32_t ab = vb0 + (uint32_t)(jp*32*SKV)*2u;
            #pragma unroll
            for (int ni = 0; ni < 16; ni++) {
                uint32_t b0, b1, b2, b3;
                ldsm4t(b0, b1, b2, b3, ab + ni*16);
                mma_f16(oacc[ni][0], oacc[ni][1], oacc[ni][2], oacc[ni][3],
                        pa[2*jp][0], pa[2*jp][1], pa[2*jp][2], pa[2*jp][3], b0, b1);
                mma_f16(oacc[ni][0], oacc[ni][1], oacc[ni][2], oacc[ni][3],
                        pa[2*jp+1][0], pa[2*jp+1][1], pa[2*jp+1][2], pa[2*jp+1][3], b2, b3);
            }
        }
        __syncthreads();
    }

    const float inv0 = 1.f / l0, inv1 = 1.f / l1;
    const size_t rowA = (size_t)b*SEQ + qb + warp*16 + g;
    const size_t rowB = rowA + 8;
    #pragma unroll
    for (int ni = 0; ni < 16; ni++) {
        const int c0 = ni*8 + 2*t4;
        float2 v0, v1;
        v0.x = oacc[ni][0]*inv0; v0.y = oacc[ni][1]*inv0;
        v1.x = oacc[ni][2]*inv1; v1.y = oacc[ni][3]*inv1;
        *reinterpret_cast<float2*>(outc + rowA*DHEAD + c0) = v0;
        *reinterpret_cast<float2*>(outc + rowB*DHEAD + c0) = v1;
        *reinterpret_cast<__half2*>(outR + rowA*DHEAD + c0) = __floats2half2_rn(v0.x, v0.y);
        *reinterpret_cast<__half2*>(outR + rowB*DHEAD + c0) = __floats2half2_rn(v1.x, v1.y);
    }
}

// ---------------- persistent merged rounds kernel (fp16, K = 128) -------------
#define HSMS 136
// byte offsets in smem
#define RB_T0   0
#define RB_T1   34816
#define RB_T2   69632
#define RB_T3   104448
#define RB_T4   139264
#define RB_RED  174080
#define RB_ACT  176128
#define RALL_SMEM_BYTES (RB_ACT + 128*4)   // 176640
#define ZFS 132

__device__ __forceinline__ void load_tile128h(uint32_t sdst_bytes,
                                              const __half* __restrict__ src, int tid)
{
    const int row = tid >> 4, c8 = (tid & 15) * 8;
    #pragma unroll
    for (int it = 0; it < 8; it++)
        cp_async16(sdst_bytes + (uint32_t)((row + it*16)*HSMS + c8)*2u,
                   src + (size_t)(row + it*16)*128 + c8);
}

__device__ __forceinline__ void mma_128x128h(const __half* __restrict__ As,
                                             const __half* __restrict__ Bs,
                                             float acc[2][8][4],
                                             int wm, int wn, int g, int t4)
{
    #pragma unroll
    for (int ks = 0; ks < 8; ks++) {
        const int k0 = ks*16 + 2*t4;
        uint32_t a[2][4];
        #pragma unroll
        for (int mi = 0; mi < 2; mi++) {
            const __half* ap = As + (wm + mi*16 + g)*HSMS + k0;
            a[mi][0] = U32(ap);
            a[mi][1] = U32(ap + 8*HSMS);
            a[mi][2] = U32(ap + 8);
            a[mi][3] = U32(ap + 8*HSMS + 8);
        }
        #pragma unroll
        for (int ni = 0; ni < 8; ni++) {
            const __half* bp = Bs + (wn + ni*8 + g)*HSMS + k0;
            uint32_t b0 = U32(bp), b1 = U32(bp + 8);
            #pragma unroll
            for (int mi = 0; mi < 2; mi++)
                mma_f16(acc[mi][ni][0], acc[mi][ni][1], acc[mi][ni][2], acc[mi][ni][3],
                        a[mi][0], a[mi][1], a[mi][2], a[mi][3], b0, b1);
        }
    }
}

#define ZERO_ACC(acc) { \
    _Pragma("unroll") for (int mi = 0; mi < 2; mi++) \
        _Pragma("unroll") for (int ni = 0; ni < 8; ni++) \
            _Pragma("unroll") for (int j = 0; j < 4; j++) acc[mi][ni][j] = 0.f; }

__global__ __launch_bounds__(256) void rounds_all(
    float* __restrict__ cur, const __half* __restrict__ curR,
    const __half* __restrict__ tw, const __half* __restrict__ wd,
    const __half* __restrict__ w1c, const __half* __restrict__ w2,
    const float* __restrict__ cvec, const float* __restrict__ b1,
    const float* __restrict__ b2, const float* __restrict__ gw,
    const float* __restrict__ gb,
    int* __restrict__ cnt, int* __restrict__ anyf)
{
    extern __shared__ char smraw[];
    __half* smh = (__half*)smraw;
    const uint32_t sm_u = s2u(smraw);
    float* ZF  = reinterpret_cast<float*>(smraw + RB_T1);
    float* red = reinterpret_cast<float*>(smraw + RB_RED);
    int* s_act = reinterpret_cast<int*>(smraw + RB_ACT);
    __shared__ int s_flag, s_any;
    const int tid = threadIdx.x, lane = tid & 31, warp = tid >> 5;
    const int wm = (warp >> 1) * 32, wn = (warp & 1) * 64;
    const int g = lane >> 2, t4 = lane & 3;
    const int m0 = blockIdx.x * 128;

    load_tile128h(sm_u + RB_T0, curR + (size_t)m0*128, tid);
    load_tile128h(sm_u + RB_T1, tw, tid);
    load_tile128h(sm_u + RB_T2, wd, tid);
    load_tile128h(sm_u + RB_T3, w1c, tid);
    load_tile128h(sm_u + RB_T4, w2, tid);
    CP_COMMIT(); CP_WAIT(0);
    if (tid < 128) s_act[tid] = 1;
    if (tid == 0) { s_flag = 1; s_any = 0; }
    __syncthreads();

    float acc[2][8][4];

    // ---- zfix phase: p = rn(curR @ tw^T); zfix = p @ wd^T (fp32, in ZF) ------
    ZERO_ACC(acc);
    mma_128x128h(smh, smh + RB_T1/2, acc, wm, wn, g, t4);
    __syncthreads();
    {   // p (fp16) -> T1 slot (tw no longer needed)
        __half* Ps = smh + RB_T1/2;
        #pragma unroll
        for (int mi = 0; mi < 2; mi++) {
            const int rA = wm + mi*16 + g, rB = rA + 8;
            #pragma unroll
            for (int ni = 0; ni < 8; ni++) {
                const int c0 = wn + ni*8 + 2*t4;
                *reinterpret_cast<__half2*>(&Ps[rA*HSMS + c0]) =
                    __floats2half2_rn(acc[mi][ni][0], acc[mi][ni][1]);
                *reinterpret_cast<__half2*>(&Ps[rB*HSMS + c0]) =
                    __floats2half2_rn(acc[mi][ni][2], acc[mi][ni][3]);
            }
        }
    }
    __syncthreads();
    ZERO_ACC(acc);
    mma_128x128h(smh + RB_T1/2, smh + RB_T2/2, acc, wm, wn, g, t4);
    __syncthreads();
    {   // zfix fp32 over T1+T2 region
        #pragma unroll
        for (int mi = 0; mi < 2; mi++) {
            const int rA = wm + mi*16 + g, rB = rA + 8;
            #pragma unroll
            for (int ni = 0; ni < 8; ni++) {
                const int c0 = wn + ni*8 + 2*t4;
                float2 v0, v1;
                v0.x = acc[mi][ni][0]; v0.y = acc[mi][ni][1];
                v1.x = acc[mi][ni][2]; v1.y = acc[mi][ni][3];
                *reinterpret_cast<float2*>(&ZF[rA*ZFS + c0]) = v0;
                *reinterpret_cast<float2*>(&ZF[rB*ZFS + c0]) = v1;
            }
        }
    }
    __syncthreads();

    // ---- dialectical rounds ---------------------------------------------------
    for (int r = 0; r < NROUNDS; r++) {
        ZERO_ACC(acc);
        mma_128x128h(smh, smh + RB_T3/2, acc, wm, wn, g, t4);   // z = curR @ w1c^T
        __syncthreads();

        float amr[4];
        #pragma unroll
        for (int mi = 0; mi < 2; mi++) {
            const int rA = wm + mi*16 + g, rB = rA + 8;
            const float amA = s_act[rA] ? 1.f : 0.f;
            const float amB = s_act[rB] ? 1.f : 0.f;
            amr[mi*2] = amA; amr[mi*2+1] = amB;
            #pragma unroll
            for (int ni = 0; ni < 8; ni++) {
                const int c0 = wn + ni*8 + 2*t4;
                float2 zA = *reinterpret_cast<const float2*>(&ZF[rA*ZFS + c0]);
                float2 zB = *reinterpret_cast<const float2*>(&ZF[rB*ZFS + c0]);
                float2 cc = *reinterpret_cast<const float2*>(cvec + c0);
                float2 bb = *reinterpret_cast<const float2*>(b1 + c0);
                float h00 = fmaxf(fmaf(amA, acc[mi][ni][0] + zA.x + cc.x, bb.x), 0.f);
                float h01 = fmaxf(fmaf(amA, acc[mi][ni][1] + zA.y + cc.y, bb.y), 0.f);
                float h10 = fmaxf(fmaf(amB, acc[mi][ni][2] + zB.x + cc.x, bb.x), 0.f);
                float h11 = fmaxf(fmaf(amB, acc[mi][ni][3] + zB.y + cc.y, bb.y), 0.f);
                *reinterpret_cast<__half2*>(&smh[rA*HSMS + c0]) = __floats2half2_rn(h00, h01);
                *reinterpret_cast<__half2*>(&smh[rB*HSMS + c0]) = __floats2half2_rn(h10, h11);
            }
        }
        __syncthreads();

        ZERO_ACC(acc);
        mma_128x128h(smh, smh + RB_T4/2, acc, wm, wn, g, t4);   // synth = h @ w2^T

        const int flg = s_flag;
        float d1[4] = {0,0,0,0}, nn[4] = {0,0,0,0};
        #pragma unroll
        for (int mi = 0; mi < 2; mi++) {
            const int rA = wm + mi*16 + g, rB = rA + 8;
            const float amA = amr[mi*2], amB = amr[mi*2+1];
            #pragma unroll
            for (int ni = 0; ni < 8; ni++) {
                const int c0 = wn + ni*8 + 2*t4;
                float2 cA = *reinterpret_cast<const float2*>(cur + (size_t)(m0+rA)*128 + c0);
                float2 cB = *reinterpret_cast<const float2*>(cur + (size_t)(m0+rB)*128 + c0);
                float2 bb = *reinterpret_cast<const float2*>(b2 + c0);
                float2 g1 = *reinterpret_cast<const float2*>(gw + c0);
                float2 g2 = *reinterpret_cast<const float2*>(gw + 128 + c0);
                float syA0 = acc[mi][ni][0] + bb.x, syA1 = acc[mi][ni][1] + bb.y;
                float syB0 = acc[mi][ni][2] + bb.x, syB1 = acc[mi][ni][3] + bb.y;
                float acA0 = cA.x * amA, acA1 = cA.y * amA;
                float acB0 = cB.x * amB, acB1 = cB.y * amB;
                d1[mi*2]   += acA0*g1.x + syA0*g2.x + acA1*g1.y + syA1*g2.y;
                d1[mi*2+1] += acB0*g1.x + syB0*g2.x + acB1*g1.y + syB1*g2.y;
                float dA0 = syA0-acA0, dA1 = syA1-acA1;
                float dB0 = syB0-acB0, dB1 = syB1-acB1;
                nn[mi*2]   += dA0*dA0 + dA1*dA1;
                nn[mi*2+1] += dB0*dB0 + dB1*dB1;
            }
        }
        #pragma unroll
        for (int j = 0; j < 4; j++) {
            d1[j] += __shfl_xor_sync(0xffffffffu, d1[j], 1);
            d1[j] += __shfl_xor_sync(0xffffffffu, d1[j], 2);
            nn[j] += __shfl_xor_sync(0xffffffffu, nn[j], 1);
            nn[j] += __shfl_xor_sync(0xffffffffu, nn[j], 2);
        }
        if (t4 == 0) {
            const int hf = (warp & 1) * 2;
            #pragma unroll
            for (int mi = 0; mi < 2; mi++) {
                const int rA = wm + mi*16 + g, rB = rA + 8;
                red[rA*4 + hf]     = d1[mi*2];
                red[rA*4 + hf + 1] = nn[mi*2];
                red[rB*4 + hf]     = d1[mi*2+1];
                red[rB*4 + hf + 1] = nn[mi*2+1];
            }
        }
        __syncthreads();

        const float gbv = gb[0];
        #pragma unroll
        for (int mi = 0; mi < 2; mi++) {
            const int rA = wm + mi*16 + g, rB = rA + 8;
            const float amA = amr[mi*2], amB = amr[mi*2+1];
            float gdA = red[rA*4+0] + red[rA*4+2] + gbv;
            float gdB = red[rB*4+0] + red[rB*4+2] + gbv;
            float n2A = red[rA*4+1] + red[rA*4+3];
            float n2B = red[rB*4+1] + red[rB*4+3];
            float gateA = 1.f / (1.f + expf(-gdA));
            float gateB = 1.f / (1.f + expf(-gdB));
            int stableA = (gateA * 0.1f * sqrtf(n2A)) < 0.1f;
            int stableB = (gateB * 0.1f * sqrtf(n2B)) < 0.1f;
            #pragma unroll
            for (int ni = 0; ni < 8; ni++) {
                const int c0 = wn + ni*8 + 2*t4;
                float2 cA = *reinterpret_cast<const float2*>(cur + (size_t)(m0+rA)*128 + c0);
                float2 cB = *reinterpret_cast<const float2*>(cur + (size_t)(m0+rB)*128 + c0);
                float2 bb = *reinterpret_cast<const float2*>(b2 + c0);
                float syA0 = acc[mi][ni][0] + bb.x, syA1 = acc[mi][ni][1] + bb.y;
                float syB0 = acc[mi][ni][2] + bb.x, syB1 = acc[mi][ni][3] + bb.y;
                float2 o0, o1;
                o0.x = cA.x; o0.y = cA.y; o1.x = cB.x; o1.y = cB.y;
                if (flg) {
                    o0.x += gateA * (syA0 - cA.x*amA) * 0.1f;
                    o0.y += gateA * (syA1 - cA.y*amA) * 0.1f;
                    o1.x += gateB * (syB0 - cB.x*amB) * 0.1f;
                    o1.y += gateB * (syB1 - cB.y*amB) * 0.1f;
                }
                *reinterpret_cast<float2*>(cur + (size_t)(m0+rA)*128 + c0) = o0;
                *reinterpret_cast<float2*>(cur + (size_t)(m0+rB)*128 + c0) = o1;
                // new curR -> T0 smem (for next round's z GEMM)
                *reinterpret_cast<__half2*>(&smh[rA*HSMS + c0]) = __floats2half2_rn(o0.x, o0.y);
                *reinterpret_cast<__half2*>(&smh[rB*HSMS + c0]) = __floats2half2_rn(o1.x, o1.y);
            }
            if ((warp & 1) == 0 && t4 == 0) {
                int actA = amA > 0.f, actB = amB > 0.f;
                int naA = actA && !stableA;
                int naB = actB && !stableB;
                if (flg) { s_act[rA] = naA; s_act[rB] = naB; }
                int effA = flg ? naA : actA;
                int effB = flg ? naB : actB;
                if (effA | effB) s_any = 1;
            }
        }
        __syncthreads();

        if (r + 1 < NROUNDS) {
            if (tid == 0) {
                if (s_any) atomicOr(&anyf[r], 1);
                __threadfence();
                atomicAdd(&cnt[r], 1);
                while (atomicAdd(&cnt[r], 0) < (int)gridDim.x) {}
                s_flag = (atomicOr(&anyf[r], 0) != 0) ? 1 : 0;
                s_any = 0;
            }
            __syncthreads();
        }
    }
}

// ---------------- single prep kernel (fp16 weight copies) ---------------------
__global__ void prep_all(
    const float* __restrict__ wq, const float* __restrict__ wk,
    const float* __restrict__ wv, const float* __restrict__ tw,
    const float* __restrict__ w2, const float* __restrict__ w1,
    const float* __restrict__ tb, const float* __restrict__ ab,
    __half* __restrict__ wqkvr, __half* __restrict__ twr,
    __half* __restrict__ w2r, __half* __restrict__ wdr,
    __half* __restrict__ w1cr, float* __restrict__ cvec,
    int* __restrict__ cnt, int* __restrict__ anyf)
{
    int idx = blockIdx.x * blockDim.x + threadIdx.x;
    const int WN4 = DHEAD*DMODEL/4;
    const int T4  = DHEAD*DHEAD/4;
    if (idx < 3*WN4) {
        const float* src = (idx < WN4) ? wq : (idx < 2*WN4 ? wk : wv);
        int off = (idx < WN4) ? idx : (idx < 2*WN4 ? idx - WN4 : idx - 2*WN4);
        float4 vv = reinterpret_cast<const float4*>(src)[off];
        reinterpret_cast<__half2*>(wqkvr)[2*idx]   = __floats2half2_rn(vv.x, vv.y);
        reinterpret_cast<__half2*>(wqkvr)[2*idx+1] = __floats2half2_rn(vv.z, vv.w);
        return;
    }
    idx -= 3*WN4;
    if (idx < T4) {
        float4 vv = reinterpret_cast<const float4*>(tw)[idx];
        reinterpret_cast<__half2*>(twr)[2*idx]   = __floats2half2_rn(vv.x, vv.y);
        reinterpret_cast<__half2*>(twr)[2*idx+1] = __floats2half2_rn(vv.z, vv.w);
        return;
    }
    idx -= T4;
    if (idx < T4) {
        float4 vv = reinterpret_cast<const float4*>(w2)[idx];
        reinterpret_cast<__half2*>(w2r)[2*idx]   = __floats2half2_rn(vv.x, vv.y);
        reinterpret_cast<__half2*>(w2r)[2*idx+1] = __floats2half2_rn(vv.z, vv.w);
        return;
    }
    idx -= T4;
    if (idx < DHEAD*DHEAD) {
        int j = idx >> 7, i = idx & 127;
        wdr[idx]  = __float2half_rn(w1[j*384 + i] - w1[j*384 + 128 + i]);
        w1cr[idx] = __float2half_rn(w1[j*384 + 256 + i]);
        return;
    }
    idx -= DHEAD*DHEAD;
    if (idx < DHEAD) {
        float s = 0.f;
        for (int i = 0; i < 128; i++)
            s += tb[i]*w1[idx*384 + i] + ab[i]*w1[idx*384 + 128 + i];
        cvec[idx] = s;
        return;
    }
    idx -= DHEAD;
    if (idx < NROUNDS) { cnt[idx] = 0; return; }
    idx -= NROUNDS;
    if (idx < NROUNDS) { anyf[idx] = 0; return; }
}
#define PREP_ITEMS (3*(DHEAD*DMODEL/4) + 2*(DHEAD*DHEAD/4) + DHEAD*DHEAD + DHEAD + 2*NROUNDS)

// ---------------- launch ------------------------------------------------------
extern "C" void kernel_launch(void* const* d_in, const int* in_sizes, int n_in,
                              void* d_out, int out_size)
{
    (void)in_sizes; (void)n_in; (void)out_size;
    const float* x  = (const float*)d_in[0];
    const float* wq = (const float*)d_in[1];
    const float* wk = (const float*)d_in[2];
    const float* wv = (const float*)d_in[3];
    const float* tw = (const float*)d_in[4];
    const float* tb = (const float*)d_in[5];
    const float* ab = (const float*)d_in[6];
    const float* w1 = (const float*)d_in[7];
    const float* b1 = (const float*)d_in[8];
    const float* w2 = (const float*)d_in[9];
    const float* b2 = (const float*)d_in[10];
    const float* gw = (const float*)d_in[11];
    const float* gb = (const float*)d_in[12];
    float* cur = (float*)d_out;

    __half *qkv,*curR,*wqkvr,*twr,*w2r,*wdr,*w1cr;
    float *cvec;
    int *cnt,*anyf;
    cudaGetSymbolAddress((void**)&qkv,    g_qkv);
    cudaGetSymbolAddress((void**)&curR,   g_curR);
    cudaGetSymbolAddress((void**)&wqkvr,  g_wqkvr);
    cudaGetSymbolAddress((void**)&twr,    g_twr);
    cudaGetSymbolAddress((void**)&w2r,    g_w2r);
    cudaGetSymbolAddress((void**)&wdr,    g_wdr);
    cudaGetSymbolAddress((void**)&w1cr,   g_w1cr);
    cudaGetSymbolAddress((void**)&cvec,   g_cvec);
    cudaGetSymbolAddress((void**)&cnt,    g_cnt);
    cudaGetSymbolAddress((void**)&anyf,   g_any);

    cudaFuncSetAttribute(qkv_gemm,   cudaFuncAttributeMaxDynamicSharedMemorySize, QKV_SMEM_BYTES);
    cudaFuncSetAttribute(flash_attn, cudaFuncAttributeMaxDynamicSharedMemorySize, FL_SMEM_BYTES);
    cudaFuncSetAttribute(rounds_all, cudaFuncAttributeMaxDynamicSharedMemorySize, RALL_SMEM_BYTES);

    prep_all<<<(PREP_ITEMS + 255)/256, 256>>>(
        wq, wk, wv, tw, w2, w1, tb, ab,
        wqkvr, twr, w2r, wdr, w1cr, cvec, cnt, anyf);

    qkv_gemm<<<dim3(3, MTOK/128), 256, QKV_SMEM_BYTES>>>(x, wqkvr, qkv);

    flash_attn<<<dim3(SEQ/128, BATCH), 256, FL_SMEM_BYTES>>>(
        qkv, qkv + (size_t)MTOK*DHEAD, qkv + 2*(size_t)MTOK*DHEAD, cur, curR);

    rounds_all<<<MTOK/128, 256, RALL_SMEM_BYTES>>>(
        cur, curR, twr, wdr, w1cr, w2r, cvec, b1, b2, gw, gb, cnt, anyf);
}